// round 1
// baseline (speedup 1.0000x reference)
#include <cuda_runtime.h>
#include <math.h>

#define NTOK (32768*16)          // 524288 tokens
#define DM   64
#define TPB  256
#define NBLK (NTOK/TPB)          // 2048 CTAs
#define WROW 68                  // padded shared row stride (272B, 16B aligned, 4-way-max STS)

// ping-pong scratch (static device array: allocation-free)
__device__ float g_scratch[(size_t)NTOK * DM];

// ---------- packed f32x2 helpers ----------
__device__ __forceinline__ unsigned long long pk2(float lo, float hi) {
    unsigned long long r;
    asm("mov.b64 %0, {%1, %2};" : "=l"(r) : "f"(lo), "f"(hi));
    return r;
}
__device__ __forceinline__ float2 upk2(unsigned long long v) {
    float2 t;
    asm("mov.b64 {%0, %1}, %2;" : "=f"(t.x), "=f"(t.y) : "l"(v));
    return t;
}
__device__ __forceinline__ unsigned long long ffma2(unsigned long long a, unsigned long long b,
                                                    unsigned long long c) {
    unsigned long long d;
    asm("fma.rn.f32x2 %0, %1, %2, %3;" : "=l"(d) : "l"(a), "l"(b), "l"(c));
    return d;
}

// dot of a 64-float vector (packed as 32 f32x2) with a 64-float shared row (16B aligned)
__device__ __forceinline__ float dot64(const unsigned long long* ux, const float* w) {
    unsigned long long a0 = 0ull, a1 = 0ull, a2 = 0ull, a3 = 0ull;
    const ulonglong2* w2 = (const ulonglong2*)w;
#pragma unroll
    for (int i = 0; i < 8; i++) {
        ulonglong2 p = w2[2 * i];
        ulonglong2 q = w2[2 * i + 1];
        a0 = ffma2(ux[4 * i + 0], p.x, a0);
        a1 = ffma2(ux[4 * i + 1], p.y, a1);
        a2 = ffma2(ux[4 * i + 2], q.x, a2);
        a3 = ffma2(ux[4 * i + 3], q.y, a3);
    }
    float2 f0 = upk2(a0), f1 = upk2(a1), f2 = upk2(a2), f3 = upk2(a3);
    return ((f0.x + f0.y) + (f1.x + f1.y)) + ((f2.x + f2.y) + (f3.x + f3.y));
}

// ==================================================================
// Attention kernel: out = x + attn(LN(x))  (one thread = one token)
// ==================================================================
// shared: Wq,Wk,Wv as [c=h*8+s][d] (WROW stride), WpT as [e][c], biases, ln params,
//         K/V staging per CTA-local token.
#define ATTN_SMEM_FLOATS (4*64*WROW + 256 + 128 + 2*256*WROW)
#define ATTN_SMEM_BYTES  (ATTN_SMEM_FLOATS*4)

template <bool CAUSAL>
__global__ void __launch_bounds__(TPB) attn_kernel(
    const float* __restrict__ xin, float* __restrict__ xout,
    const float* __restrict__ Wq, const float* __restrict__ bq,
    const float* __restrict__ Wk, const float* __restrict__ bk,
    const float* __restrict__ Wv, const float* __restrict__ bv,
    const float* __restrict__ Wp, const float* __restrict__ bp,
    const float* __restrict__ g1, const float* __restrict__ be1)
{
    extern __shared__ float sm[];
    float* sWq = sm;                        // 64 x WROW
    float* sWk = sm + 64 * WROW;
    float* sWv = sm + 2 * 64 * WROW;
    float* sWp = sm + 3 * 64 * WROW;        // [e][c]
    float* sb  = sm + 4 * 64 * WROW;        // bq(64) bk(64) bv(64) bp(64)
    float* sg  = sb + 256;                  // g1(64) be1(64)
    float* sK  = sg + 128;                  // 256 x WROW
    float* sV  = sK + 256 * WROW;

    const int tid = threadIdx.x;

    // stage weights (coalesced LDG; stride-68 STS => <=4-way conflicts, once per CTA)
    for (int i = tid; i < 4096; i += TPB) {
        // Wq/Wk/Wv layout [h][d][s]: i = h*512 + d*8 + s ; c = h*8+s
        int h = i >> 9, d = (i >> 3) & 63, s = i & 7;
        int c = h * 8 + s;
        sWq[c * WROW + d] = Wq[i];
        sWk[c * WROW + d] = Wk[i];
        sWv[c * WROW + d] = Wv[i];
        // Wp row-major [c][e]: i = pc*64 + pe ; store transposed [e][c]
        int pc = i >> 6, pe = i & 63;
        sWp[pe * WROW + pc] = Wp[i];
    }
    if (tid < 64) {
        sb[tid]       = bq[tid];
        sb[64 + tid]  = bk[tid];
        sb[128 + tid] = bv[tid];
        sb[192 + tid] = bp[tid];
        sg[tid]       = g1[tid];
        sg[64 + tid]  = be1[tid];
    }
    __syncthreads();

    const size_t tok = (size_t)blockIdx.x * TPB + tid;
    const float4* xr4 = (const float4*)(xin + tok * DM);

    // load token row + LayerNorm (fully thread-local)
    float xv[64];
#pragma unroll
    for (int i = 0; i < 16; i++) {
        float4 t = xr4[i];
        xv[4 * i] = t.x; xv[4 * i + 1] = t.y; xv[4 * i + 2] = t.z; xv[4 * i + 3] = t.w;
    }
    float mean = 0.f;
#pragma unroll
    for (int d = 0; d < 64; d++) mean += xv[d];
    mean *= (1.f / 64.f);
    float var = 0.f;
#pragma unroll
    for (int d = 0; d < 64; d++) { float dv = xv[d] - mean; var += dv * dv; }
    var *= (1.f / 64.f);
    const float rstd = rsqrtf(var + 1e-5f);

    unsigned long long ux[32];
#pragma unroll
    for (int i = 0; i < 32; i++) {
        float a = (xv[2 * i] - mean) * rstd * sg[2 * i] + sg[64 + 2 * i];
        float b = (xv[2 * i + 1] - mean) * rstd * sg[2 * i + 1] + sg[64 + 2 * i + 1];
        ux[i] = pk2(a, b);
    }

    // q in registers; k,v to shared
    float q[64];
#pragma unroll 4
    for (int c = 0; c < 64; c++) q[c] = sb[c] + dot64(ux, &sWq[c * WROW]);
    float* myK = &sK[tid * WROW];
    float* myV = &sV[tid * WROW];
#pragma unroll 4
    for (int c = 0; c < 64; c++) myK[c] = sb[64 + c] + dot64(ux, &sWk[c * WROW]);
#pragma unroll 4
    for (int c = 0; c < 64; c++) myV[c] = sb[128 + c] + dot64(ux, &sWv[c * WROW]);
    __syncthreads();

    const int t     = tid & 15;         // position within its 16-token batch
    const int bbase = tid & ~15;        // CTA-local row of this batch's token 0

    float att[64];
#pragma unroll
    for (int h = 0; h < 8; h++) {
        float s[16];
        float mx = -1e30f;
#pragma unroll
        for (int u = 0; u < 16; u++) {
            const float4* kr = (const float4*)(&sK[(bbase + u) * WROW + h * 8]);
            float4 k0 = kr[0], k1 = kr[1];
            float a = q[h * 8 + 0] * k0.x + q[h * 8 + 1] * k0.y +
                      q[h * 8 + 2] * k0.z + q[h * 8 + 3] * k0.w +
                      q[h * 8 + 4] * k1.x + q[h * 8 + 5] * k1.y +
                      q[h * 8 + 6] * k1.z + q[h * 8 + 7] * k1.w;
            a *= 0.35355339059327373f;          // HS^-0.5
            if (CAUSAL && u > t) a = -1e30f;
            s[u] = a;
            mx = fmaxf(mx, a);
        }
        float sum = 0.f;
#pragma unroll
        for (int u = 0; u < 16; u++) { float e = __expf(s[u] - mx); s[u] = e; sum += e; }
        const float inv = 1.f / sum;

        float o0 = 0.f, o1 = 0.f, o2 = 0.f, o3 = 0.f, o4 = 0.f, o5 = 0.f, o6 = 0.f, o7 = 0.f;
#pragma unroll
        for (int u = 0; u < 16; u++) {
            const float4* vr = (const float4*)(&sV[(bbase + u) * WROW + h * 8]);
            float4 v0 = vr[0], v1 = vr[1];
            float w = s[u];
            o0 += w * v0.x; o1 += w * v0.y; o2 += w * v0.z; o3 += w * v0.w;
            o4 += w * v1.x; o5 += w * v1.y; o6 += w * v1.z; o7 += w * v1.w;
        }
        att[h * 8 + 0] = o0 * inv; att[h * 8 + 1] = o1 * inv;
        att[h * 8 + 2] = o2 * inv; att[h * 8 + 3] = o3 * inv;
        att[h * 8 + 4] = o4 * inv; att[h * 8 + 5] = o5 * inv;
        att[h * 8 + 6] = o6 * inv; att[h * 8 + 7] = o7 * inv;
    }

    // output projection + residual
    unsigned long long uo[32];
#pragma unroll
    for (int i = 0; i < 32; i++) uo[i] = pk2(att[2 * i], att[2 * i + 1]);
    float4* out4 = (float4*)(xout + tok * DM);
#pragma unroll 2
    for (int e4 = 0; e4 < 16; e4++) {
        float4 r = xr4[e4];
        float p0 = sb[192 + 4 * e4 + 0] + dot64(uo, &sWp[(4 * e4 + 0) * WROW]);
        float p1 = sb[192 + 4 * e4 + 1] + dot64(uo, &sWp[(4 * e4 + 1) * WROW]);
        float p2 = sb[192 + 4 * e4 + 2] + dot64(uo, &sWp[(4 * e4 + 2) * WROW]);
        float p3 = sb[192 + 4 * e4 + 3] + dot64(uo, &sWp[(4 * e4 + 3) * WROW]);
        out4[e4] = make_float4(r.x + p0, r.y + p1, r.z + p2, r.w + p3);
    }
}

// ==================================================================
// FFN kernel: out = x + gelu(LN(x)@W1 + b1)@W2 + b2
// ==================================================================
#define FFN_SMEM_FLOATS (256*WROW + 256*64 + 256 + 64 + 128)
#define FFN_SMEM_BYTES  (FFN_SMEM_FLOATS*4)

__global__ void __launch_bounds__(TPB) ffn_kernel(
    const float* __restrict__ xin, float* __restrict__ xout,
    const float* __restrict__ W1, const float* __restrict__ b1,
    const float* __restrict__ W2, const float* __restrict__ b2,
    const float* __restrict__ g2, const float* __restrict__ be2)
{
    extern __shared__ float sm[];
    float* sW1 = sm;                 // [j][d], WROW stride (transposed)
    float* sW2 = sm + 256 * WROW;    // [j][e], stride 64 (native layout)
    float* sb1 = sW2 + 256 * 64;     // 256
    float* sb2 = sb1 + 256;          // 64
    float* sg  = sb2 + 64;           // g2(64) be2(64)

    const int tid = threadIdx.x;
    for (int i = tid; i < 16384; i += TPB) {
        int d = i >> 8, j = i & 255;         // W1[d][j] at i = d*256+j
        sW1[j * WROW + d] = W1[i];
        sW2[i] = W2[i];                      // W2 already [j][e]
    }
    if (tid < 64) { sb2[tid] = b2[tid]; sg[tid] = g2[tid]; sg[64 + tid] = be2[tid]; }
    sb1[tid] = b1[tid];
    __syncthreads();

    const size_t tok = (size_t)blockIdx.x * TPB + tid;
    const float4* xr4 = (const float4*)(xin + tok * DM);

    float xv[64];
#pragma unroll
    for (int i = 0; i < 16; i++) {
        float4 v = xr4[i];
        xv[4 * i] = v.x; xv[4 * i + 1] = v.y; xv[4 * i + 2] = v.z; xv[4 * i + 3] = v.w;
    }
    float mean = 0.f;
#pragma unroll
    for (int d = 0; d < 64; d++) mean += xv[d];
    mean *= (1.f / 64.f);
    float var = 0.f;
#pragma unroll
    for (int d = 0; d < 64; d++) { float dv = xv[d] - mean; var += dv * dv; }
    var *= (1.f / 64.f);
    const float rstd = rsqrtf(var + 1e-5f);

    unsigned long long ux[32];   // LN(x) packed
    unsigned long long ua[32];   // accumulator, init = x + b2 (residual + output bias)
#pragma unroll
    for (int i = 0; i < 32; i++) {
        float a = (xv[2 * i] - mean) * rstd * sg[2 * i] + sg[64 + 2 * i];
        float b = (xv[2 * i + 1] - mean) * rstd * sg[2 * i + 1] + sg[64 + 2 * i + 1];
        ux[i] = pk2(a, b);
        ua[i] = pk2(xv[2 * i] + sb2[2 * i], xv[2 * i + 1] + sb2[2 * i + 1]);
    }

#pragma unroll 2
    for (int j = 0; j < 256; j++) {
        float z = sb1[j] + dot64(ux, &sW1[j * WROW]);
        float g = 0.5f * z * (1.f + erff(z * 0.7071067811865475f));   // exact GELU
        unsigned long long hh = pk2(g, g);
        const ulonglong2* w2 = (const ulonglong2*)(&sW2[j * 64]);
#pragma unroll
        for (int i = 0; i < 16; i++) {
            ulonglong2 wv = w2[i];
            ua[2 * i]     = ffma2(hh, wv.x, ua[2 * i]);
            ua[2 * i + 1] = ffma2(hh, wv.y, ua[2 * i + 1]);
        }
    }

    float4* o4 = (float4*)(xout + tok * DM);
#pragma unroll
    for (int i = 0; i < 16; i++) {
        float2 a = upk2(ua[2 * i]), b = upk2(ua[2 * i + 1]);
        o4[i] = make_float4(a.x, a.y, b.x, b.y);
    }
}

// ==================================================================
// launch: attn(u) -> ffn -> attn(m, causal) -> ffn
// ==================================================================
extern "C" void kernel_launch(void* const* d_in, const int* in_sizes, int n_in,
                              void* d_out, int out_size)
{
    (void)in_sizes; (void)n_in; (void)out_size;
    const float* x   = (const float*)d_in[0];
    const float* uWq = (const float*)d_in[1];  const float* ubq = (const float*)d_in[2];
    const float* uWk = (const float*)d_in[3];  const float* ubk = (const float*)d_in[4];
    const float* uWv = (const float*)d_in[5];  const float* ubv = (const float*)d_in[6];
    const float* uWp = (const float*)d_in[7];  const float* ubp = (const float*)d_in[8];
    const float* mWq = (const float*)d_in[9];  const float* mbq = (const float*)d_in[10];
    const float* mWk = (const float*)d_in[11]; const float* mbk = (const float*)d_in[12];
    const float* mWv = (const float*)d_in[13]; const float* mbv = (const float*)d_in[14];
    const float* mWp = (const float*)d_in[15]; const float* mbp = (const float*)d_in[16];
    const float* fW1 = (const float*)d_in[17]; const float* fb1 = (const float*)d_in[18];
    const float* fW2 = (const float*)d_in[19]; const float* fb2 = (const float*)d_in[20];
    const float* g1  = (const float*)d_in[21]; const float* be1 = (const float*)d_in[22];
    const float* g2  = (const float*)d_in[23]; const float* be2 = (const float*)d_in[24];
    float* out = (float*)d_out;

    float* scratch = nullptr;
    cudaGetSymbolAddress((void**)&scratch, g_scratch);

    cudaFuncSetAttribute(attn_kernel<false>, cudaFuncAttributeMaxDynamicSharedMemorySize, ATTN_SMEM_BYTES);
    cudaFuncSetAttribute(attn_kernel<true>,  cudaFuncAttributeMaxDynamicSharedMemorySize, ATTN_SMEM_BYTES);
    cudaFuncSetAttribute(ffn_kernel,         cudaFuncAttributeMaxDynamicSharedMemorySize, FFN_SMEM_BYTES);

    // x2 = x + attn_u(ln1(x))
    attn_kernel<false><<<NBLK, TPB, ATTN_SMEM_BYTES>>>(x, scratch,
        uWq, ubq, uWk, ubk, uWv, ubv, uWp, ubp, g1, be1);
    // x = x2 + ffn(ln2(x2))
    ffn_kernel<<<NBLK, TPB, FFN_SMEM_BYTES>>>(scratch, out, fW1, fb1, fW2, fb2, g2, be2);
    // x2 = x + attn_m(ln1(x)), causal
    attn_kernel<true><<<NBLK, TPB, ATTN_SMEM_BYTES>>>(out, scratch,
        mWq, mbq, mWk, mbk, mWv, mbv, mWp, mbp, g1, be1);
    // x = x2 + ffn(ln2(x2))
    ffn_kernel<<<NBLK, TPB, FFN_SMEM_BYTES>>>(scratch, out, fW1, fb1, fW2, fb2, g2, be2);
}

// round 2
// speedup vs baseline: 1.0312x; 1.0312x over previous
#include <cuda_runtime.h>
#include <math.h>

#define NTOK (32768*16)          // 524288 tokens
#define TPB  256
#define TOKS 64                  // tokens per CTA
#define NBLK (NTOK/TOKS)         // 8192 CTAs

// ping-pong scratch (static device array: allocation-free)
__device__ float g_scratch[(size_t)NTOK * 64];

// ---------- packed f32x2 helpers ----------
__device__ __forceinline__ unsigned long long pk2(float lo, float hi) {
    unsigned long long r;
    asm("mov.b64 %0, {%1, %2};" : "=l"(r) : "f"(lo), "f"(hi));
    return r;
}
__device__ __forceinline__ float2 upk2(unsigned long long v) {
    float2 t;
    asm("mov.b64 {%0, %1}, %2;" : "=f"(t.x), "=f"(t.y) : "l"(v));
    return t;
}
__device__ __forceinline__ unsigned long long ffma2(unsigned long long a, unsigned long long b,
                                                    unsigned long long c) {
    unsigned long long d;
    asm("fma.rn.f32x2 %0, %1, %2, %3;" : "=l"(d) : "l"(a), "l"(b), "l"(c));
    return d;
}

// LayerNorm one token row from gmem into sDst[k*68 + t] (column layout)
__device__ __forceinline__ void ln_to_smem(const float* __restrict__ xrow,
                                           float* __restrict__ sDst, int t,
                                           const float* __restrict__ sg) {
    float xv[64];
    const float4* x4 = (const float4*)xrow;
#pragma unroll
    for (int i = 0; i < 16; i++) {
        float4 v = x4[i];
        xv[4*i] = v.x; xv[4*i+1] = v.y; xv[4*i+2] = v.z; xv[4*i+3] = v.w;
    }
    float mean = 0.f;
#pragma unroll
    for (int d = 0; d < 64; d++) mean += xv[d];
    mean *= (1.f/64.f);
    float var = 0.f;
#pragma unroll
    for (int d = 0; d < 64; d++) { float dv = xv[d] - mean; var += dv*dv; }
    var *= (1.f/64.f);
    float rstd = rsqrtf(var + 1e-5f);
#pragma unroll
    for (int k = 0; k < 64; k++)
        sDst[k*68 + t] = (xv[k] - mean) * rstd * sg[k] + sg[64 + k];
}

// ==================================================================
// FFN kernel: out = x + gelu(LN(x)@W1 + b1)@W2 + b2   (64-token tile)
// ==================================================================
#define FFN_SMEM_FLOATS (16384 + 256*68 + 64*68 + 256*68 + 256 + 64 + 128)
#define FFN_SMEM_BYTES  (FFN_SMEM_FLOATS*4)

__global__ void __launch_bounds__(TPB) ffn_kernel(
    const float* __restrict__ xin, float* __restrict__ xout,
    const float* __restrict__ W1, const float* __restrict__ b1,
    const float* __restrict__ W2, const float* __restrict__ b2,
    const float* __restrict__ g2, const float* __restrict__ be2)
{
    extern __shared__ float sm[];
    float* sW1 = sm;                      // [k][j] stride 256 (native)
    float* sW2 = sW1 + 16384;             // [j][e] stride 68 (padded)
    float* sA  = sW2 + 256*68;            // [k][t] stride 68  (LN out)
    float* sH  = sA  + 64*68;             // [j][t] stride 68  (hidden)
    float* sb1 = sH  + 256*68;            // 256
    float* sb2 = sb1 + 256;               // 64
    float* sg  = sb2 + 64;                // g2(64) be2(64)

    const int tid = threadIdx.x;

    // stage weights
    for (int i = tid; i < 16384; i += TPB) {
        sW1[i] = W1[i];
        int j = i >> 6, e = i & 63;
        sW2[j*68 + e] = W2[i];
    }
    if (tid < 64) { sb2[tid] = b2[tid]; sg[tid] = g2[tid]; sg[64+tid] = be2[tid]; }
    sb1[tid] = b1[tid];

    const size_t base = (size_t)blockIdx.x * TOKS;
    if (tid < TOKS) ln_to_smem(xin + (base + tid)*64, sA, tid, sg);
    __syncthreads();

    // ---------- phase 1: H = gelu(A @ W1 + b1), 8tok x 8hid per thread ----------
    {
        const int tx = tid & 31;          // j0 = tx*8
        const int ty = tid >> 5;          // t0 = ty*8  (warp-uniform -> broadcast A)
        const int j0 = tx*8, t0 = ty*8;
        unsigned long long acc[8][4];
#pragma unroll
        for (int r = 0; r < 8; r++)
#pragma unroll
            for (int p = 0; p < 4; p++) acc[r][p] = 0ull;

#pragma unroll 8
        for (int k = 0; k < 64; k++) {
            float4 a0 = *(const float4*)(sA + k*68 + t0);
            float4 a1 = *(const float4*)(sA + k*68 + t0 + 4);
            ulonglong2 w0 = *(const ulonglong2*)(sW1 + k*256 + j0);
            ulonglong2 w1 = *(const ulonglong2*)(sW1 + k*256 + j0 + 4);
            float av[8] = {a0.x,a0.y,a0.z,a0.w,a1.x,a1.y,a1.z,a1.w};
#pragma unroll
            for (int r = 0; r < 8; r++) {
                unsigned long long ar = pk2(av[r], av[r]);
                acc[r][0] = ffma2(ar, w0.x, acc[r][0]);
                acc[r][1] = ffma2(ar, w0.y, acc[r][1]);
                acc[r][2] = ffma2(ar, w1.x, acc[r][2]);
                acc[r][3] = ffma2(ar, w1.y, acc[r][3]);
            }
        }
        // bias + exact gelu
        float h[8][8];
#pragma unroll
        for (int r = 0; r < 8; r++)
#pragma unroll
            for (int p = 0; p < 4; p++) {
                float2 f = upk2(acc[r][p]);
                float z0 = f.x + sb1[j0 + 2*p];
                float z1 = f.y + sb1[j0 + 2*p + 1];
                h[r][2*p]   = 0.5f*z0*(1.f + erff(z0*0.70710678118654752f));
                h[r][2*p+1] = 0.5f*z1*(1.f + erff(z1*0.70710678118654752f));
            }
        // write H columns: sH[j][t0..t0+8)
#pragma unroll
        for (int c = 0; c < 8; c++) {
            *(float4*)(sH + (j0+c)*68 + t0)     = make_float4(h[0][c],h[1][c],h[2][c],h[3][c]);
            *(float4*)(sH + (j0+c)*68 + t0 + 4) = make_float4(h[4][c],h[5][c],h[6][c],h[7][c]);
        }
    }
    __syncthreads();

    // ---------- phase 2: out = x + H @ W2 + b2, 8tok x 8out tiles, 4-way split-K ----------
    {
        const int ksub = tid & 3;
        const int t0 = ((tid >> 2) & 7) * 8;
        const int e0 = (tid >> 5) * 8;        // warp-uniform
        unsigned long long acc[8][4];
#pragma unroll
        for (int r = 0; r < 8; r++)
#pragma unroll
            for (int p = 0; p < 4; p++) acc[r][p] = 0ull;

#pragma unroll 8
        for (int jj = 0; jj < 64; jj++) {
            int j = ksub + 4*jj;
            float4 a0 = *(const float4*)(sH + j*68 + t0);
            float4 a1 = *(const float4*)(sH + j*68 + t0 + 4);
            ulonglong2 w0 = *(const ulonglong2*)(sW2 + j*68 + e0);
            ulonglong2 w1 = *(const ulonglong2*)(sW2 + j*68 + e0 + 4);
            float av[8] = {a0.x,a0.y,a0.z,a0.w,a1.x,a1.y,a1.z,a1.w};
#pragma unroll
            for (int r = 0; r < 8; r++) {
                unsigned long long ar = pk2(av[r], av[r]);
                acc[r][0] = ffma2(ar, w0.x, acc[r][0]);
                acc[r][1] = ffma2(ar, w0.y, acc[r][1]);
                acc[r][2] = ffma2(ar, w1.x, acc[r][2]);
                acc[r][3] = ffma2(ar, w1.y, acc[r][3]);
            }
        }
        // reduce across ksub lanes (xor 1, xor 2)
        float res[8][8];
#pragma unroll
        for (int r = 0; r < 8; r++)
#pragma unroll
            for (int p = 0; p < 4; p++) {
                float2 f = upk2(acc[r][p]);
                f.x += __shfl_xor_sync(0xffffffffu, f.x, 1);
                f.y += __shfl_xor_sync(0xffffffffu, f.y, 1);
                f.x += __shfl_xor_sync(0xffffffffu, f.x, 2);
                f.y += __shfl_xor_sync(0xffffffffu, f.y, 2);
                res[r][2*p] = f.x; res[r][2*p+1] = f.y;
            }
        if (ksub == 0) {
#pragma unroll
            for (int r = 0; r < 8; r++) {
                const float* xr = xin + (base + t0 + r)*64 + e0;
                float4 x0 = *(const float4*)xr;
                float4 x1 = *(const float4*)(xr + 4);
                float4 o0 = make_float4(x0.x + res[r][0] + sb2[e0+0],
                                        x0.y + res[r][1] + sb2[e0+1],
                                        x0.z + res[r][2] + sb2[e0+2],
                                        x0.w + res[r][3] + sb2[e0+3]);
                float4 o1 = make_float4(x1.x + res[r][4] + sb2[e0+4],
                                        x1.y + res[r][5] + sb2[e0+5],
                                        x1.z + res[r][6] + sb2[e0+6],
                                        x1.w + res[r][7] + sb2[e0+7]);
                float* orow = xout + (base + t0 + r)*64 + e0;
                *(float4*)orow = o0;
                *(float4*)(orow + 4) = o1;
            }
        }
    }
}

// ==================================================================
// Attention kernel: out = x + attn(LN(x))   (64-token tile = 4 batches)
// ==================================================================
#define ATTN_SMEM_FLOATS (64*192 + 64*68 + 64*68 + 192*68 + 192 + 64 + 128)
#define ATTN_SMEM_BYTES  (ATTN_SMEM_FLOATS*4)

template <bool CAUSAL>
__global__ void __launch_bounds__(TPB) attn_kernel(
    const float* __restrict__ xin, float* __restrict__ xout,
    const float* __restrict__ Wq, const float* __restrict__ bq,
    const float* __restrict__ Wk, const float* __restrict__ bk,
    const float* __restrict__ Wv, const float* __restrict__ bv,
    const float* __restrict__ Wp, const float* __restrict__ bp,
    const float* __restrict__ g1, const float* __restrict__ be1)
{
    extern __shared__ float sm[];
    float* sWqkv = sm;                    // [d][c] stride 192; c: 0..63 q, 64..127 k, 128..191 v
    float* sWp   = sWqkv + 64*192;        // [c][e] stride 68
    float* sA    = sWp + 64*68;           // [k][t] stride 68 (LN out; reused as sO[c][t])
    float* sQKV  = sA + 64*68;            // [c][t] stride 68
    float* sbqkv = sQKV + 192*68;         // 192
    float* sbp   = sbqkv + 192;           // 64
    float* sg    = sbp + 64;              // g1(64) be1(64)

    const int tid = threadIdx.x;

    for (int i = tid; i < 4096; i += TPB) {
        int h = i >> 9, d = (i >> 3) & 63, s = i & 7;
        int c = h*8 + s;
        sWqkv[d*192 + c]        = Wq[i];
        sWqkv[d*192 + 64 + c]   = Wk[i];
        sWqkv[d*192 + 128 + c]  = Wv[i];
        int pc = i >> 6, pe = i & 63;
        sWp[pc*68 + pe] = Wp[i];
    }
    if (tid < 192) sbqkv[tid] = (tid < 64) ? bq[tid] : (tid < 128 ? bk[tid-64] : bv[tid-128]);
    if (tid < 64)  sbp[tid] = bp[tid];
    if (tid < 128) sg[tid] = (tid < 64) ? g1[tid] : be1[tid-64];

    const size_t base = (size_t)blockIdx.x * TOKS;
    if (tid < TOKS) ln_to_smem(xin + (base + tid)*64, sA, tid, sg);
    __syncthreads();

    // ---------- phase 1: QKV = A @ Wqkv + b, 4tok x 12col per thread ----------
    {
        const int tx = tid & 15;          // c0 = tx*12
        const int ty = tid >> 4;          // t0 = ty*4
        const int c0 = tx*12, t0 = ty*4;
        unsigned long long acc[4][6];
#pragma unroll
        for (int r = 0; r < 4; r++)
#pragma unroll
            for (int p = 0; p < 6; p++)
                acc[r][p] = pk2(sbqkv[c0 + 2*p], sbqkv[c0 + 2*p + 1]);

#pragma unroll 8
        for (int k = 0; k < 64; k++) {
            float4 a = *(const float4*)(sA + k*68 + t0);
            ulonglong2 w0 = *(const ulonglong2*)(sWqkv + k*192 + c0);
            ulonglong2 w1 = *(const ulonglong2*)(sWqkv + k*192 + c0 + 4);
            ulonglong2 w2 = *(const ulonglong2*)(sWqkv + k*192 + c0 + 8);
            float av[4] = {a.x, a.y, a.z, a.w};
#pragma unroll
            for (int r = 0; r < 4; r++) {
                unsigned long long ar = pk2(av[r], av[r]);
                acc[r][0] = ffma2(ar, w0.x, acc[r][0]);
                acc[r][1] = ffma2(ar, w0.y, acc[r][1]);
                acc[r][2] = ffma2(ar, w1.x, acc[r][2]);
                acc[r][3] = ffma2(ar, w1.y, acc[r][3]);
                acc[r][4] = ffma2(ar, w2.x, acc[r][4]);
                acc[r][5] = ffma2(ar, w2.y, acc[r][5]);
            }
        }
        float v[4][12];
#pragma unroll
        for (int r = 0; r < 4; r++)
#pragma unroll
            for (int p = 0; p < 6; p++) {
                float2 f = upk2(acc[r][p]);
                v[r][2*p] = f.x; v[r][2*p+1] = f.y;
            }
#pragma unroll
        for (int c = 0; c < 12; c++)
            *(float4*)(sQKV + (c0+c)*68 + t0) = make_float4(v[0][c],v[1][c],v[2][c],v[3][c]);
    }
    __syncthreads();

    // ---------- phase 2: attention core; thread = (token, head-pair) ----------
    {
        const int t_loc = tid & 63;
        const int hp    = tid >> 6;       // handles heads hp and hp+4
        const int bb    = t_loc & ~15;    // batch base (CTA-local)
        const int tpos  = t_loc & 15;

#pragma unroll
        for (int hi = 0; hi < 2; hi++) {
            const int h = hp + hi*4;
            float q[8];
#pragma unroll
            for (int s = 0; s < 8; s++) q[s] = sQKV[(h*8+s)*68 + t_loc];

            unsigned long long sc[8];
#pragma unroll
            for (int p = 0; p < 8; p++) sc[p] = 0ull;
#pragma unroll
            for (int s = 0; s < 8; s++) {
                const ulonglong2* kr = (const ulonglong2*)(sQKV + (64 + h*8 + s)*68 + bb);
                unsigned long long qd = pk2(q[s], q[s]);
                ulonglong2 k0 = kr[0], k1 = kr[1], k2 = kr[2], k3 = kr[3];
                sc[0] = ffma2(qd, k0.x, sc[0]); sc[1] = ffma2(qd, k0.y, sc[1]);
                sc[2] = ffma2(qd, k1.x, sc[2]); sc[3] = ffma2(qd, k1.y, sc[3]);
                sc[4] = ffma2(qd, k2.x, sc[4]); sc[5] = ffma2(qd, k2.y, sc[5]);
                sc[6] = ffma2(qd, k3.x, sc[6]); sc[7] = ffma2(qd, k3.y, sc[7]);
            }
            float scf[16];
            float mx = -1e30f;
#pragma unroll
            for (int p = 0; p < 8; p++) {
                float2 f = upk2(sc[p]);
                scf[2*p]   = f.x * 0.35355339059327373f;
                scf[2*p+1] = f.y * 0.35355339059327373f;
            }
#pragma unroll
            for (int u = 0; u < 16; u++) {
                if (CAUSAL && u > tpos) scf[u] = -1e30f;
                mx = fmaxf(mx, scf[u]);
            }
            float sum = 0.f;
#pragma unroll
            for (int u = 0; u < 16; u++) { float e = __expf(scf[u] - mx); scf[u] = e; sum += e; }
            const float inv = 1.f / sum;

            unsigned long long wv[8];
#pragma unroll
            for (int p = 0; p < 8; p++) wv[p] = pk2(scf[2*p], scf[2*p+1]);
#pragma unroll
            for (int s = 0; s < 8; s++) {
                const ulonglong2* vr = (const ulonglong2*)(sQKV + (128 + h*8 + s)*68 + bb);
                ulonglong2 v0 = vr[0], v1 = vr[1], v2 = vr[2], v3 = vr[3];
                unsigned long long a = 0ull;
                a = ffma2(wv[0], v0.x, a); a = ffma2(wv[1], v0.y, a);
                a = ffma2(wv[2], v1.x, a); a = ffma2(wv[3], v1.y, a);
                a = ffma2(wv[4], v2.x, a); a = ffma2(wv[5], v2.y, a);
                a = ffma2(wv[6], v3.x, a); a = ffma2(wv[7], v3.y, a);
                float2 f = upk2(a);
                sA[(h*8+s)*68 + t_loc] = (f.x + f.y) * inv;   // sA reused as sO
            }
        }
    }
    __syncthreads();

    // ---------- phase 3: out = x + O @ Wp + bp, 8tok x 8out tiles, 4-way split-K ----------
    {
        const int ksub = tid & 3;
        const int t0 = ((tid >> 2) & 7) * 8;
        const int e0 = (tid >> 5) * 8;
        unsigned long long acc[8][4];
#pragma unroll
        for (int r = 0; r < 8; r++)
#pragma unroll
            for (int p = 0; p < 4; p++) acc[r][p] = 0ull;

#pragma unroll 4
        for (int cc = 0; cc < 16; cc++) {
            int c = ksub + 4*cc;
            float4 a0 = *(const float4*)(sA + c*68 + t0);
            float4 a1 = *(const float4*)(sA + c*68 + t0 + 4);
            ulonglong2 w0 = *(const ulonglong2*)(sWp + c*68 + e0);
            ulonglong2 w1 = *(const ulonglong2*)(sWp + c*68 + e0 + 4);
            float av[8] = {a0.x,a0.y,a0.z,a0.w,a1.x,a1.y,a1.z,a1.w};
#pragma unroll
            for (int r = 0; r < 8; r++) {
                unsigned long long ar = pk2(av[r], av[r]);
                acc[r][0] = ffma2(ar, w0.x, acc[r][0]);
                acc[r][1] = ffma2(ar, w0.y, acc[r][1]);
                acc[r][2] = ffma2(ar, w1.x, acc[r][2]);
                acc[r][3] = ffma2(ar, w1.y, acc[r][3]);
            }
        }
        float res[8][8];
#pragma unroll
        for (int r = 0; r < 8; r++)
#pragma unroll
            for (int p = 0; p < 4; p++) {
                float2 f = upk2(acc[r][p]);
                f.x += __shfl_xor_sync(0xffffffffu, f.x, 1);
                f.y += __shfl_xor_sync(0xffffffffu, f.y, 1);
                f.x += __shfl_xor_sync(0xffffffffu, f.x, 2);
                f.y += __shfl_xor_sync(0xffffffffu, f.y, 2);
                res[r][2*p] = f.x; res[r][2*p+1] = f.y;
            }
        if (ksub == 0) {
#pragma unroll
            for (int r = 0; r < 8; r++) {
                const float* xr = xin + (base + t0 + r)*64 + e0;
                float4 x0 = *(const float4*)xr;
                float4 x1 = *(const float4*)(xr + 4);
                float4 o0 = make_float4(x0.x + res[r][0] + sbp[e0+0],
                                        x0.y + res[r][1] + sbp[e0+1],
                                        x0.z + res[r][2] + sbp[e0+2],
                                        x0.w + res[r][3] + sbp[e0+3]);
                float4 o1 = make_float4(x1.x + res[r][4] + sbp[e0+4],
                                        x1.y + res[r][5] + sbp[e0+5],
                                        x1.z + res[r][6] + sbp[e0+6],
                                        x1.w + res[r][7] + sbp[e0+7]);
                float* orow = xout + (base + t0 + r)*64 + e0;
                *(float4*)orow = o0;
                *(float4*)(orow + 4) = o1;
            }
        }
    }
}

// ==================================================================
// launch: attn(u) -> ffn -> attn(m, causal) -> ffn
// ==================================================================
extern "C" void kernel_launch(void* const* d_in, const int* in_sizes, int n_in,
                              void* d_out, int out_size)
{
    (void)in_sizes; (void)n_in; (void)out_size;
    const float* x   = (const float*)d_in[0];
    const float* uWq = (const float*)d_in[1];  const float* ubq = (const float*)d_in[2];
    const float* uWk = (const float*)d_in[3];  const float* ubk = (const float*)d_in[4];
    const float* uWv = (const float*)d_in[5];  const float* ubv = (const float*)d_in[6];
    const float* uWp = (const float*)d_in[7];  const float* ubp = (const float*)d_in[8];
    const float* mWq = (const float*)d_in[9];  const float* mbq = (const float*)d_in[10];
    const float* mWk = (const float*)d_in[11]; const float* mbk = (const float*)d_in[12];
    const float* mWv = (const float*)d_in[13]; const float* mbv = (const float*)d_in[14];
    const float* mWp = (const float*)d_in[15]; const float* mbp = (const float*)d_in[16];
    const float* fW1 = (const float*)d_in[17]; const float* fb1 = (const float*)d_in[18];
    const float* fW2 = (const float*)d_in[19]; const float* fb2 = (const float*)d_in[20];
    const float* g1  = (const float*)d_in[21]; const float* be1 = (const float*)d_in[22];
    const float* g2  = (const float*)d_in[23]; const float* be2 = (const float*)d_in[24];
    float* out = (float*)d_out;

    float* scratch = nullptr;
    cudaGetSymbolAddress((void**)&scratch, g_scratch);

    cudaFuncSetAttribute(attn_kernel<false>, cudaFuncAttributeMaxDynamicSharedMemorySize, ATTN_SMEM_BYTES);
    cudaFuncSetAttribute(attn_kernel<true>,  cudaFuncAttributeMaxDynamicSharedMemorySize, ATTN_SMEM_BYTES);
    cudaFuncSetAttribute(ffn_kernel,         cudaFuncAttributeMaxDynamicSharedMemorySize, FFN_SMEM_BYTES);

    attn_kernel<false><<<NBLK, TPB, ATTN_SMEM_BYTES>>>(x, scratch,
        uWq, ubq, uWk, ubk, uWv, ubv, uWp, ubp, g1, be1);
    ffn_kernel<<<NBLK, TPB, FFN_SMEM_BYTES>>>(scratch, out, fW1, fb1, fW2, fb2, g2, be2);
    attn_kernel<true><<<NBLK, TPB, ATTN_SMEM_BYTES>>>(out, scratch,
        mWq, mbq, mWk, mbk, mWv, mbv, mWp, mbp, g1, be1);
    ffn_kernel<<<NBLK, TPB, FFN_SMEM_BYTES>>>(scratch, out, fW1, fb1, fW2, fb2, g2, be2);
}

// round 4
// speedup vs baseline: 3.7651x; 3.6510x over previous
#include <cuda_runtime.h>
#include <cuda_bf16.h>
#include <math.h>

#define NTOK (32768*16)          // 524288 tokens
#define TPB  256
#define TOKS 64                  // tokens per CTA
#define NBLK (NTOK/TOKS)         // 8192 CTAs

// ---------------- device globals (allocation-free scratch) ----------------
__device__ float g_scratch[(size_t)NTOK * 64];
__device__ __align__(16) __nv_bfloat16 g_W1b[64*256];
__device__ __align__(16) __nv_bfloat16 g_W2b[256*64];
__device__ __align__(16) __nv_bfloat16 g_Tu[64*192];   // [d][h*8+s (+0/64/128 for q/k/v)]
__device__ __align__(16) __nv_bfloat16 g_Tm[64*192];
__device__ __align__(16) __nv_bfloat16 g_Wpu[64*64];
__device__ __align__(16) __nv_bfloat16 g_Wpm[64*64];

// ---------------- small helpers ----------------
__device__ __forceinline__ unsigned long long pk2(float lo, float hi) {
    unsigned long long r;
    asm("mov.b64 %0, {%1, %2};" : "=l"(r) : "f"(lo), "f"(hi));
    return r;
}
__device__ __forceinline__ float2 upk2(unsigned long long v) {
    float2 t;
    asm("mov.b64 {%0, %1}, %2;" : "=f"(t.x), "=f"(t.y) : "l"(v));
    return t;
}
__device__ __forceinline__ unsigned long long ffma2(unsigned long long a, unsigned long long b,
                                                    unsigned long long c) {
    unsigned long long d;
    asm("fma.rn.f32x2 %0, %1, %2, %3;" : "=l"(d) : "l"(a), "l"(b), "l"(c));
    return d;
}
// pack two floats to bf16x2 (low=a, high=b) via single cvt instruction
__device__ __forceinline__ unsigned bf2u(float a, float b) {
    unsigned r;
    asm("cvt.rn.bf16x2.f32 %0, %1, %2;" : "=r"(r) : "f"(b), "f"(a));
    return r;
}
__device__ __forceinline__ unsigned su32(const void* p) {
    return (unsigned)__cvta_generic_to_shared(p);
}

#define LDSM4(r0,r1,r2,r3,addr) \
    asm volatile("ldmatrix.sync.aligned.m8n8.x4.shared.b16 {%0,%1,%2,%3},[%4];" \
        : "=r"(r0),"=r"(r1),"=r"(r2),"=r"(r3) : "r"(addr))
#define LDSM4T(r0,r1,r2,r3,addr) \
    asm volatile("ldmatrix.sync.aligned.m8n8.x4.trans.shared.b16 {%0,%1,%2,%3},[%4];" \
        : "=r"(r0),"=r"(r1),"=r"(r2),"=r"(r3) : "r"(addr))
#define MMA16816(c0,c1,c2,c3,a0,a1,a2,a3,b0,b1) \
    asm volatile("mma.sync.aligned.m16n8k16.row.col.f32.bf16.bf16.f32 " \
        "{%0,%1,%2,%3},{%4,%5,%6,%7},{%8,%9},{%0,%1,%2,%3};" \
        : "+f"(c0),"+f"(c1),"+f"(c2),"+f"(c3) \
        : "r"(a0),"r"(a1),"r"(a2),"r"(a3),"r"(b0),"r"(b1))

// LayerNorm token row -> bf16 row-major [t][64] XOR-swizzled (128B rows)
__device__ __forceinline__ void ln_row_bf16(const float* __restrict__ xrow,
                                            char* __restrict__ sA, int t,
                                            const float* __restrict__ sg) {
    float xv[64];
    const float4* x4 = (const float4*)xrow;
#pragma unroll
    for (int i = 0; i < 16; i++) {
        float4 v = x4[i];
        xv[4*i] = v.x; xv[4*i+1] = v.y; xv[4*i+2] = v.z; xv[4*i+3] = v.w;
    }
    float mean = 0.f;
#pragma unroll
    for (int d = 0; d < 64; d++) mean += xv[d];
    mean *= (1.f/64.f);
    float var = 0.f;
#pragma unroll
    for (int d = 0; d < 64; d++) { float dv = xv[d] - mean; var += dv*dv; }
    var *= (1.f/64.f);
    float rstd = rsqrtf(var + 1e-5f);
#pragma unroll
    for (int c = 0; c < 8; c++) {
        float v[8];
#pragma unroll
        for (int e = 0; e < 8; e++) {
            int k = c*8 + e;
            v[e] = (xv[k] - mean) * rstd * sg[k] + sg[64 + k];
        }
        uint4 q;
        q.x = bf2u(v[0], v[1]); q.y = bf2u(v[2], v[3]);
        q.z = bf2u(v[4], v[5]); q.w = bf2u(v[6], v[7]);
        *(uint4*)(sA + t*128 + ((c ^ (t & 7)) << 4)) = q;
    }
}

// ---------------- prep: fp32 weights -> bf16 (and qkv transpose) ----------------
__global__ void prep_kernel(const float* __restrict__ W1, const float* __restrict__ W2,
                            const float* __restrict__ uWq, const float* __restrict__ uWk,
                            const float* __restrict__ uWv, const float* __restrict__ uWp,
                            const float* __restrict__ mWq, const float* __restrict__ mWk,
                            const float* __restrict__ mWv, const float* __restrict__ mWp)
{
    int i0 = blockIdx.x * blockDim.x + threadIdx.x;
    int stride = gridDim.x * blockDim.x;
    for (int i = i0; i < 16384; i += stride) {
        g_W1b[i] = __float2bfloat16(W1[i]);
        g_W2b[i] = __float2bfloat16(W2[i]);
    }
    for (int i = i0; i < 4096; i += stride) {
        int h = i >> 9, d = (i >> 3) & 63, s = i & 7;
        int c = h*8 + s;
        g_Tu[d*192 + c]       = __float2bfloat16(uWq[i]);
        g_Tu[d*192 + 64 + c]  = __float2bfloat16(uWk[i]);
        g_Tu[d*192 + 128 + c] = __float2bfloat16(uWv[i]);
        g_Tm[d*192 + c]       = __float2bfloat16(mWq[i]);
        g_Tm[d*192 + 64 + c]  = __float2bfloat16(mWk[i]);
        g_Tm[d*192 + 128 + c] = __float2bfloat16(mWv[i]);
        g_Wpu[i] = __float2bfloat16(uWp[i]);
        g_Wpm[i] = __float2bfloat16(mWp[i]);
    }
}

// ==================================================================
// FFN kernel: out = x + gelu(LN(x)@W1 + b1)@W2 + b2 (64-token tile)
// smem: sW1[64][512B] | sW2[256][128B] | sH[64][512B] | sA[64][128B] | biases
// ==================================================================
#define FFN_SW1  0
#define FFN_SW2  32768
#define FFN_SH   65536
#define FFN_SA   98304
#define FFN_SB1  106496
#define FFN_SB2  107520
#define FFN_SG   107776
#define FFN_SMEM_BYTES 108288

__global__ void __launch_bounds__(TPB, 2) ffn_kernel(
    const float* __restrict__ xin, float* __restrict__ xout,
    const float* __restrict__ b1, const float* __restrict__ b2,
    const float* __restrict__ g2, const float* __restrict__ be2)
{
    extern __shared__ char smc[];
    float* sb1 = (float*)(smc + FFN_SB1);
    float* sb2 = (float*)(smc + FFN_SB2);
    float* sg  = (float*)(smc + FFN_SG);

    const int tid = threadIdx.x;
    const unsigned sbase = su32(smc);

    // stage bf16 weights with XOR swizzle
    {
        const uint4* src1 = (const uint4*)g_W1b;   // 2048 x 16B : row=c>>5, ch=c&31
        const uint4* src2 = (const uint4*)g_W2b;   // 2048 x 16B : row=c>>3, ch=c&7
        for (int c = tid; c < 2048; c += TPB) {
            int r1 = c >> 5, c1 = c & 31;
            *(uint4*)(smc + FFN_SW1 + r1*512 + ((c1 ^ (r1 & 7)) << 4)) = src1[c];
            int r2 = c >> 3, c2 = c & 7;
            *(uint4*)(smc + FFN_SW2 + r2*128 + ((c2 ^ (r2 & 7)) << 4)) = src2[c];
        }
    }
    sb1[tid] = b1[tid];
    if (tid < 64) { sb2[tid] = b2[tid]; sg[tid] = g2[tid]; sg[64+tid] = be2[tid]; }
    __syncthreads();

    const size_t base = (size_t)blockIdx.x * TOKS;
    if (tid < TOKS) ln_row_bf16(xin + (base + tid)*64, smc + FFN_SA, tid, sg);
    __syncthreads();

    const int lane = tid & 31, wid = tid >> 5;
    const int gid = lane >> 2, tig = lane & 3;
    const int tw = wid & 3, nh = wid >> 2;
    const int t0 = tw * 16;

    // ---------- phase 1: H = gelu(A @ W1 + b1); warp = 16t x 128j ----------
    {
        const int jbase = nh * 128;
        float acc[16][4];
#pragma unroll
        for (int m = 0; m < 16; m++)
#pragma unroll
            for (int p = 0; p < 4; p++) acc[m][p] = 0.f;

#pragma unroll
        for (int ks = 0; ks < 4; ks++) {
            const int k0 = ks * 16;
            unsigned a0,a1,a2,a3;
            {
                int ar = t0 + (lane & 15);
                int ac = (k0 >> 3) + (lane >> 4);
                unsigned aaddr = sbase + FFN_SA + ar*128 + ((ac ^ (ar & 7)) << 4);
                LDSM4(a0,a1,a2,a3, aaddr);
            }
#pragma unroll
            for (int st = 0; st < 8; st++) {
                int n0 = jbase + st * 16;
                unsigned b0,b1r,b2,b3;
                int br = k0 + (lane & 15);
                int bc = (n0 >> 3) + (lane >> 4);
                unsigned baddr = sbase + FFN_SW1 + br*512 + ((bc ^ (br & 7)) << 4);
                LDSM4T(b0,b1r,b2,b3, baddr);
                MMA16816(acc[2*st][0],acc[2*st][1],acc[2*st][2],acc[2*st][3],
                         a0,a1,a2,a3, b0,b1r);
                MMA16816(acc[2*st+1][0],acc[2*st+1][1],acc[2*st+1][2],acc[2*st+1][3],
                         a0,a1,a2,a3, b2,b3);
            }
        }
        // bias + exact gelu + store bf16 to sH [t][256] swizzled
        const int r0 = t0 + gid, r1 = t0 + gid + 8;
#pragma unroll
        for (int m = 0; m < 16; m++) {
            int col = jbase + m*8 + 2*tig;
            float bb0 = sb1[col], bb1 = sb1[col+1];
            float z00 = acc[m][0] + bb0, z01 = acc[m][1] + bb1;
            float z10 = acc[m][2] + bb0, z11 = acc[m][3] + bb1;
            float h00 = 0.5f*z00*(1.f + erff(z00*0.70710678118654752f));
            float h01 = 0.5f*z01*(1.f + erff(z01*0.70710678118654752f));
            float h10 = 0.5f*z10*(1.f + erff(z10*0.70710678118654752f));
            float h11 = 0.5f*z11*(1.f + erff(z11*0.70710678118654752f));
            int ch = col >> 3, off = (col & 7) << 1;
            *(unsigned*)(smc + FFN_SH + r0*512 + ((ch ^ (r0 & 7)) << 4) + off) = bf2u(h00, h01);
            *(unsigned*)(smc + FFN_SH + r1*512 + ((ch ^ (r1 & 7)) << 4) + off) = bf2u(h10, h11);
        }
    }
    __syncthreads();

    // ---------- phase 2: out = x + H @ W2 + b2; warp = 16t x 32e ----------
    {
        const int ebase = nh * 32;
        float acc[4][4];
#pragma unroll
        for (int m = 0; m < 4; m++)
#pragma unroll
            for (int p = 0; p < 4; p++) acc[m][p] = 0.f;

#pragma unroll
        for (int ks = 0; ks < 16; ks++) {
            const int k0 = ks * 16;
            unsigned a0,a1,a2,a3;
            {
                int ar = t0 + (lane & 15);
                int ac = (k0 >> 3) + (lane >> 4);
                unsigned aaddr = sbase + FFN_SH + ar*512 + ((ac ^ (ar & 7)) << 4);
                LDSM4(a0,a1,a2,a3, aaddr);
            }
#pragma unroll
            for (int st = 0; st < 2; st++) {
                int n0 = ebase + st * 16;
                unsigned b0,b1r,b2,b3;
                int br = k0 + (lane & 15);
                int bc = (n0 >> 3) + (lane >> 4);
                unsigned baddr = sbase + FFN_SW2 + br*128 + ((bc ^ (br & 7)) << 4);
                LDSM4T(b0,b1r,b2,b3, baddr);
                MMA16816(acc[2*st][0],acc[2*st][1],acc[2*st][2],acc[2*st][3],
                         a0,a1,a2,a3, b0,b1r);
                MMA16816(acc[2*st+1][0],acc[2*st+1][1],acc[2*st+1][2],acc[2*st+1][3],
                         a0,a1,a2,a3, b2,b3);
            }
        }
        const int r0 = t0 + gid, r1 = t0 + gid + 8;
#pragma unroll
        for (int m = 0; m < 4; m++) {
            int e = ebase + m*8 + 2*tig;
            float bb0 = sb2[e], bb1 = sb2[e+1];
            const float2* xr0 = (const float2*)(xin + (base + r0)*64 + e);
            const float2* xr1 = (const float2*)(xin + (base + r1)*64 + e);
            float2 x0 = *xr0, x1 = *xr1;
            float2 o0 = make_float2(x0.x + acc[m][0] + bb0, x0.y + acc[m][1] + bb1);
            float2 o1 = make_float2(x1.x + acc[m][2] + bb0, x1.y + acc[m][3] + bb1);
            *(float2*)(xout + (base + r0)*64 + e) = o0;
            *(float2*)(xout + (base + r1)*64 + e) = o1;
        }
    }
}

// ==================================================================
// Attention kernel: out = x + attn(LN(x)) (64-token tile, 4 batches)
// smem: sT[64][384B] | sWp[64][128B] | sA[64][128B] | sOb[64][128B] |
//       sQKV fp32 [192][68] | biases
// ==================================================================
#define ATT_ST    0
#define ATT_SWP   24576
#define ATT_SA    32768
#define ATT_SOB   40960
#define ATT_SQKV  49152
#define ATT_SBQKV 101376
#define ATT_SBP   102144
#define ATT_SG    102400
#define ATT_SMEM_BYTES 102912

template <bool CAUSAL>
__global__ void __launch_bounds__(TPB, 2) attn_kernel(
    const float* __restrict__ xin, float* __restrict__ xout,
    const __nv_bfloat16* __restrict__ Tqkv, const __nv_bfloat16* __restrict__ Wpb,
    const float* __restrict__ bq, const float* __restrict__ bk,
    const float* __restrict__ bv, const float* __restrict__ bp,
    const float* __restrict__ g1, const float* __restrict__ be1)
{
    extern __shared__ char smc[];
    float* sQKVf = (float*)(smc + ATT_SQKV);   // [c][68]
    float* sbqkv = (float*)(smc + ATT_SBQKV);  // 192
    float* sbp   = (float*)(smc + ATT_SBP);    // 64
    float* sg    = (float*)(smc + ATT_SG);     // 128

    const int tid = threadIdx.x;
    const unsigned sbase = su32(smc);

    // stage bf16 weights
    {
        const uint4* srcT = (const uint4*)Tqkv;   // 64 rows x 24 chunks = 1536
        for (int c = tid; c < 1536; c += TPB) {
            int r = c / 24, ch = c % 24;
            *(uint4*)(smc + ATT_ST + r*384 + ((ch ^ (r & 7)) << 4)) = srcT[c];
        }
        const uint4* srcP = (const uint4*)Wpb;    // 64 rows x 8 chunks = 512
        for (int c = tid; c < 512; c += TPB) {
            int r = c >> 3, ch = c & 7;
            *(uint4*)(smc + ATT_SWP + r*128 + ((ch ^ (r & 7)) << 4)) = srcP[c];
        }
    }
    if (tid < 192) sbqkv[tid] = (tid < 64) ? bq[tid] : (tid < 128 ? bk[tid-64] : bv[tid-128]);
    if (tid < 64)  sbp[tid] = bp[tid];
    if (tid < 128) sg[tid] = (tid < 64) ? g1[tid] : be1[tid-64];
    __syncthreads();

    const size_t base = (size_t)blockIdx.x * TOKS;
    if (tid < TOKS) ln_row_bf16(xin + (base + tid)*64, smc + ATT_SA, tid, sg);
    __syncthreads();

    const int lane = tid & 31, wid = tid >> 5;
    const int gid = lane >> 2, tig = lane & 3;
    const int tw = wid & 3, nh = wid >> 2;
    const int t0 = tw * 16;

    // ---------- phase 1: QKV = A @ T + b ; warp = 16t x 96c ----------
    {
        const int cbase = nh * 96;
        float acc[12][4];
#pragma unroll
        for (int m = 0; m < 12; m++)
#pragma unroll
            for (int p = 0; p < 4; p++) acc[m][p] = 0.f;

#pragma unroll
        for (int ks = 0; ks < 4; ks++) {
            const int k0 = ks * 16;
            unsigned a0,a1,a2,a3;
            {
                int ar = t0 + (lane & 15);
                int ac = (k0 >> 3) + (lane >> 4);
                unsigned aaddr = sbase + ATT_SA + ar*128 + ((ac ^ (ar & 7)) << 4);
                LDSM4(a0,a1,a2,a3, aaddr);
            }
#pragma unroll
            for (int st = 0; st < 6; st++) {
                int n0 = cbase + st * 16;
                unsigned b0,b1r,b2,b3;
                int br = k0 + (lane & 15);
                int bc = (n0 >> 3) + (lane >> 4);
                unsigned baddr = sbase + ATT_ST + br*384 + ((bc ^ (br & 7)) << 4);
                LDSM4T(b0,b1r,b2,b3, baddr);
                MMA16816(acc[2*st][0],acc[2*st][1],acc[2*st][2],acc[2*st][3],
                         a0,a1,a2,a3, b0,b1r);
                MMA16816(acc[2*st+1][0],acc[2*st+1][1],acc[2*st+1][2],acc[2*st+1][3],
                         a0,a1,a2,a3, b2,b3);
            }
        }
        // write fp32 QKV to [c][68] (conflict-free scalar STS)
        const int r0 = t0 + gid, r1 = t0 + gid + 8;
#pragma unroll
        for (int m = 0; m < 12; m++) {
            int c = cbase + m*8 + 2*tig;
            float bb0 = sbqkv[c], bb1 = sbqkv[c+1];
            sQKVf[c*68 + r0]     = acc[m][0] + bb0;
            sQKVf[(c+1)*68 + r0] = acc[m][1] + bb1;
            sQKVf[c*68 + r1]     = acc[m][2] + bb0;
            sQKVf[(c+1)*68 + r1] = acc[m][3] + bb1;
        }
    }
    __syncthreads();

    // ---------- phase 2: attention core (fp32); thread = (token, head-pair) ----------
    {
        const int t_loc = tid & 63;
        const int hp    = tid >> 6;
        const int bb    = t_loc & ~15;
        const int tpos  = t_loc & 15;

#pragma unroll
        for (int hi = 0; hi < 2; hi++) {
            const int h = hp + hi*4;
            float q[8];
#pragma unroll
            for (int s = 0; s < 8; s++) q[s] = sQKVf[(h*8+s)*68 + t_loc];

            unsigned long long sc[8];
#pragma unroll
            for (int p = 0; p < 8; p++) sc[p] = 0ull;
#pragma unroll
            for (int s = 0; s < 8; s++) {
                const ulonglong2* kr = (const ulonglong2*)(sQKVf + (64 + h*8 + s)*68 + bb);
                unsigned long long qd = pk2(q[s], q[s]);
                ulonglong2 k0 = kr[0], k1 = kr[1], k2 = kr[2], k3 = kr[3];
                sc[0] = ffma2(qd, k0.x, sc[0]); sc[1] = ffma2(qd, k0.y, sc[1]);
                sc[2] = ffma2(qd, k1.x, sc[2]); sc[3] = ffma2(qd, k1.y, sc[3]);
                sc[4] = ffma2(qd, k2.x, sc[4]); sc[5] = ffma2(qd, k2.y, sc[5]);
                sc[6] = ffma2(qd, k3.x, sc[6]); sc[7] = ffma2(qd, k3.y, sc[7]);
            }
            float scf[16];
            float mx = -1e30f;
#pragma unroll
            for (int p = 0; p < 8; p++) {
                float2 f = upk2(sc[p]);
                scf[2*p]   = f.x * 0.35355339059327373f;
                scf[2*p+1] = f.y * 0.35355339059327373f;
            }
#pragma unroll
            for (int u = 0; u < 16; u++) {
                if (CAUSAL && u > tpos) scf[u] = -1e30f;
                mx = fmaxf(mx, scf[u]);
            }
            float sum = 0.f;
#pragma unroll
            for (int u = 0; u < 16; u++) { float e = __expf(scf[u] - mx); scf[u] = e; sum += e; }
            const float inv = 1.f / sum;

            unsigned long long wv[8];
#pragma unroll
            for (int p = 0; p < 8; p++) wv[p] = pk2(scf[2*p], scf[2*p+1]);
#pragma unroll
            for (int s = 0; s < 8; s++) {
                const ulonglong2* vr = (const ulonglong2*)(sQKVf + (128 + h*8 + s)*68 + bb);
                ulonglong2 v0 = vr[0], v1 = vr[1], v2 = vr[2], v3 = vr[3];
                unsigned long long a = 0ull;
                a = ffma2(wv[0], v0.x, a); a = ffma2(wv[1], v0.y, a);
                a = ffma2(wv[2], v1.x, a); a = ffma2(wv[3], v1.y, a);
                a = ffma2(wv[4], v2.x, a); a = ffma2(wv[5], v2.y, a);
                a = ffma2(wv[6], v3.x, a); a = ffma2(wv[7], v3.y, a);
                float2 f = upk2(a);
                int c = h*8 + s;
                unsigned off = ATT_SOB + t_loc*128 + (((c >> 3) ^ (t_loc & 7)) << 4) + ((c & 7) << 1);
                *(__nv_bfloat16*)(smc + off) = __float2bfloat16((f.x + f.y) * inv);
            }
        }
    }
    __syncthreads();

    // ---------- phase 3: out = x + O @ Wp + bp ; warp = 16t x 32e ----------
    {
        const int ebase = nh * 32;
        float acc[4][4];
#pragma unroll
        for (int m = 0; m < 4; m++)
#pragma unroll
            for (int p = 0; p < 4; p++) acc[m][p] = 0.f;

#pragma unroll
        for (int ks = 0; ks < 4; ks++) {
            const int k0 = ks * 16;
            unsigned a0,a1,a2,a3;
            {
                int ar = t0 + (lane & 15);
                int ac = (k0 >> 3) + (lane >> 4);
                unsigned aaddr = sbase + ATT_SOB + ar*128 + ((ac ^ (ar & 7)) << 4);
                LDSM4(a0,a1,a2,a3, aaddr);
            }
#pragma unroll
            for (int st = 0; st < 2; st++) {
                int n0 = ebase + st * 16;
                unsigned b0,b1r,b2,b3;
                int br = k0 + (lane & 15);
                int bc = (n0 >> 3) + (lane >> 4);
                unsigned baddr = sbase + ATT_SWP + br*128 + ((bc ^ (br & 7)) << 4);
                LDSM4T(b0,b1r,b2,b3, baddr);
                MMA16816(acc[2*st][0],acc[2*st][1],acc[2*st][2],acc[2*st][3],
                         a0,a1,a2,a3, b0,b1r);
                MMA16816(acc[2*st+1][0],acc[2*st+1][1],acc[2*st+1][2],acc[2*st+1][3],
                         a0,a1,a2,a3, b2,b3);
            }
        }
        const int r0 = t0 + gid, r1 = t0 + gid + 8;
#pragma unroll
        for (int m = 0; m < 4; m++) {
            int e = ebase + m*8 + 2*tig;
            float bb0 = sbp[e], bb1 = sbp[e+1];
            float2 x0 = *(const float2*)(xin + (base + r0)*64 + e);
            float2 x1 = *(const float2*)(xin + (base + r1)*64 + e);
            float2 o0 = make_float2(x0.x + acc[m][0] + bb0, x0.y + acc[m][1] + bb1);
            float2 o1 = make_float2(x1.x + acc[m][2] + bb0, x1.y + acc[m][3] + bb1);
            *(float2*)(xout + (base + r0)*64 + e) = o0;
            *(float2*)(xout + (base + r1)*64 + e) = o1;
        }
    }
}

// ==================================================================
// launch: prep -> attn(u) -> ffn -> attn(m, causal) -> ffn
// ==================================================================
extern "C" void kernel_launch(void* const* d_in, const int* in_sizes, int n_in,
                              void* d_out, int out_size)
{
    (void)in_sizes; (void)n_in; (void)out_size;
    const float* x   = (const float*)d_in[0];
    const float* uWq = (const float*)d_in[1];  const float* ubq = (const float*)d_in[2];
    const float* uWk = (const float*)d_in[3];  const float* ubk = (const float*)d_in[4];
    const float* uWv = (const float*)d_in[5];  const float* ubv = (const float*)d_in[6];
    const float* uWp = (const float*)d_in[7];  const float* ubp = (const float*)d_in[8];
    const float* mWq = (const float*)d_in[9];  const float* mbq = (const float*)d_in[10];
    const float* mWk = (const float*)d_in[11]; const float* mbk = (const float*)d_in[12];
    const float* mWv = (const float*)d_in[13]; const float* mbv = (const float*)d_in[14];
    const float* mWp = (const float*)d_in[15]; const float* mbp = (const float*)d_in[16];
    const float* fW1 = (const float*)d_in[17]; const float* fb1 = (const float*)d_in[18];
    const float* fW2 = (const float*)d_in[19]; const float* fb2 = (const float*)d_in[20];
    const float* g1  = (const float*)d_in[21]; const float* be1 = (const float*)d_in[22];
    const float* g2  = (const float*)d_in[23]; const float* be2 = (const float*)d_in[24];
    float* out = (float*)d_out;

    float* scratch = nullptr;
    cudaGetSymbolAddress((void**)&scratch, g_scratch);
    __nv_bfloat16 *Tu = nullptr, *Tm = nullptr, *Wpu = nullptr, *Wpm = nullptr;
    cudaGetSymbolAddress((void**)&Tu, g_Tu);
    cudaGetSymbolAddress((void**)&Tm, g_Tm);
    cudaGetSymbolAddress((void**)&Wpu, g_Wpu);
    cudaGetSymbolAddress((void**)&Wpm, g_Wpm);

    cudaFuncSetAttribute(attn_kernel<false>, cudaFuncAttributeMaxDynamicSharedMemorySize, ATT_SMEM_BYTES);
    cudaFuncSetAttribute(attn_kernel<true>,  cudaFuncAttributeMaxDynamicSharedMemorySize, ATT_SMEM_BYTES);
    cudaFuncSetAttribute(ffn_kernel,         cudaFuncAttributeMaxDynamicSharedMemorySize, FFN_SMEM_BYTES);

    prep_kernel<<<32, 256>>>(fW1, fW2, uWq, uWk, uWv, uWp, mWq, mWk, mWv, mWp);

    attn_kernel<false><<<NBLK, TPB, ATT_SMEM_BYTES>>>(x, scratch, Tu, Wpu,
        ubq, ubk, ubv, ubp, g1, be1);
    ffn_kernel<<<NBLK, TPB, FFN_SMEM_BYTES>>>(scratch, out, fb1, fb2, g2, be2);
    attn_kernel<true><<<NBLK, TPB, ATT_SMEM_BYTES>>>(out, scratch, Tm, Wpm,
        mbq, mbk, mbv, mbp, g1, be1);
    ffn_kernel<<<NBLK, TPB, FFN_SMEM_BYTES>>>(scratch, out, fb1, fb2, g2, be2);
}

// round 5
// speedup vs baseline: 4.0674x; 1.0803x over previous
#include <cuda_runtime.h>
#include <cuda_bf16.h>
#include <math.h>

#define NTOK (32768*16)          // 524288 tokens
#define TPB  256
#define TOKS 64                  // tokens per CTA
#define NBLK (NTOK/TOKS)         // 8192 CTAs

// ---------------- device globals (allocation-free scratch) ----------------
__device__ float g_scratch[(size_t)NTOK * 64];
__device__ __align__(16) __nv_bfloat16 g_W1b[64*256];
__device__ __align__(16) __nv_bfloat16 g_W2b[256*64];
__device__ __align__(16) __nv_bfloat16 g_Tu[64*192];   // [d][h*8+s (+0/64/128 for q/k/v)]
__device__ __align__(16) __nv_bfloat16 g_Tm[64*192];
__device__ __align__(16) __nv_bfloat16 g_Wpu[64*64];
__device__ __align__(16) __nv_bfloat16 g_Wpm[64*64];

// ---------------- small helpers ----------------
// pack two floats to bf16x2 (low=a, high=b)
__device__ __forceinline__ unsigned bf2u(float a, float b) {
    unsigned r;
    asm("cvt.rn.bf16x2.f32 %0, %1, %2;" : "=r"(r) : "f"(b), "f"(a));
    return r;
}
__device__ __forceinline__ unsigned su32(const void* p) {
    return (unsigned)__cvta_generic_to_shared(p);
}

#define LDSM2(r0,r1,addr) \
    asm volatile("ldmatrix.sync.aligned.m8n8.x2.shared.b16 {%0,%1},[%2];" \
        : "=r"(r0),"=r"(r1) : "r"(addr))
#define LDSM2T(r0,r1,addr) \
    asm volatile("ldmatrix.sync.aligned.m8n8.x2.trans.shared.b16 {%0,%1},[%2];" \
        : "=r"(r0),"=r"(r1) : "r"(addr))
#define LDSM4(r0,r1,r2,r3,addr) \
    asm volatile("ldmatrix.sync.aligned.m8n8.x4.shared.b16 {%0,%1,%2,%3},[%4];" \
        : "=r"(r0),"=r"(r1),"=r"(r2),"=r"(r3) : "r"(addr))
#define LDSM4T(r0,r1,r2,r3,addr) \
    asm volatile("ldmatrix.sync.aligned.m8n8.x4.trans.shared.b16 {%0,%1,%2,%3},[%4];" \
        : "=r"(r0),"=r"(r1),"=r"(r2),"=r"(r3) : "r"(addr))
#define MMA16816(c0,c1,c2,c3,a0,a1,a2,a3,b0,b1) \
    asm volatile("mma.sync.aligned.m16n8k16.row.col.f32.bf16.bf16.f32 " \
        "{%0,%1,%2,%3},{%4,%5,%6,%7},{%8,%9},{%0,%1,%2,%3};" \
        : "+f"(c0),"+f"(c1),"+f"(c2),"+f"(c3) \
        : "r"(a0),"r"(a1),"r"(a2),"r"(a3),"r"(b0),"r"(b1))
#define MMA16808(c0,c1,c2,c3,a0,a1,b0) \
    asm volatile("mma.sync.aligned.m16n8k8.row.col.f32.bf16.bf16.f32 " \
        "{%0,%1,%2,%3},{%4,%5},{%6},{%0,%1,%2,%3};" \
        : "+f"(c0),"+f"(c1),"+f"(c2),"+f"(c3) \
        : "r"(a0),"r"(a1),"r"(b0))

// LayerNorm token row -> bf16 row-major [t][64] XOR-swizzled (128B rows)
__device__ __forceinline__ void ln_row_bf16(const float* __restrict__ xrow,
                                            char* __restrict__ sA, int t,
                                            const float* __restrict__ sg) {
    float xv[64];
    const float4* x4 = (const float4*)xrow;
#pragma unroll
    for (int i = 0; i < 16; i++) {
        float4 v = x4[i];
        xv[4*i] = v.x; xv[4*i+1] = v.y; xv[4*i+2] = v.z; xv[4*i+3] = v.w;
    }
    float mean = 0.f;
#pragma unroll
    for (int d = 0; d < 64; d++) mean += xv[d];
    mean *= (1.f/64.f);
    float var = 0.f;
#pragma unroll
    for (int d = 0; d < 64; d++) { float dv = xv[d] - mean; var += dv*dv; }
    var *= (1.f/64.f);
    float rstd = rsqrtf(var + 1e-5f);
#pragma unroll
    for (int c = 0; c < 8; c++) {
        float v[8];
#pragma unroll
        for (int e = 0; e < 8; e++) {
            int k = c*8 + e;
            v[e] = (xv[k] - mean) * rstd * sg[k] + sg[64 + k];
        }
        uint4 q;
        q.x = bf2u(v[0], v[1]); q.y = bf2u(v[2], v[3]);
        q.z = bf2u(v[4], v[5]); q.w = bf2u(v[6], v[7]);
        *(uint4*)(sA + t*128 + ((c ^ (t & 7)) << 4)) = q;
    }
}

// ---------------- prep: fp32 weights -> bf16 (and qkv transpose) ----------------
__global__ void prep_kernel(const float* __restrict__ W1, const float* __restrict__ W2,
                            const float* __restrict__ uWq, const float* __restrict__ uWk,
                            const float* __restrict__ uWv, const float* __restrict__ uWp,
                            const float* __restrict__ mWq, const float* __restrict__ mWk,
                            const float* __restrict__ mWv, const float* __restrict__ mWp)
{
    int i0 = blockIdx.x * blockDim.x + threadIdx.x;
    int stride = gridDim.x * blockDim.x;
    for (int i = i0; i < 16384; i += stride) {
        g_W1b[i] = __float2bfloat16(W1[i]);
        g_W2b[i] = __float2bfloat16(W2[i]);
    }
    for (int i = i0; i < 4096; i += stride) {
        int h = i >> 9, d = (i >> 3) & 63, s = i & 7;
        int c = h*8 + s;
        g_Tu[d*192 + c]       = __float2bfloat16(uWq[i]);
        g_Tu[d*192 + 64 + c]  = __float2bfloat16(uWk[i]);
        g_Tu[d*192 + 128 + c] = __float2bfloat16(uWv[i]);
        g_Tm[d*192 + c]       = __float2bfloat16(mWq[i]);
        g_Tm[d*192 + 64 + c]  = __float2bfloat16(mWk[i]);
        g_Tm[d*192 + 128 + c] = __float2bfloat16(mWv[i]);
        g_Wpu[i] = __float2bfloat16(uWp[i]);
        g_Wpm[i] = __float2bfloat16(mWp[i]);
    }
}

// ==================================================================
// FFN kernel: out = x + gelu(LN(x)@W1 + b1)@W2 + b2 (64-token tile)
// ==================================================================
#define FFN_SW1  0
#define FFN_SW2  32768
#define FFN_SH   65536
#define FFN_SA   98304
#define FFN_SB1  106496
#define FFN_SB2  107520
#define FFN_SG   107776
#define FFN_SMEM_BYTES 108288

__global__ void __launch_bounds__(TPB, 2) ffn_kernel(
    const float* __restrict__ xin, float* __restrict__ xout,
    const float* __restrict__ b1, const float* __restrict__ b2,
    const float* __restrict__ g2, const float* __restrict__ be2)
{
    extern __shared__ char smc[];
    float* sb1 = (float*)(smc + FFN_SB1);
    float* sb2 = (float*)(smc + FFN_SB2);
    float* sg  = (float*)(smc + FFN_SG);

    const int tid = threadIdx.x;
    const unsigned sbase = su32(smc);

    {
        const uint4* src1 = (const uint4*)g_W1b;
        const uint4* src2 = (const uint4*)g_W2b;
        for (int c = tid; c < 2048; c += TPB) {
            int r1 = c >> 5, c1 = c & 31;
            *(uint4*)(smc + FFN_SW1 + r1*512 + ((c1 ^ (r1 & 7)) << 4)) = src1[c];
            int r2 = c >> 3, c2 = c & 7;
            *(uint4*)(smc + FFN_SW2 + r2*128 + ((c2 ^ (r2 & 7)) << 4)) = src2[c];
        }
    }
    sb1[tid] = b1[tid];
    if (tid < 64) { sb2[tid] = b2[tid]; sg[tid] = g2[tid]; sg[64+tid] = be2[tid]; }
    __syncthreads();

    const size_t base = (size_t)blockIdx.x * TOKS;
    if (tid < TOKS) ln_row_bf16(xin + (base + tid)*64, smc + FFN_SA, tid, sg);
    __syncthreads();

    const int lane = tid & 31, wid = tid >> 5;
    const int gid = lane >> 2, tig = lane & 3;
    const int tw = wid & 3, nh = wid >> 2;
    const int t0 = tw * 16;

    // ---------- phase 1: H = gelu(A @ W1 + b1); warp = 16t x 128j ----------
    {
        const int jbase = nh * 128;
        float acc[16][4];
#pragma unroll
        for (int m = 0; m < 16; m++)
#pragma unroll
            for (int p = 0; p < 4; p++) acc[m][p] = 0.f;

#pragma unroll
        for (int ks = 0; ks < 4; ks++) {
            const int k0 = ks * 16;
            unsigned a0,a1,a2,a3;
            {
                int ar = t0 + (lane & 15);
                int ac = (k0 >> 3) + (lane >> 4);
                unsigned aaddr = sbase + FFN_SA + ar*128 + ((ac ^ (ar & 7)) << 4);
                LDSM4(a0,a1,a2,a3, aaddr);
            }
#pragma unroll
            for (int st = 0; st < 8; st++) {
                int n0 = jbase + st * 16;
                unsigned b0,b1r,b2,b3;
                int br = k0 + (lane & 15);
                int bc = (n0 >> 3) + (lane >> 4);
                unsigned baddr = sbase + FFN_SW1 + br*512 + ((bc ^ (br & 7)) << 4);
                LDSM4T(b0,b1r,b2,b3, baddr);
                MMA16816(acc[2*st][0],acc[2*st][1],acc[2*st][2],acc[2*st][3],
                         a0,a1,a2,a3, b0,b1r);
                MMA16816(acc[2*st+1][0],acc[2*st+1][1],acc[2*st+1][2],acc[2*st+1][3],
                         a0,a1,a2,a3, b2,b3);
            }
        }
        const int r0 = t0 + gid, r1 = t0 + gid + 8;
#pragma unroll
        for (int m = 0; m < 16; m++) {
            int col = jbase + m*8 + 2*tig;
            float bb0 = sb1[col], bb1 = sb1[col+1];
            float z00 = acc[m][0] + bb0, z01 = acc[m][1] + bb1;
            float z10 = acc[m][2] + bb0, z11 = acc[m][3] + bb1;
            float h00 = 0.5f*z00*(1.f + erff(z00*0.70710678118654752f));
            float h01 = 0.5f*z01*(1.f + erff(z01*0.70710678118654752f));
            float h10 = 0.5f*z10*(1.f + erff(z10*0.70710678118654752f));
            float h11 = 0.5f*z11*(1.f + erff(z11*0.70710678118654752f));
            int ch = col >> 3, off = (col & 7) << 1;
            *(unsigned*)(smc + FFN_SH + r0*512 + ((ch ^ (r0 & 7)) << 4) + off) = bf2u(h00, h01);
            *(unsigned*)(smc + FFN_SH + r1*512 + ((ch ^ (r1 & 7)) << 4) + off) = bf2u(h10, h11);
        }
    }
    __syncthreads();

    // ---------- phase 2: out = x + H @ W2 + b2; warp = 16t x 32e ----------
    {
        const int ebase = nh * 32;
        float acc[4][4];
#pragma unroll
        for (int m = 0; m < 4; m++)
#pragma unroll
            for (int p = 0; p < 4; p++) acc[m][p] = 0.f;

#pragma unroll
        for (int ks = 0; ks < 16; ks++) {
            const int k0 = ks * 16;
            unsigned a0,a1,a2,a3;
            {
                int ar = t0 + (lane & 15);
                int ac = (k0 >> 3) + (lane >> 4);
                unsigned aaddr = sbase + FFN_SH + ar*512 + ((ac ^ (ar & 7)) << 4);
                LDSM4(a0,a1,a2,a3, aaddr);
            }
#pragma unroll
            for (int st = 0; st < 2; st++) {
                int n0 = ebase + st * 16;
                unsigned b0,b1r,b2,b3;
                int br = k0 + (lane & 15);
                int bc = (n0 >> 3) + (lane >> 4);
                unsigned baddr = sbase + FFN_SW2 + br*128 + ((bc ^ (br & 7)) << 4);
                LDSM4T(b0,b1r,b2,b3, baddr);
                MMA16816(acc[2*st][0],acc[2*st][1],acc[2*st][2],acc[2*st][3],
                         a0,a1,a2,a3, b0,b1r);
                MMA16816(acc[2*st+1][0],acc[2*st+1][1],acc[2*st+1][2],acc[2*st+1][3],
                         a0,a1,a2,a3, b2,b3);
            }
        }
        const int r0 = t0 + gid, r1 = t0 + gid + 8;
#pragma unroll
        for (int m = 0; m < 4; m++) {
            int e = ebase + m*8 + 2*tig;
            float bb0 = sb2[e], bb1 = sb2[e+1];
            float2 x0 = *(const float2*)(xin + (base + r0)*64 + e);
            float2 x1 = *(const float2*)(xin + (base + r1)*64 + e);
            float2 o0 = make_float2(x0.x + acc[m][0] + bb0, x0.y + acc[m][1] + bb1);
            float2 o1 = make_float2(x1.x + acc[m][2] + bb0, x1.y + acc[m][3] + bb1);
            *(float2*)(xout + (base + r0)*64 + e) = o0;
            *(float2*)(xout + (base + r1)*64 + e) = o1;
        }
    }
}

// ==================================================================
// Attention kernel: out = x + attn(LN(x)) (64-token tile, 4 batches)
// smem: sT[24KB] | sWp[8KB] | sA[8KB] | sOb[8KB] | QKV tiles[24KB] | biases
// QKV tiles: per (sec, b, h): 16 rows x 16B bf16 (row = token in batch,
// col = s). sec 0=Q(pre-scaled),1=K,2=V at sec*8192 + (b*8+h)*256.
// ==================================================================
#define ATT_ST    0
#define ATT_SWP   24576
#define ATT_SA    32768
#define ATT_SOB   40960
#define ATT_SQKV  49152
#define ATT_SBQKV 73728
#define ATT_SBP   74496
#define ATT_SG    74752
#define ATT_SMEM_BYTES 75264

template <bool CAUSAL>
__global__ void __launch_bounds__(TPB, 2) attn_kernel(
    const float* __restrict__ xin, float* __restrict__ xout,
    const __nv_bfloat16* __restrict__ Tqkv, const __nv_bfloat16* __restrict__ Wpb,
    const float* __restrict__ bq, const float* __restrict__ bk,
    const float* __restrict__ bv, const float* __restrict__ bp,
    const float* __restrict__ g1, const float* __restrict__ be1)
{
    extern __shared__ char smc[];
    float* sbqkv = (float*)(smc + ATT_SBQKV);
    float* sbp   = (float*)(smc + ATT_SBP);
    float* sg    = (float*)(smc + ATT_SG);

    const int tid = threadIdx.x;
    const unsigned sbase = su32(smc);

    // stage bf16 weights
    {
        const uint4* srcT = (const uint4*)Tqkv;   // 64 rows x 24 chunks
        for (int c = tid; c < 1536; c += TPB) {
            int r = c / 24, ch = c % 24;
            *(uint4*)(smc + ATT_ST + r*384 + ((ch ^ (r & 7)) << 4)) = srcT[c];
        }
        const uint4* srcP = (const uint4*)Wpb;
        for (int c = tid; c < 512; c += TPB) {
            int r = c >> 3, ch = c & 7;
            *(uint4*)(smc + ATT_SWP + r*128 + ((ch ^ (r & 7)) << 4)) = srcP[c];
        }
    }
    if (tid < 192) sbqkv[tid] = (tid < 64) ? bq[tid] : (tid < 128 ? bk[tid-64] : bv[tid-128]);
    if (tid < 64)  sbp[tid] = bp[tid];
    if (tid < 128) sg[tid] = (tid < 64) ? g1[tid] : be1[tid-64];
    __syncthreads();

    const size_t base = (size_t)blockIdx.x * TOKS;
    if (tid < TOKS) ln_row_bf16(xin + (base + tid)*64, smc + ATT_SA, tid, sg);
    __syncthreads();

    const int lane = tid & 31, wid = tid >> 5;
    const int gid = lane >> 2, tig = lane & 3;
    const int tw = wid & 3, nh = wid >> 2;
    const int t0 = tw * 16;

    // ---------- phase 1: QKV = A @ T + b ; warp = batch tw, 96 c-cols ----------
    {
        const int cbase = nh * 96;
        float acc[12][4];
#pragma unroll
        for (int m = 0; m < 12; m++)
#pragma unroll
            for (int p = 0; p < 4; p++) acc[m][p] = 0.f;

#pragma unroll
        for (int ks = 0; ks < 4; ks++) {
            const int k0 = ks * 16;
            unsigned a0,a1,a2,a3;
            {
                int ar = t0 + (lane & 15);
                int ac = (k0 >> 3) + (lane >> 4);
                unsigned aaddr = sbase + ATT_SA + ar*128 + ((ac ^ (ar & 7)) << 4);
                LDSM4(a0,a1,a2,a3, aaddr);
            }
#pragma unroll
            for (int st = 0; st < 6; st++) {
                int n0 = cbase + st * 16;
                unsigned b0,b1r,b2,b3;
                int br = k0 + (lane & 15);
                int bc = (n0 >> 3) + (lane >> 4);
                unsigned baddr = sbase + ATT_ST + br*384 + ((bc ^ (br & 7)) << 4);
                LDSM4T(b0,b1r,b2,b3, baddr);
                MMA16816(acc[2*st][0],acc[2*st][1],acc[2*st][2],acc[2*st][3],
                         a0,a1,a2,a3, b0,b1r);
                MMA16816(acc[2*st+1][0],acc[2*st+1][1],acc[2*st+1][2],acc[2*st+1][3],
                         a0,a1,a2,a3, b2,b3);
            }
        }
        // epilogue: bias (+0.35355 scale for Q), write bf16 tiles [16 x 16B]
#pragma unroll
        for (int m = 0; m < 12; m++) {
            int cc = cbase + m*8;            // 8-aligned: head block
            int sec = cc >> 6;               // 0=q 1=k 2=v
            int h = (cc >> 3) & 7;
            int c = cc + 2*tig;
            float bb0 = sbqkv[c], bb1 = sbqkv[c+1];
            float scale = (sec == 0) ? 0.35355339059327373f : 1.f;
            float v00 = (acc[m][0] + bb0) * scale, v01 = (acc[m][1] + bb1) * scale;
            float v10 = (acc[m][2] + bb0) * scale, v11 = (acc[m][3] + bb1) * scale;
            unsigned tb = ATT_SQKV + sec*8192 + (tw*8 + h)*256 + tig*4;
            *(unsigned*)(smc + tb + gid*16)       = bf2u(v00, v01);
            *(unsigned*)(smc + tb + (gid+8)*16)   = bf2u(v10, v11);
        }
    }
    __syncthreads();

    // ---------- phase 2: MMA attention core; warp handles 4 (b,h) pairs ----------
    {
#pragma unroll
        for (int i = 0; i < 4; i++) {
            const int p = wid*4 + i;
            const int b = p >> 3, h = p & 7;
            const unsigned tq = sbase + ATT_SQKV + (b*8+h)*256 + (lane & 15)*16;

            unsigned qa0, qa1, kb0, kb1, vb0, vb1;
            LDSM2 (qa0, qa1, tq);            // Q a-frag (m16k8), scale folded
            LDSM2 (kb0, kb1, tq + 8192);     // K b-frags (n=u0..7, u8..15)
            LDSM2T(vb0, vb1, tq + 16384);    // V b-frags (k=u, n=s)

            float s0=0,s1=0,s2=0,s3=0,s4=0,s5=0,s6=0,s7=0;
            MMA16808(s0,s1,s2,s3, qa0,qa1, kb0);   // cols u = 2tig,2tig+1
            MMA16808(s4,s5,s6,s7, qa0,qa1, kb1);   // cols u = 2tig+8,2tig+9

            // rows: tlo=gid, thi=gid+8 ; causal mask u > t
            if (CAUSAL) {
                const int u0 = 2*tig, u1 = 2*tig+1, u2 = 2*tig+8, u3 = 2*tig+9;
                if (u0 > gid)   s0 = -1e30f;
                if (u1 > gid)   s1 = -1e30f;
                if (u2 > gid)   s4 = -1e30f;
                if (u3 > gid)   s5 = -1e30f;
                if (u0 > gid+8) s2 = -1e30f;
                if (u1 > gid+8) s3 = -1e30f;
                if (u2 > gid+8) s6 = -1e30f;
                if (u3 > gid+8) s7 = -1e30f;
            }
            // softmax over u (16 vals/row spread across quad)
            float mlo = fmaxf(fmaxf(s0,s1), fmaxf(s4,s5));
            float mhi = fmaxf(fmaxf(s2,s3), fmaxf(s6,s7));
            mlo = fmaxf(mlo, __shfl_xor_sync(0xffffffffu, mlo, 1));
            mlo = fmaxf(mlo, __shfl_xor_sync(0xffffffffu, mlo, 2));
            mhi = fmaxf(mhi, __shfl_xor_sync(0xffffffffu, mhi, 1));
            mhi = fmaxf(mhi, __shfl_xor_sync(0xffffffffu, mhi, 2));
            float e0 = __expf(s0-mlo), e1 = __expf(s1-mlo);
            float e4 = __expf(s4-mlo), e5 = __expf(s5-mlo);
            float e2 = __expf(s2-mhi), e3 = __expf(s3-mhi);
            float e6 = __expf(s6-mhi), e7 = __expf(s7-mhi);
            float slo = e0+e1+e4+e5, shi = e2+e3+e6+e7;
            slo += __shfl_xor_sync(0xffffffffu, slo, 1);
            slo += __shfl_xor_sync(0xffffffffu, slo, 2);
            shi += __shfl_xor_sync(0xffffffffu, shi, 1);
            shi += __shfl_xor_sync(0xffffffffu, shi, 2);
            const float ilo = 1.f/slo, ihi = 1.f/shi;

            // pack P as a-frag of m16n8k16 (k = u)
            unsigned pa0 = bf2u(e0, e1);   // (gid,   u 2tig..)
            unsigned pa1 = bf2u(e2, e3);   // (gid+8, u 2tig..)
            unsigned pa2 = bf2u(e4, e5);   // (gid,   u 2tig+8..)
            unsigned pa3 = bf2u(e6, e7);   // (gid+8, u 2tig+8..)

            float o0=0,o1=0,o2=0,o3=0;
            MMA16816(o0,o1,o2,o3, pa0,pa1,pa2,pa3, vb0,vb1);
            o0 *= ilo; o1 *= ilo; o2 *= ihi; o3 *= ihi;

            // store O (bf16) into sOb [t][64] swizzled rows
            const int tA = b*16 + gid, tB = tA + 8;
            const int c = h*8 + 2*tig;
            unsigned offA = ATT_SOB + tA*128 + (((c>>3) ^ (tA & 7)) << 4) + ((c & 7) << 1);
            unsigned offB = ATT_SOB + tB*128 + (((c>>3) ^ (tB & 7)) << 4) + ((c & 7) << 1);
            *(unsigned*)(smc + offA) = bf2u(o0, o1);
            *(unsigned*)(smc + offB) = bf2u(o2, o3);
        }
    }
    __syncthreads();

    // ---------- phase 3: out = x + O @ Wp + bp ; warp = 16t x 32e ----------
    {
        const int ebase = nh * 32;
        float acc[4][4];
#pragma unroll
        for (int m = 0; m < 4; m++)
#pragma unroll
            for (int p = 0; p < 4; p++) acc[m][p] = 0.f;

#pragma unroll
        for (int ks = 0; ks < 4; ks++) {
            const int k0 = ks * 16;
            unsigned a0,a1,a2,a3;
            {
                int ar = t0 + (lane & 15);
                int ac = (k0 >> 3) + (lane >> 4);
                unsigned aaddr = sbase + ATT_SOB + ar*128 + ((ac ^ (ar & 7)) << 4);
                LDSM4(a0,a1,a2,a3, aaddr);
            }
#pragma unroll
            for (int st = 0; st < 2; st++) {
                int n0 = ebase + st * 16;
                unsigned b0,b1r,b2,b3;
                int br = k0 + (lane & 15);
                int bc = (n0 >> 3) + (lane >> 4);
                unsigned baddr = sbase + ATT_SWP + br*128 + ((bc ^ (br & 7)) << 4);
                LDSM4T(b0,b1r,b2,b3, baddr);
                MMA16816(acc[2*st][0],acc[2*st][1],acc[2*st][2],acc[2*st][3],
                         a0,a1,a2,a3, b0,b1r);
                MMA16816(acc[2*st+1][0],acc[2*st+1][1],acc[2*st+1][2],acc[2*st+1][3],
                         a0,a1,a2,a3, b2,b3);
            }
        }
        const int r0 = t0 + gid, r1 = t0 + gid + 8;
#pragma unroll
        for (int m = 0; m < 4; m++) {
            int e = ebase + m*8 + 2*tig;
            float bb0 = sbp[e], bb1 = sbp[e+1];
            float2 x0 = *(const float2*)(xin + (base + r0)*64 + e);
            float2 x1 = *(const float2*)(xin + (base + r1)*64 + e);
            float2 o0 = make_float2(x0.x + acc[m][0] + bb0, x0.y + acc[m][1] + bb1);
            float2 o1 = make_float2(x1.x + acc[m][2] + bb0, x1.y + acc[m][3] + bb1);
            *(float2*)(xout + (base + r0)*64 + e) = o0;
            *(float2*)(xout + (base + r1)*64 + e) = o1;
        }
    }
}

// ==================================================================
// launch: prep -> attn(u) -> ffn -> attn(m, causal) -> ffn
// ==================================================================
extern "C" void kernel_launch(void* const* d_in, const int* in_sizes, int n_in,
                              void* d_out, int out_size)
{
    (void)in_sizes; (void)n_in; (void)out_size;
    const float* x   = (const float*)d_in[0];
    const float* uWq = (const float*)d_in[1];  const float* ubq = (const float*)d_in[2];
    const float* uWk = (const float*)d_in[3];  const float* ubk = (const float*)d_in[4];
    const float* uWv = (const float*)d_in[5];  const float* ubv = (const float*)d_in[6];
    const float* uWp = (const float*)d_in[7];  const float* ubp = (const float*)d_in[8];
    const float* mWq = (const float*)d_in[9];  const float* mbq = (const float*)d_in[10];
    const float* mWk = (const float*)d_in[11]; const float* mbk = (const float*)d_in[12];
    const float* mWv = (const float*)d_in[13]; const float* mbv = (const float*)d_in[14];
    const float* mWp = (const float*)d_in[15]; const float* mbp = (const float*)d_in[16];
    const float* fW1 = (const float*)d_in[17]; const float* fb1 = (const float*)d_in[18];
    const float* fW2 = (const float*)d_in[19]; const float* fb2 = (const float*)d_in[20];
    const float* g1  = (const float*)d_in[21]; const float* be1 = (const float*)d_in[22];
    const float* g2  = (const float*)d_in[23]; const float* be2 = (const float*)d_in[24];
    float* out = (float*)d_out;

    float* scratch = nullptr;
    cudaGetSymbolAddress((void**)&scratch, g_scratch);
    __nv_bfloat16 *Tu = nullptr, *Tm = nullptr, *Wpu = nullptr, *Wpm = nullptr;
    cudaGetSymbolAddress((void**)&Tu, g_Tu);
    cudaGetSymbolAddress((void**)&Tm, g_Tm);
    cudaGetSymbolAddress((void**)&Wpu, g_Wpu);
    cudaGetSymbolAddress((void**)&Wpm, g_Wpm);

    cudaFuncSetAttribute(attn_kernel<false>, cudaFuncAttributeMaxDynamicSharedMemorySize, ATT_SMEM_BYTES);
    cudaFuncSetAttribute(attn_kernel<true>,  cudaFuncAttributeMaxDynamicSharedMemorySize, ATT_SMEM_BYTES);
    cudaFuncSetAttribute(ffn_kernel,         cudaFuncAttributeMaxDynamicSharedMemorySize, FFN_SMEM_BYTES);

    prep_kernel<<<32, 256>>>(fW1, fW2, uWq, uWk, uWv, uWp, mWq, mWk, mWv, mWp);

    attn_kernel<false><<<NBLK, TPB, ATT_SMEM_BYTES>>>(x, scratch, Tu, Wpu,
        ubq, ubk, ubv, ubp, g1, be1);
    ffn_kernel<<<NBLK, TPB, FFN_SMEM_BYTES>>>(scratch, out, fb1, fb2, g2, be2);
    attn_kernel<true><<<NBLK, TPB, ATT_SMEM_BYTES>>>(out, scratch, Tm, Wpm,
        mbq, mbk, mbv, mbp, g1, be1);
    ffn_kernel<<<NBLK, TPB, FFN_SMEM_BYTES>>>(scratch, out, fb1, fb2, g2, be2);
}

// round 6
// speedup vs baseline: 4.4664x; 1.0981x over previous
#include <cuda_runtime.h>
#include <cuda_bf16.h>
#include <math.h>

#define NTOK (32768*16)          // 524288 tokens
#define TPB  256
#define TOKS 64                  // tokens per CTA
#define NBLK (NTOK/TOKS)         // 8192 CTAs

// ---------------- device globals (allocation-free scratch) ----------------
__device__ float g_scratch[(size_t)NTOK * 64];
__device__ __align__(16) __nv_bfloat16 g_W1b[64*256];
__device__ __align__(16) __nv_bfloat16 g_W2b[256*64];
__device__ __align__(16) __nv_bfloat16 g_Tu[64*192];   // [d][h*8+s (+0/64/128 for q/k/v)]
__device__ __align__(16) __nv_bfloat16 g_Tm[64*192];
__device__ __align__(16) __nv_bfloat16 g_Wpu[64*64];
__device__ __align__(16) __nv_bfloat16 g_Wpm[64*64];

// ---------------- small helpers ----------------
// pack two floats to bf16x2 (low=a, high=b)
__device__ __forceinline__ unsigned bf2u(float a, float b) {
    unsigned r;
    asm("cvt.rn.bf16x2.f32 %0, %1, %2;" : "=r"(r) : "f"(b), "f"(a));
    return r;
}
__device__ __forceinline__ unsigned su32(const void* p) {
    return (unsigned)__cvta_generic_to_shared(p);
}
// fast GELU: 0.5z(1+tanh(0.79788456(z + 0.044715 z^3))), HW tanh
__device__ __forceinline__ float gelu_f(float z) {
    float w = z * fmaf(0.035677408136f, z*z, 0.79788456080287f);
    float t;
    asm("tanh.approx.f32 %0, %1;" : "=f"(t) : "f"(w));
    float hz = 0.5f*z;
    return fmaf(hz, t, hz);
}

#define LDSM2(r0,r1,addr) \
    asm volatile("ldmatrix.sync.aligned.m8n8.x2.shared.b16 {%0,%1},[%2];" \
        : "=r"(r0),"=r"(r1) : "r"(addr))
#define LDSM2T(r0,r1,addr) \
    asm volatile("ldmatrix.sync.aligned.m8n8.x2.trans.shared.b16 {%0,%1},[%2];" \
        : "=r"(r0),"=r"(r1) : "r"(addr))
#define LDSM4(r0,r1,r2,r3,addr) \
    asm volatile("ldmatrix.sync.aligned.m8n8.x4.shared.b16 {%0,%1,%2,%3},[%4];" \
        : "=r"(r0),"=r"(r1),"=r"(r2),"=r"(r3) : "r"(addr))
#define LDSM4T(r0,r1,r2,r3,addr) \
    asm volatile("ldmatrix.sync.aligned.m8n8.x4.trans.shared.b16 {%0,%1,%2,%3},[%4];" \
        : "=r"(r0),"=r"(r1),"=r"(r2),"=r"(r3) : "r"(addr))
#define MMA16816(c0,c1,c2,c3,a0,a1,a2,a3,b0,b1) \
    asm volatile("mma.sync.aligned.m16n8k16.row.col.f32.bf16.bf16.f32 " \
        "{%0,%1,%2,%3},{%4,%5,%6,%7},{%8,%9},{%0,%1,%2,%3};" \
        : "+f"(c0),"+f"(c1),"+f"(c2),"+f"(c3) \
        : "r"(a0),"r"(a1),"r"(a2),"r"(a3),"r"(b0),"r"(b1))
#define MMA16808(c0,c1,c2,c3,a0,a1,b0) \
    asm volatile("mma.sync.aligned.m16n8k8.row.col.f32.bf16.bf16.f32 " \
        "{%0,%1,%2,%3},{%4,%5},{%6},{%0,%1,%2,%3};" \
        : "+f"(c0),"+f"(c1),"+f"(c2),"+f"(c3) \
        : "r"(a0),"r"(a1),"r"(b0))

// LayerNorm token row -> bf16 row-major [t][64] XOR-swizzled (128B rows)
__device__ __forceinline__ void ln_row_bf16(const float* __restrict__ xrow,
                                            char* __restrict__ sA, int t,
                                            const float* __restrict__ sg) {
    float xv[64];
    const float4* x4 = (const float4*)xrow;
#pragma unroll
    for (int i = 0; i < 16; i++) {
        float4 v = x4[i];
        xv[4*i] = v.x; xv[4*i+1] = v.y; xv[4*i+2] = v.z; xv[4*i+3] = v.w;
    }
    float mean = 0.f;
#pragma unroll
    for (int d = 0; d < 64; d++) mean += xv[d];
    mean *= (1.f/64.f);
    float var = 0.f;
#pragma unroll
    for (int d = 0; d < 64; d++) { float dv = xv[d] - mean; var += dv*dv; }
    var *= (1.f/64.f);
    float rstd = rsqrtf(var + 1e-5f);
#pragma unroll
    for (int c = 0; c < 8; c++) {
        float v[8];
#pragma unroll
        for (int e = 0; e < 8; e++) {
            int k = c*8 + e;
            v[e] = (xv[k] - mean) * rstd * sg[k] + sg[64 + k];
        }
        uint4 q;
        q.x = bf2u(v[0], v[1]); q.y = bf2u(v[2], v[3]);
        q.z = bf2u(v[4], v[5]); q.w = bf2u(v[6], v[7]);
        *(uint4*)(sA + t*128 + ((c ^ (t & 7)) << 4)) = q;
    }
}

// ---------------- prep: fp32 weights -> bf16 (and qkv transpose) ----------------
__global__ void prep_kernel(const float* __restrict__ W1, const float* __restrict__ W2,
                            const float* __restrict__ uWq, const float* __restrict__ uWk,
                            const float* __restrict__ uWv, const float* __restrict__ uWp,
                            const float* __restrict__ mWq, const float* __restrict__ mWk,
                            const float* __restrict__ mWv, const float* __restrict__ mWp)
{
    int i0 = blockIdx.x * blockDim.x + threadIdx.x;
    int stride = gridDim.x * blockDim.x;
    for (int i = i0; i < 16384; i += stride) {
        g_W1b[i] = __float2bfloat16(W1[i]);
        g_W2b[i] = __float2bfloat16(W2[i]);
    }
    for (int i = i0; i < 4096; i += stride) {
        int h = i >> 9, d = (i >> 3) & 63, s = i & 7;
        int c = h*8 + s;
        g_Tu[d*192 + c]       = __float2bfloat16(uWq[i]);
        g_Tu[d*192 + 64 + c]  = __float2bfloat16(uWk[i]);
        g_Tu[d*192 + 128 + c] = __float2bfloat16(uWv[i]);
        g_Tm[d*192 + c]       = __float2bfloat16(mWq[i]);
        g_Tm[d*192 + 64 + c]  = __float2bfloat16(mWk[i]);
        g_Tm[d*192 + 128 + c] = __float2bfloat16(mWv[i]);
        g_Wpu[i] = __float2bfloat16(uWp[i]);
        g_Wpm[i] = __float2bfloat16(mWp[i]);
    }
}

// ==================================================================
// FFN kernel: out = x + gelu(LN(x)@W1 + b1)@W2 + b2 (64-token tile)
// phase1: H c-frags kept in registers (no sH); phase2 = k-split GEMM,
// warp nh owns k in [128nh,128nh+128), cross-warp fp32 reduce in smem.
// ==================================================================
#define FFN_SW1  0
#define FFN_SW2  32768
#define FFN_SA   65536
#define FFN_SRED 73728            // 4 groups x 16 x 68 floats = 17408
#define FFN_SB1  91136
#define FFN_SB2  92160
#define FFN_SG   92416
#define FFN_SMEM_BYTES 92928

__global__ void __launch_bounds__(TPB, 2) ffn_kernel(
    const float* __restrict__ xin, float* __restrict__ xout,
    const float* __restrict__ b1, const float* __restrict__ b2,
    const float* __restrict__ g2, const float* __restrict__ be2)
{
    extern __shared__ char smc[];
    float* sb1 = (float*)(smc + FFN_SB1);
    float* sb2 = (float*)(smc + FFN_SB2);
    float* sg  = (float*)(smc + FFN_SG);

    const int tid = threadIdx.x;
    const unsigned sbase = su32(smc);

    {
        const uint4* src1 = (const uint4*)g_W1b;
        const uint4* src2 = (const uint4*)g_W2b;
        for (int c = tid; c < 2048; c += TPB) {
            int r1 = c >> 5, c1 = c & 31;
            *(uint4*)(smc + FFN_SW1 + r1*512 + ((c1 ^ (r1 & 7)) << 4)) = src1[c];
            int r2 = c >> 3, c2 = c & 7;
            *(uint4*)(smc + FFN_SW2 + r2*128 + ((c2 ^ (r2 & 7)) << 4)) = src2[c];
        }
    }
    sb1[tid] = b1[tid];
    if (tid < 64) { sb2[tid] = b2[tid]; sg[tid] = g2[tid]; sg[64+tid] = be2[tid]; }
    __syncthreads();

    const size_t base = (size_t)blockIdx.x * TOKS;
    if (tid < TOKS) ln_row_bf16(xin + (base + tid)*64, smc + FFN_SA, tid, sg);
    __syncthreads();

    const int lane = tid & 31, wid = tid >> 5;
    const int gid = lane >> 2, tig = lane & 3;
    const int tw = wid & 3, nh = wid >> 2;
    const int t0 = tw * 16;
    const int jbase = nh * 128;

    // ---------- phase 1: Z = A @ W1 (c-frags in regs); warp = 16t x 128j ----------
    float acc[16][4];
#pragma unroll
    for (int m = 0; m < 16; m++)
#pragma unroll
        for (int p = 0; p < 4; p++) acc[m][p] = 0.f;

#pragma unroll
    for (int ks = 0; ks < 4; ks++) {
        const int k0 = ks * 16;
        unsigned a0,a1,a2,a3;
        {
            int ar = t0 + (lane & 15);
            int ac = (k0 >> 3) + (lane >> 4);
            unsigned aaddr = sbase + FFN_SA + ar*128 + ((ac ^ (ar & 7)) << 4);
            LDSM4(a0,a1,a2,a3, aaddr);
        }
#pragma unroll
        for (int st = 0; st < 8; st++) {
            int n0 = jbase + st * 16;
            unsigned b0,b1r,b2,b3;
            int br = k0 + (lane & 15);
            int bc = (n0 >> 3) + (lane >> 4);
            unsigned baddr = sbase + FFN_SW1 + br*512 + ((bc ^ (br & 7)) << 4);
            LDSM4T(b0,b1r,b2,b3, baddr);
            MMA16816(acc[2*st][0],acc[2*st][1],acc[2*st][2],acc[2*st][3],
                     a0,a1,a2,a3, b0,b1r);
            MMA16816(acc[2*st+1][0],acc[2*st+1][1],acc[2*st+1][2],acc[2*st+1][3],
                     a0,a1,a2,a3, b2,b3);
        }
    }

    // ---------- gelu in registers, pack to A-frags of phase 2 ----------
    // pk[ks][0]= (row gid, k 2tig,2tig+1); [1]=(gid+8, same); [2]=(gid, k+8); [3]=(gid+8, k+8)
    unsigned pk[8][4];
#pragma unroll
    for (int m = 0; m < 16; m++) {
        int col = jbase + m*8 + 2*tig;
        float bb0 = sb1[col], bb1 = sb1[col+1];
        float h00 = gelu_f(acc[m][0] + bb0);
        float h01 = gelu_f(acc[m][1] + bb1);
        float h10 = gelu_f(acc[m][2] + bb0);
        float h11 = gelu_f(acc[m][3] + bb1);
        if ((m & 1) == 0) {
            pk[m>>1][0] = bf2u(h00, h01);
            pk[m>>1][1] = bf2u(h10, h11);
        } else {
            pk[m>>1][2] = bf2u(h00, h01);
            pk[m>>1][3] = bf2u(h10, h11);
        }
    }

    // ---------- phase 2: partial out = H_slab @ W2[jbase:+128][0:64] ----------
    float acc2[8][4];
#pragma unroll
    for (int m = 0; m < 8; m++)
#pragma unroll
        for (int p = 0; p < 4; p++) acc2[m][p] = 0.f;

#pragma unroll
    for (int ks = 0; ks < 8; ks++) {
        const int br = jbase + ks*16 + (lane & 15);
#pragma unroll
        for (int st = 0; st < 4; st++) {
            int n0 = st * 16;
            unsigned b0,b1r,b2,b3;
            int bc = (n0 >> 3) + (lane >> 4);
            unsigned baddr = sbase + FFN_SW2 + br*128 + ((bc ^ (br & 7)) << 4);
            LDSM4T(b0,b1r,b2,b3, baddr);
            MMA16816(acc2[2*st][0],acc2[2*st][1],acc2[2*st][2],acc2[2*st][3],
                     pk[ks][0],pk[ks][1],pk[ks][2],pk[ks][3], b0,b1r);
            MMA16816(acc2[2*st+1][0],acc2[2*st+1][1],acc2[2*st+1][2],acc2[2*st+1][3],
                     pk[ks][0],pk[ks][1],pk[ks][2],pk[ks][3], b2,b3);
        }
    }

    // ---------- cross-warp k-reduction (balanced halves) ----------
    float* red = (float*)(smc + FFN_SRED) + tw * (16*68);
    const int st_sto = (nh == 1) ? 0 : 4;   // partial stored for partner
    const int st_fin = (nh == 1) ? 4 : 0;   // half this warp finalizes
#pragma unroll
    for (int s = 0; s < 4; s++) {
        int st = st_sto + s;
#pragma unroll
        for (int rp = 0; rp < 2; rp++) {
            int row = gid + rp*8;
            *(float2*)(red + row*68 + st*8 + 2*tig) =
                make_float2(acc2[st][2*rp], acc2[st][2*rp+1]);
        }
    }
    __syncthreads();
#pragma unroll
    for (int s = 0; s < 4; s++) {
        int st = st_fin + s;
        int e = st*8 + 2*tig;
        float bb0 = sb2[e], bb1 = sb2[e+1];
#pragma unroll
        for (int rp = 0; rp < 2; rp++) {
            int row = gid + rp*8;
            float2 r = *(const float2*)(red + row*68 + e);
            const float* xr = xin + (base + t0 + row)*64 + e;
            float2 x = *(const float2*)xr;
            float2 o = make_float2(x.x + r.x + acc2[st][2*rp]   + bb0,
                                   x.y + r.y + acc2[st][2*rp+1] + bb1);
            *(float2*)(xout + (base + t0 + row)*64 + e) = o;
        }
    }
}

// ==================================================================
// Attention kernel: out = x + attn(LN(x)) (64-token tile, 4 batches)
// sOb aliases sA (dead after phase1). smem 67072 B.
// ==================================================================
#define ATT_ST    0
#define ATT_SWP   24576
#define ATT_SA    32768
#define ATT_SOB   32768          // alias: sA dead after phase 1
#define ATT_SQKV  40960
#define ATT_SBQKV 65536
#define ATT_SBP   66304
#define ATT_SG    66560
#define ATT_SMEM_BYTES 67072

template <bool CAUSAL>
__global__ void __launch_bounds__(TPB, 2) attn_kernel(
    const float* __restrict__ xin, float* __restrict__ xout,
    const __nv_bfloat16* __restrict__ Tqkv, const __nv_bfloat16* __restrict__ Wpb,
    const float* __restrict__ bq, const float* __restrict__ bk,
    const float* __restrict__ bv, const float* __restrict__ bp,
    const float* __restrict__ g1, const float* __restrict__ be1)
{
    extern __shared__ char smc[];
    float* sbqkv = (float*)(smc + ATT_SBQKV);
    float* sbp   = (float*)(smc + ATT_SBP);
    float* sg    = (float*)(smc + ATT_SG);

    const int tid = threadIdx.x;
    const unsigned sbase = su32(smc);

    {
        const uint4* srcT = (const uint4*)Tqkv;   // 64 rows x 24 chunks
        for (int c = tid; c < 1536; c += TPB) {
            int r = c / 24, ch = c % 24;
            *(uint4*)(smc + ATT_ST + r*384 + ((ch ^ (r & 7)) << 4)) = srcT[c];
        }
        const uint4* srcP = (const uint4*)Wpb;
        for (int c = tid; c < 512; c += TPB) {
            int r = c >> 3, ch = c & 7;
            *(uint4*)(smc + ATT_SWP + r*128 + ((ch ^ (r & 7)) << 4)) = srcP[c];
        }
    }
    if (tid < 192) sbqkv[tid] = (tid < 64) ? bq[tid] : (tid < 128 ? bk[tid-64] : bv[tid-128]);
    if (tid < 64)  sbp[tid] = bp[tid];
    if (tid < 128) sg[tid] = (tid < 64) ? g1[tid] : be1[tid-64];
    __syncthreads();

    const size_t base = (size_t)blockIdx.x * TOKS;
    if (tid < TOKS) ln_row_bf16(xin + (base + tid)*64, smc + ATT_SA, tid, sg);
    __syncthreads();

    const int lane = tid & 31, wid = tid >> 5;
    const int gid = lane >> 2, tig = lane & 3;
    const int tw = wid & 3, nh = wid >> 2;
    const int t0 = tw * 16;

    // ---------- phase 1: QKV = A @ T + b ; warp = batch tw, 96 c-cols ----------
    {
        const int cbase = nh * 96;
        float acc[12][4];
#pragma unroll
        for (int m = 0; m < 12; m++)
#pragma unroll
            for (int p = 0; p < 4; p++) acc[m][p] = 0.f;

#pragma unroll
        for (int ks = 0; ks < 4; ks++) {
            const int k0 = ks * 16;
            unsigned a0,a1,a2,a3;
            {
                int ar = t0 + (lane & 15);
                int ac = (k0 >> 3) + (lane >> 4);
                unsigned aaddr = sbase + ATT_SA + ar*128 + ((ac ^ (ar & 7)) << 4);
                LDSM4(a0,a1,a2,a3, aaddr);
            }
#pragma unroll
            for (int st = 0; st < 6; st++) {
                int n0 = cbase + st * 16;
                unsigned b0,b1r,b2,b3;
                int br = k0 + (lane & 15);
                int bc = (n0 >> 3) + (lane >> 4);
                unsigned baddr = sbase + ATT_ST + br*384 + ((bc ^ (br & 7)) << 4);
                LDSM4T(b0,b1r,b2,b3, baddr);
                MMA16816(acc[2*st][0],acc[2*st][1],acc[2*st][2],acc[2*st][3],
                         a0,a1,a2,a3, b0,b1r);
                MMA16816(acc[2*st+1][0],acc[2*st+1][1],acc[2*st+1][2],acc[2*st+1][3],
                         a0,a1,a2,a3, b2,b3);
            }
        }
        // epilogue: bias (+0.35355 scale for Q), write bf16 tiles [16 x 16B]
#pragma unroll
        for (int m = 0; m < 12; m++) {
            int cc = cbase + m*8;            // 8-aligned: head block
            int sec = cc >> 6;               // 0=q 1=k 2=v
            int h = (cc >> 3) & 7;
            int c = cc + 2*tig;
            float bb0 = sbqkv[c], bb1 = sbqkv[c+1];
            float scale = (sec == 0) ? 0.35355339059327373f : 1.f;
            float v00 = (acc[m][0] + bb0) * scale, v01 = (acc[m][1] + bb1) * scale;
            float v10 = (acc[m][2] + bb0) * scale, v11 = (acc[m][3] + bb1) * scale;
            unsigned tb = ATT_SQKV + sec*8192 + (tw*8 + h)*256 + tig*4;
            *(unsigned*)(smc + tb + gid*16)       = bf2u(v00, v01);
            *(unsigned*)(smc + tb + (gid+8)*16)   = bf2u(v10, v11);
        }
    }
    __syncthreads();

    // ---------- phase 2: MMA attention core; warp handles 4 (b,h) pairs ----------
    // softmax WITHOUT max-subtraction: |scores| <= ~2 by construction, exp safe;
    // causal mask -1e30 -> expf gives exact 0.
    {
#pragma unroll
        for (int i = 0; i < 4; i++) {
            const int p = wid*4 + i;
            const int b = p >> 3, h = p & 7;
            const unsigned tq = sbase + ATT_SQKV + (b*8+h)*256 + (lane & 15)*16;

            unsigned qa0, qa1, kb0, kb1, vb0, vb1;
            LDSM2 (qa0, qa1, tq);            // Q a-frag (m16k8), scale folded
            LDSM2 (kb0, kb1, tq + 8192);     // K b-frags (n=u0..7, u8..15)
            LDSM2T(vb0, vb1, tq + 16384);    // V b-frags (k=u, n=s)

            float s0=0,s1=0,s2=0,s3=0,s4=0,s5=0,s6=0,s7=0;
            MMA16808(s0,s1,s2,s3, qa0,qa1, kb0);   // cols u = 2tig,2tig+1
            MMA16808(s4,s5,s6,s7, qa0,qa1, kb1);   // cols u = 2tig+8,2tig+9

            if (CAUSAL) {
                const int u0 = 2*tig, u1 = 2*tig+1, u2 = 2*tig+8, u3 = 2*tig+9;
                if (u0 > gid)   s0 = -1e30f;
                if (u1 > gid)   s1 = -1e30f;
                if (u2 > gid)   s4 = -1e30f;
                if (u3 > gid)   s5 = -1e30f;
                if (u0 > gid+8) s2 = -1e30f;
                if (u1 > gid+8) s3 = -1e30f;
                if (u2 > gid+8) s6 = -1e30f;
                if (u3 > gid+8) s7 = -1e30f;
            }
            float e0 = __expf(s0), e1 = __expf(s1);
            float e4 = __expf(s4), e5 = __expf(s5);
            float e2 = __expf(s2), e3 = __expf(s3);
            float e6 = __expf(s6), e7 = __expf(s7);
            float slo = e0+e1+e4+e5, shi = e2+e3+e6+e7;
            slo += __shfl_xor_sync(0xffffffffu, slo, 1);
            slo += __shfl_xor_sync(0xffffffffu, slo, 2);
            shi += __shfl_xor_sync(0xffffffffu, shi, 1);
            shi += __shfl_xor_sync(0xffffffffu, shi, 2);
            const float ilo = 1.f/slo, ihi = 1.f/shi;

            unsigned pa0 = bf2u(e0, e1);   // (gid,   u 2tig..)
            unsigned pa1 = bf2u(e2, e3);   // (gid+8, u 2tig..)
            unsigned pa2 = bf2u(e4, e5);   // (gid,   u 2tig+8..)
            unsigned pa3 = bf2u(e6, e7);   // (gid+8, u 2tig+8..)

            float o0=0,o1=0,o2=0,o3=0;
            MMA16816(o0,o1,o2,o3, pa0,pa1,pa2,pa3, vb0,vb1);
            o0 *= ilo; o1 *= ilo; o2 *= ihi; o3 *= ihi;

            const int tA = b*16 + gid, tB = tA + 8;
            const int c = h*8 + 2*tig;
            unsigned offA = ATT_SOB + tA*128 + (((c>>3) ^ (tA & 7)) << 4) + ((c & 7) << 1);
            unsigned offB = ATT_SOB + tB*128 + (((c>>3) ^ (tB & 7)) << 4) + ((c & 7) << 1);
            *(unsigned*)(smc + offA) = bf2u(o0, o1);
            *(unsigned*)(smc + offB) = bf2u(o2, o3);
        }
    }
    __syncthreads();

    // ---------- phase 3: out = x + O @ Wp + bp ; warp = 16t x 32e ----------
    {
        const int ebase = nh * 32;
        float acc[4][4];
#pragma unroll
        for (int m = 0; m < 4; m++)
#pragma unroll
            for (int p = 0; p < 4; p++) acc[m][p] = 0.f;

#pragma unroll
        for (int ks = 0; ks < 4; ks++) {
            const int k0 = ks * 16;
            unsigned a0,a1,a2,a3;
            {
                int ar = t0 + (lane & 15);
                int ac = (k0 >> 3) + (lane >> 4);
                unsigned aaddr = sbase + ATT_SOB + ar*128 + ((ac ^ (ar & 7)) << 4);
                LDSM4(a0,a1,a2,a3, aaddr);
            }
#pragma unroll
            for (int st = 0; st < 2; st++) {
                int n0 = ebase + st * 16;
                unsigned b0,b1r,b2,b3;
                int br = k0 + (lane & 15);
                int bc = (n0 >> 3) + (lane >> 4);
                unsigned baddr = sbase + ATT_SWP + br*128 + ((bc ^ (br & 7)) << 4);
                LDSM4T(b0,b1r,b2,b3, baddr);
                MMA16816(acc[2*st][0],acc[2*st][1],acc[2*st][2],acc[2*st][3],
                         a0,a1,a2,a3, b0,b1r);
                MMA16816(acc[2*st+1][0],acc[2*st+1][1],acc[2*st+1][2],acc[2*st+1][3],
                         a0,a1,a2,a3, b2,b3);
            }
        }
        const int r0 = t0 + gid, r1 = t0 + gid + 8;
#pragma unroll
        for (int m = 0; m < 4; m++) {
            int e = ebase + m*8 + 2*tig;
            float bb0 = sbp[e], bb1 = sbp[e+1];
            float2 x0 = *(const float2*)(xin + (base + r0)*64 + e);
            float2 x1 = *(const float2*)(xin + (base + r1)*64 + e);
            float2 o0 = make_float2(x0.x + acc[m][0] + bb0, x0.y + acc[m][1] + bb1);
            float2 o1 = make_float2(x1.x + acc[m][2] + bb0, x1.y + acc[m][3] + bb1);
            *(float2*)(xout + (base + r0)*64 + e) = o0;
            *(float2*)(xout + (base + r1)*64 + e) = o1;
        }
    }
}

// ==================================================================
// launch: prep -> attn(u) -> ffn -> attn(m, causal) -> ffn
// ==================================================================
extern "C" void kernel_launch(void* const* d_in, const int* in_sizes, int n_in,
                              void* d_out, int out_size)
{
    (void)in_sizes; (void)n_in; (void)out_size;
    const float* x   = (const float*)d_in[0];
    const float* uWq = (const float*)d_in[1];  const float* ubq = (const float*)d_in[2];
    const float* uWk = (const float*)d_in[3];  const float* ubk = (const float*)d_in[4];
    const float* uWv = (const float*)d_in[5];  const float* ubv = (const float*)d_in[6];
    const float* uWp = (const float*)d_in[7];  const float* ubp = (const float*)d_in[8];
    const float* mWq = (const float*)d_in[9];  const float* mbq = (const float*)d_in[10];
    const float* mWk = (const float*)d_in[11]; const float* mbk = (const float*)d_in[12];
    const float* mWv = (const float*)d_in[13]; const float* mbv = (const float*)d_in[14];
    const float* mWp = (const float*)d_in[15]; const float* mbp = (const float*)d_in[16];
    const float* fW1 = (const float*)d_in[17]; const float* fb1 = (const float*)d_in[18];
    const float* fW2 = (const float*)d_in[19]; const float* fb2 = (const float*)d_in[20];
    const float* g1  = (const float*)d_in[21]; const float* be1 = (const float*)d_in[22];
    const float* g2  = (const float*)d_in[23]; const float* be2 = (const float*)d_in[24];
    float* out = (float*)d_out;

    float* scratch = nullptr;
    cudaGetSymbolAddress((void**)&scratch, g_scratch);
    __nv_bfloat16 *Tu = nullptr, *Tm = nullptr, *Wpu = nullptr, *Wpm = nullptr;
    cudaGetSymbolAddress((void**)&Tu, g_Tu);
    cudaGetSymbolAddress((void**)&Tm, g_Tm);
    cudaGetSymbolAddress((void**)&Wpu, g_Wpu);
    cudaGetSymbolAddress((void**)&Wpm, g_Wpm);

    cudaFuncSetAttribute(attn_kernel<false>, cudaFuncAttributeMaxDynamicSharedMemorySize, ATT_SMEM_BYTES);
    cudaFuncSetAttribute(attn_kernel<true>,  cudaFuncAttributeMaxDynamicSharedMemorySize, ATT_SMEM_BYTES);
    cudaFuncSetAttribute(ffn_kernel,         cudaFuncAttributeMaxDynamicSharedMemorySize, FFN_SMEM_BYTES);

    prep_kernel<<<32, 256>>>(fW1, fW2, uWq, uWk, uWv, uWp, mWq, mWk, mWv, mWp);

    attn_kernel<false><<<NBLK, TPB, ATT_SMEM_BYTES>>>(x, scratch, Tu, Wpu,
        ubq, ubk, ubv, ubp, g1, be1);
    ffn_kernel<<<NBLK, TPB, FFN_SMEM_BYTES>>>(scratch, out, fb1, fb2, g2, be2);
    attn_kernel<true><<<NBLK, TPB, ATT_SMEM_BYTES>>>(out, scratch, Tm, Wpm,
        mbq, mbk, mbv, mbp, g1, be1);
    ffn_kernel<<<NBLK, TPB, FFN_SMEM_BYTES>>>(scratch, out, fb1, fb2, g2, be2);
}

// round 7
// speedup vs baseline: 5.5423x; 1.2409x over previous
#include <cuda_runtime.h>
#include <cuda_bf16.h>
#include <math.h>

#define NTOK (32768*16)          // 524288 tokens
#define TPB  256
#define TOKS 64                  // tokens per tile
#define NT   4                   // tiles per CTA
#define NBLK (NTOK/(TOKS*NT))    // 2048 CTAs

// ---------------- device globals (allocation-free scratch) ----------------
__device__ float g_scratch[(size_t)NTOK * 64];
__device__ __align__(16) __nv_bfloat16 g_W1b[64*256];
__device__ __align__(16) __nv_bfloat16 g_W2b[256*64];
__device__ __align__(16) __nv_bfloat16 g_Tu[64*192];   // [d][h*8+s (+0/64/128 for q/k/v)]
__device__ __align__(16) __nv_bfloat16 g_Tm[64*192];
__device__ __align__(16) __nv_bfloat16 g_Wpu[64*64];
__device__ __align__(16) __nv_bfloat16 g_Wpm[64*64];

// ---------------- small helpers ----------------
__device__ __forceinline__ unsigned bf2u(float a, float b) {
    unsigned r;
    asm("cvt.rn.bf16x2.f32 %0, %1, %2;" : "=r"(r) : "f"(b), "f"(a));
    return r;
}
__device__ __forceinline__ unsigned su32(const void* p) {
    return (unsigned)__cvta_generic_to_shared(p);
}
// fast GELU: 0.5z(1+tanh(0.79788456(z + 0.044715 z^3))), HW tanh
__device__ __forceinline__ float gelu_f(float z) {
    float w = z * fmaf(0.035677408136f, z*z, 0.79788456080287f);
    float t;
    asm("tanh.approx.f32 %0, %1;" : "=f"(t) : "f"(w));
    float hz = 0.5f*z;
    return fmaf(hz, t, hz);
}

#define LDSM2(r0,r1,addr) \
    asm volatile("ldmatrix.sync.aligned.m8n8.x2.shared.b16 {%0,%1},[%2];" \
        : "=r"(r0),"=r"(r1) : "r"(addr))
#define LDSM2T(r0,r1,addr) \
    asm volatile("ldmatrix.sync.aligned.m8n8.x2.trans.shared.b16 {%0,%1},[%2];" \
        : "=r"(r0),"=r"(r1) : "r"(addr))
#define LDSM4(r0,r1,r2,r3,addr) \
    asm volatile("ldmatrix.sync.aligned.m8n8.x4.shared.b16 {%0,%1,%2,%3},[%4];" \
        : "=r"(r0),"=r"(r1),"=r"(r2),"=r"(r3) : "r"(addr))
#define LDSM4T(r0,r1,r2,r3,addr) \
    asm volatile("ldmatrix.sync.aligned.m8n8.x4.trans.shared.b16 {%0,%1,%2,%3},[%4];" \
        : "=r"(r0),"=r"(r1),"=r"(r2),"=r"(r3) : "r"(addr))
#define MMA16816(c0,c1,c2,c3,a0,a1,a2,a3,b0,b1) \
    asm volatile("mma.sync.aligned.m16n8k16.row.col.f32.bf16.bf16.f32 " \
        "{%0,%1,%2,%3},{%4,%5,%6,%7},{%8,%9},{%0,%1,%2,%3};" \
        : "+f"(c0),"+f"(c1),"+f"(c2),"+f"(c3) \
        : "r"(a0),"r"(a1),"r"(a2),"r"(a3),"r"(b0),"r"(b1))
#define MMA16808(c0,c1,c2,c3,a0,a1,b0) \
    asm volatile("mma.sync.aligned.m16n8k8.row.col.f32.bf16.bf16.f32 " \
        "{%0,%1,%2,%3},{%4,%5},{%6},{%0,%1,%2,%3};" \
        : "+f"(c0),"+f"(c1),"+f"(c2),"+f"(c3) \
        : "r"(a0),"r"(a1),"r"(b0))

// Quad-parallel LayerNorm: all 256 threads; token = tid>>2, quarter = tid&3.
// Writes bf16 row-major [t][64] XOR-swizzled (128B rows) into sA.
__device__ __forceinline__ void ln_tile_bf16(const float* __restrict__ xin, size_t base,
                                             char* __restrict__ sA, int tid,
                                             const float* __restrict__ sg) {
    const int t = tid >> 2, qp = tid & 3;
    const float4* x4 = (const float4*)(xin + (base + t)*64) + qp*4;
    float xv[16];
#pragma unroll
    for (int i = 0; i < 4; i++) {
        float4 v = x4[i];
        xv[4*i]=v.x; xv[4*i+1]=v.y; xv[4*i+2]=v.z; xv[4*i+3]=v.w;
    }
    float s = 0.f, ss = 0.f;
#pragma unroll
    for (int i = 0; i < 16; i++) { s += xv[i]; ss = fmaf(xv[i], xv[i], ss); }
    s  += __shfl_xor_sync(0xffffffffu, s, 1);  ss += __shfl_xor_sync(0xffffffffu, ss, 1);
    s  += __shfl_xor_sync(0xffffffffu, s, 2);  ss += __shfl_xor_sync(0xffffffffu, ss, 2);
    const float mean = s * (1.f/64.f);
    const float var  = ss * (1.f/64.f) - mean*mean;
    const float rstd = rsqrtf(var + 1e-5f);
    const int kb = qp * 16;
#pragma unroll
    for (int c = 0; c < 2; c++) {
        float v[8];
#pragma unroll
        for (int e = 0; e < 8; e++) {
            int k = kb + c*8 + e;
            v[e] = (xv[c*8+e] - mean) * rstd * sg[k] + sg[64+k];
        }
        uint4 q;
        q.x = bf2u(v[0], v[1]); q.y = bf2u(v[2], v[3]);
        q.z = bf2u(v[4], v[5]); q.w = bf2u(v[6], v[7]);
        int ch = qp*2 + c;
        *(uint4*)(sA + t*128 + ((ch ^ (t & 7)) << 4)) = q;
    }
}

// ---------------- prep: fp32 weights -> bf16 (and qkv transpose) ----------------
__global__ void prep_kernel(const float* __restrict__ W1, const float* __restrict__ W2,
                            const float* __restrict__ uWq, const float* __restrict__ uWk,
                            const float* __restrict__ uWv, const float* __restrict__ uWp,
                            const float* __restrict__ mWq, const float* __restrict__ mWk,
                            const float* __restrict__ mWv, const float* __restrict__ mWp)
{
    int i0 = blockIdx.x * blockDim.x + threadIdx.x;
    int stride = gridDim.x * blockDim.x;
    for (int i = i0; i < 16384; i += stride) {
        g_W1b[i] = __float2bfloat16(W1[i]);
        g_W2b[i] = __float2bfloat16(W2[i]);
    }
    for (int i = i0; i < 4096; i += stride) {
        int h = i >> 9, d = (i >> 3) & 63, s = i & 7;
        int c = h*8 + s;
        g_Tu[d*192 + c]       = __float2bfloat16(uWq[i]);
        g_Tu[d*192 + 64 + c]  = __float2bfloat16(uWk[i]);
        g_Tu[d*192 + 128 + c] = __float2bfloat16(uWv[i]);
        g_Tm[d*192 + c]       = __float2bfloat16(mWq[i]);
        g_Tm[d*192 + 64 + c]  = __float2bfloat16(mWk[i]);
        g_Tm[d*192 + 128 + c] = __float2bfloat16(mWv[i]);
        g_Wpu[i] = __float2bfloat16(uWp[i]);
        g_Wpm[i] = __float2bfloat16(mWp[i]);
    }
}

// ==================================================================
// FFN kernel: out = x + gelu(LN(x)@W1 + b1)@W2 + b2 ; NT tiles per CTA
// ==================================================================
#define FFN_SW1  0
#define FFN_SW2  32768
#define FFN_SA   65536
#define FFN_SRED 73728            // 4 groups x 16 x 68 floats = 17408
#define FFN_SB1  91136
#define FFN_SB2  92160
#define FFN_SG   92416
#define FFN_SMEM_BYTES 92928

__global__ void __launch_bounds__(TPB, 2) ffn_kernel(
    const float* __restrict__ xin, float* __restrict__ xout,
    const float* __restrict__ b1, const float* __restrict__ b2,
    const float* __restrict__ g2, const float* __restrict__ be2)
{
    extern __shared__ char smc[];
    float* sb1 = (float*)(smc + FFN_SB1);
    float* sb2 = (float*)(smc + FFN_SB2);
    float* sg  = (float*)(smc + FFN_SG);

    const int tid = threadIdx.x;
    const unsigned sbase = su32(smc);

    {
        const uint4* src1 = (const uint4*)g_W1b;
        const uint4* src2 = (const uint4*)g_W2b;
        for (int c = tid; c < 2048; c += TPB) {
            int r1 = c >> 5, c1 = c & 31;
            *(uint4*)(smc + FFN_SW1 + r1*512 + ((c1 ^ (r1 & 7)) << 4)) = src1[c];
            int r2 = c >> 3, c2 = c & 7;
            *(uint4*)(smc + FFN_SW2 + r2*128 + ((c2 ^ (r2 & 7)) << 4)) = src2[c];
        }
    }
    sb1[tid] = b1[tid];
    if (tid < 64) { sb2[tid] = b2[tid]; sg[tid] = g2[tid]; sg[64+tid] = be2[tid]; }
    __syncthreads();

    const int lane = tid & 31, wid = tid >> 5;
    const int gid = lane >> 2, tig = lane & 3;
    const int tw = wid & 3, nh = wid >> 2;
    const int t0 = tw * 16;
    const int jbase = nh * 128;

    for (int tt = 0; tt < NT; tt++) {
        const size_t base = ((size_t)blockIdx.x * NT + tt) * TOKS;
        ln_tile_bf16(xin, base, smc + FFN_SA, tid, sg);
        __syncthreads();

        // ---------- phase 1: Z = A @ W1 (c-frags in regs); warp = 16t x 128j ----------
        float acc[16][4];
#pragma unroll
        for (int m = 0; m < 16; m++)
#pragma unroll
            for (int p = 0; p < 4; p++) acc[m][p] = 0.f;

#pragma unroll
        for (int ks = 0; ks < 4; ks++) {
            const int k0 = ks * 16;
            unsigned a0,a1,a2,a3;
            {
                int ar = t0 + (lane & 15);
                int ac = (k0 >> 3) + (lane >> 4);
                unsigned aaddr = sbase + FFN_SA + ar*128 + ((ac ^ (ar & 7)) << 4);
                LDSM4(a0,a1,a2,a3, aaddr);
            }
#pragma unroll
            for (int st = 0; st < 8; st++) {
                int n0 = jbase + st * 16;
                unsigned b0,b1r,b2,b3;
                int br = k0 + (lane & 15);
                int bc = (n0 >> 3) + (lane >> 4);
                unsigned baddr = sbase + FFN_SW1 + br*512 + ((bc ^ (br & 7)) << 4);
                LDSM4T(b0,b1r,b2,b3, baddr);
                MMA16816(acc[2*st][0],acc[2*st][1],acc[2*st][2],acc[2*st][3],
                         a0,a1,a2,a3, b0,b1r);
                MMA16816(acc[2*st+1][0],acc[2*st+1][1],acc[2*st+1][2],acc[2*st+1][3],
                         a0,a1,a2,a3, b2,b3);
            }
        }

        // ---------- gelu in registers, pack to A-frags of phase 2 ----------
        unsigned pk[8][4];
#pragma unroll
        for (int m = 0; m < 16; m++) {
            int col = jbase + m*8 + 2*tig;
            float bb0 = sb1[col], bb1 = sb1[col+1];
            float h00 = gelu_f(acc[m][0] + bb0);
            float h01 = gelu_f(acc[m][1] + bb1);
            float h10 = gelu_f(acc[m][2] + bb0);
            float h11 = gelu_f(acc[m][3] + bb1);
            if ((m & 1) == 0) {
                pk[m>>1][0] = bf2u(h00, h01);
                pk[m>>1][1] = bf2u(h10, h11);
            } else {
                pk[m>>1][2] = bf2u(h00, h01);
                pk[m>>1][3] = bf2u(h10, h11);
            }
        }

        // ---------- phase 2: partial out = H_slab @ W2[jbase:+128][0:64] ----------
        float acc2[8][4];
#pragma unroll
        for (int m = 0; m < 8; m++)
#pragma unroll
            for (int p = 0; p < 4; p++) acc2[m][p] = 0.f;

#pragma unroll
        for (int ks = 0; ks < 8; ks++) {
            const int br = jbase + ks*16 + (lane & 15);
#pragma unroll
            for (int st = 0; st < 4; st++) {
                int n0 = st * 16;
                unsigned b0,b1r,b2,b3;
                int bc = (n0 >> 3) + (lane >> 4);
                unsigned baddr = sbase + FFN_SW2 + br*128 + ((bc ^ (br & 7)) << 4);
                LDSM4T(b0,b1r,b2,b3, baddr);
                MMA16816(acc2[2*st][0],acc2[2*st][1],acc2[2*st][2],acc2[2*st][3],
                         pk[ks][0],pk[ks][1],pk[ks][2],pk[ks][3], b0,b1r);
                MMA16816(acc2[2*st+1][0],acc2[2*st+1][1],acc2[2*st+1][2],acc2[2*st+1][3],
                         pk[ks][0],pk[ks][1],pk[ks][2],pk[ks][3], b2,b3);
            }
        }

        // ---------- cross-warp k-reduction (balanced halves) ----------
        float* red = (float*)(smc + FFN_SRED) + tw * (16*68);
        const int st_sto = (nh == 1) ? 0 : 4;
        const int st_fin = (nh == 1) ? 4 : 0;
#pragma unroll
        for (int s = 0; s < 4; s++) {
            int st = st_sto + s;
#pragma unroll
            for (int rp = 0; rp < 2; rp++) {
                int row = gid + rp*8;
                *(float2*)(red + row*68 + st*8 + 2*tig) =
                    make_float2(acc2[st][2*rp], acc2[st][2*rp+1]);
            }
        }
        __syncthreads();
#pragma unroll
        for (int s = 0; s < 4; s++) {
            int st = st_fin + s;
            int e = st*8 + 2*tig;
            float bb0 = sb2[e], bb1 = sb2[e+1];
#pragma unroll
            for (int rp = 0; rp < 2; rp++) {
                int row = gid + rp*8;
                float2 r = *(const float2*)(red + row*68 + e);
                float2 x = *(const float2*)(xin + (base + t0 + row)*64 + e);
                float2 o = make_float2(x.x + r.x + acc2[st][2*rp]   + bb0,
                                       x.y + r.y + acc2[st][2*rp+1] + bb1);
                *(float2*)(xout + (base + t0 + row)*64 + e) = o;
            }
        }
        __syncthreads();
    }
}

// ==================================================================
// Attention kernel: out = x + attn(LN(x)) ; NT tiles per CTA
// ==================================================================
#define ATT_ST    0
#define ATT_SWP   24576
#define ATT_SA    32768
#define ATT_SOB   32768          // alias: sA dead after phase 1
#define ATT_SQKV  40960
#define ATT_SBQKV 65536
#define ATT_SBP   66304
#define ATT_SG    66560
#define ATT_SMEM_BYTES 67072

template <bool CAUSAL>
__global__ void __launch_bounds__(TPB, 2) attn_kernel(
    const float* __restrict__ xin, float* __restrict__ xout,
    const __nv_bfloat16* __restrict__ Tqkv, const __nv_bfloat16* __restrict__ Wpb,
    const float* __restrict__ bq, const float* __restrict__ bk,
    const float* __restrict__ bv, const float* __restrict__ bp,
    const float* __restrict__ g1, const float* __restrict__ be1)
{
    extern __shared__ char smc[];
    float* sbqkv = (float*)(smc + ATT_SBQKV);
    float* sbp   = (float*)(smc + ATT_SBP);
    float* sg    = (float*)(smc + ATT_SG);

    const int tid = threadIdx.x;
    const unsigned sbase = su32(smc);

    {
        const uint4* srcT = (const uint4*)Tqkv;   // 64 rows x 24 chunks
        for (int c = tid; c < 1536; c += TPB) {
            int r = c / 24, ch = c % 24;
            *(uint4*)(smc + ATT_ST + r*384 + ((ch ^ (r & 7)) << 4)) = srcT[c];
        }
        const uint4* srcP = (const uint4*)Wpb;
        for (int c = tid; c < 512; c += TPB) {
            int r = c >> 3, ch = c & 7;
            *(uint4*)(smc + ATT_SWP + r*128 + ((ch ^ (r & 7)) << 4)) = srcP[c];
        }
    }
    if (tid < 192) sbqkv[tid] = (tid < 64) ? bq[tid] : (tid < 128 ? bk[tid-64] : bv[tid-128]);
    if (tid < 64)  sbp[tid] = bp[tid];
    if (tid < 128) sg[tid] = (tid < 64) ? g1[tid] : be1[tid-64];
    __syncthreads();

    const int lane = tid & 31, wid = tid >> 5;
    const int gid = lane >> 2, tig = lane & 3;
    const int tw = wid & 3, nh = wid >> 2;
    const int t0 = tw * 16;

    for (int tt = 0; tt < NT; tt++) {
        const size_t base = ((size_t)blockIdx.x * NT + tt) * TOKS;
        ln_tile_bf16(xin, base, smc + ATT_SA, tid, sg);
        __syncthreads();

        // ---------- phase 1: QKV = A @ T + b ; warp = batch tw, 96 c-cols ----------
        {
            const int cbase = nh * 96;
            float acc[12][4];
#pragma unroll
            for (int m = 0; m < 12; m++)
#pragma unroll
                for (int p = 0; p < 4; p++) acc[m][p] = 0.f;

#pragma unroll
            for (int ks = 0; ks < 4; ks++) {
                const int k0 = ks * 16;
                unsigned a0,a1,a2,a3;
                {
                    int ar = t0 + (lane & 15);
                    int ac = (k0 >> 3) + (lane >> 4);
                    unsigned aaddr = sbase + ATT_SA + ar*128 + ((ac ^ (ar & 7)) << 4);
                    LDSM4(a0,a1,a2,a3, aaddr);
                }
#pragma unroll
                for (int st = 0; st < 6; st++) {
                    int n0 = cbase + st * 16;
                    unsigned b0,b1r,b2,b3;
                    int br = k0 + (lane & 15);
                    int bc = (n0 >> 3) + (lane >> 4);
                    unsigned baddr = sbase + ATT_ST + br*384 + ((bc ^ (br & 7)) << 4);
                    LDSM4T(b0,b1r,b2,b3, baddr);
                    MMA16816(acc[2*st][0],acc[2*st][1],acc[2*st][2],acc[2*st][3],
                             a0,a1,a2,a3, b0,b1r);
                    MMA16816(acc[2*st+1][0],acc[2*st+1][1],acc[2*st+1][2],acc[2*st+1][3],
                             a0,a1,a2,a3, b2,b3);
                }
            }
#pragma unroll
            for (int m = 0; m < 12; m++) {
                int cc = cbase + m*8;
                int sec = cc >> 6;               // 0=q 1=k 2=v
                int h = (cc >> 3) & 7;
                int c = cc + 2*tig;
                float bb0 = sbqkv[c], bb1 = sbqkv[c+1];
                float scale = (sec == 0) ? 0.35355339059327373f : 1.f;
                float v00 = (acc[m][0] + bb0) * scale, v01 = (acc[m][1] + bb1) * scale;
                float v10 = (acc[m][2] + bb0) * scale, v11 = (acc[m][3] + bb1) * scale;
                unsigned tb = ATT_SQKV + sec*8192 + (tw*8 + h)*256 + tig*4;
                *(unsigned*)(smc + tb + gid*16)       = bf2u(v00, v01);
                *(unsigned*)(smc + tb + (gid+8)*16)   = bf2u(v10, v11);
            }
        }
        __syncthreads();

        // ---------- phase 2: MMA attention core; warp handles 4 (b,h) pairs ----------
        {
#pragma unroll
            for (int i = 0; i < 4; i++) {
                const int p = wid*4 + i;
                const int b = p >> 3, h = p & 7;
                const unsigned tq = sbase + ATT_SQKV + (b*8+h)*256 + (lane & 15)*16;

                unsigned qa0, qa1, kb0, kb1, vb0, vb1;
                LDSM2 (qa0, qa1, tq);
                LDSM2 (kb0, kb1, tq + 8192);
                LDSM2T(vb0, vb1, tq + 16384);

                float s0=0,s1=0,s2=0,s3=0,s4=0,s5=0,s6=0,s7=0;
                MMA16808(s0,s1,s2,s3, qa0,qa1, kb0);
                MMA16808(s4,s5,s6,s7, qa0,qa1, kb1);

                if (CAUSAL) {
                    const int u0 = 2*tig, u1 = 2*tig+1, u2 = 2*tig+8, u3 = 2*tig+9;
                    if (u0 > gid)   s0 = -1e30f;
                    if (u1 > gid)   s1 = -1e30f;
                    if (u2 > gid)   s4 = -1e30f;
                    if (u3 > gid)   s5 = -1e30f;
                    if (u0 > gid+8) s2 = -1e30f;
                    if (u1 > gid+8) s3 = -1e30f;
                    if (u2 > gid+8) s6 = -1e30f;
                    if (u3 > gid+8) s7 = -1e30f;
                }
                float e0 = __expf(s0), e1 = __expf(s1);
                float e4 = __expf(s4), e5 = __expf(s5);
                float e2 = __expf(s2), e3 = __expf(s3);
                float e6 = __expf(s6), e7 = __expf(s7);
                float slo = e0+e1+e4+e5, shi = e2+e3+e6+e7;
                slo += __shfl_xor_sync(0xffffffffu, slo, 1);
                slo += __shfl_xor_sync(0xffffffffu, slo, 2);
                shi += __shfl_xor_sync(0xffffffffu, shi, 1);
                shi += __shfl_xor_sync(0xffffffffu, shi, 2);
                const float ilo = 1.f/slo, ihi = 1.f/shi;

                unsigned pa0 = bf2u(e0, e1);
                unsigned pa1 = bf2u(e2, e3);
                unsigned pa2 = bf2u(e4, e5);
                unsigned pa3 = bf2u(e6, e7);

                float o0=0,o1=0,o2=0,o3=0;
                MMA16816(o0,o1,o2,o3, pa0,pa1,pa2,pa3, vb0,vb1);
                o0 *= ilo; o1 *= ilo; o2 *= ihi; o3 *= ihi;

                const int tA = b*16 + gid, tB = tA + 8;
                const int c = h*8 + 2*tig;
                unsigned offA = ATT_SOB + tA*128 + (((c>>3) ^ (tA & 7)) << 4) + ((c & 7) << 1);
                unsigned offB = ATT_SOB + tB*128 + (((c>>3) ^ (tB & 7)) << 4) + ((c & 7) << 1);
                *(unsigned*)(smc + offA) = bf2u(o0, o1);
                *(unsigned*)(smc + offB) = bf2u(o2, o3);
            }
        }
        __syncthreads();

        // ---------- phase 3: out = x + O @ Wp + bp ; warp = 16t x 32e ----------
        {
            const int ebase = nh * 32;
            float acc[4][4];
#pragma unroll
            for (int m = 0; m < 4; m++)
#pragma unroll
                for (int p = 0; p < 4; p++) acc[m][p] = 0.f;

#pragma unroll
            for (int ks = 0; ks < 4; ks++) {
                const int k0 = ks * 16;
                unsigned a0,a1,a2,a3;
                {
                    int ar = t0 + (lane & 15);
                    int ac = (k0 >> 3) + (lane >> 4);
                    unsigned aaddr = sbase + ATT_SOB + ar*128 + ((ac ^ (ar & 7)) << 4);
                    LDSM4(a0,a1,a2,a3, aaddr);
                }
#pragma unroll
                for (int st = 0; st < 2; st++) {
                    int n0 = ebase + st * 16;
                    unsigned b0,b1r,b2,b3;
                    int br = k0 + (lane & 15);
                    int bc = (n0 >> 3) + (lane >> 4);
                    unsigned baddr = sbase + ATT_SWP + br*128 + ((bc ^ (br & 7)) << 4);
                    LDSM4T(b0,b1r,b2,b3, baddr);
                    MMA16816(acc[2*st][0],acc[2*st][1],acc[2*st][2],acc[2*st][3],
                             a0,a1,a2,a3, b0,b1r);
                    MMA16816(acc[2*st+1][0],acc[2*st+1][1],acc[2*st+1][2],acc[2*st+1][3],
                             a0,a1,a2,a3, b2,b3);
                }
            }
            const int r0 = t0 + gid, r1 = t0 + gid + 8;
#pragma unroll
            for (int m = 0; m < 4; m++) {
                int e = ebase + m*8 + 2*tig;
                float bb0 = sbp[e], bb1 = sbp[e+1];
                float2 x0 = *(const float2*)(xin + (base + r0)*64 + e);
                float2 x1 = *(const float2*)(xin + (base + r1)*64 + e);
                float2 o0 = make_float2(x0.x + acc[m][0] + bb0, x0.y + acc[m][1] + bb1);
                float2 o1 = make_float2(x1.x + acc[m][2] + bb0, x1.y + acc[m][3] + bb1);
                *(float2*)(xout + (base + r0)*64 + e) = o0;
                *(float2*)(xout + (base + r1)*64 + e) = o1;
            }
        }
        __syncthreads();
    }
}

// ==================================================================
// launch: prep -> attn(u) -> ffn -> attn(m, causal) -> ffn
// ==================================================================
extern "C" void kernel_launch(void* const* d_in, const int* in_sizes, int n_in,
                              void* d_out, int out_size)
{
    (void)in_sizes; (void)n_in; (void)out_size;
    const float* x   = (const float*)d_in[0];
    const float* uWq = (const float*)d_in[1];  const float* ubq = (const float*)d_in[2];
    const float* uWk = (const float*)d_in[3];  const float* ubk = (const float*)d_in[4];
    const float* uWv = (const float*)d_in[5];  const float* ubv = (const float*)d_in[6];
    const float* uWp = (const float*)d_in[7];  const float* ubp = (const float*)d_in[8];
    const float* mWq = (const float*)d_in[9];  const float* mbq = (const float*)d_in[10];
    const float* mWk = (const float*)d_in[11]; const float* mbk = (const float*)d_in[12];
    const float* mWv = (const float*)d_in[13]; const float* mbv = (const float*)d_in[14];
    const float* mWp = (const float*)d_in[15]; const float* mbp = (const float*)d_in[16];
    const float* fW1 = (const float*)d_in[17]; const float* fb1 = (const float*)d_in[18];
    const float* fW2 = (const float*)d_in[19]; const float* fb2 = (const float*)d_in[20];
    const float* g1  = (const float*)d_in[21]; const float* be1 = (const float*)d_in[22];
    const float* g2  = (const float*)d_in[23]; const float* be2 = (const float*)d_in[24];
    float* out = (float*)d_out;

    float* scratch = nullptr;
    cudaGetSymbolAddress((void**)&scratch, g_scratch);
    __nv_bfloat16 *Tu = nullptr, *Tm = nullptr, *Wpu = nullptr, *Wpm = nullptr;
    cudaGetSymbolAddress((void**)&Tu, g_Tu);
    cudaGetSymbolAddress((void**)&Tm, g_Tm);
    cudaGetSymbolAddress((void**)&Wpu, g_Wpu);
    cudaGetSymbolAddress((void**)&Wpm, g_Wpm);

    cudaFuncSetAttribute(attn_kernel<false>, cudaFuncAttributeMaxDynamicSharedMemorySize, ATT_SMEM_BYTES);
    cudaFuncSetAttribute(attn_kernel<true>,  cudaFuncAttributeMaxDynamicSharedMemorySize, ATT_SMEM_BYTES);
    cudaFuncSetAttribute(ffn_kernel,         cudaFuncAttributeMaxDynamicSharedMemorySize, FFN_SMEM_BYTES);

    prep_kernel<<<32, 256>>>(fW1, fW2, uWq, uWk, uWv, uWp, mWq, mWk, mWv, mWp);

    attn_kernel<false><<<NBLK, TPB, ATT_SMEM_BYTES>>>(x, scratch, Tu, Wpu,
        ubq, ubk, ubv, ubp, g1, be1);
    ffn_kernel<<<NBLK, TPB, FFN_SMEM_BYTES>>>(scratch, out, fb1, fb2, g2, be2);
    attn_kernel<true><<<NBLK, TPB, ATT_SMEM_BYTES>>>(out, scratch, Tm, Wpm,
        mbq, mbk, mbv, mbp, g1, be1);
    ffn_kernel<<<NBLK, TPB, FFN_SMEM_BYTES>>>(scratch, out, fb1, fb2, g2, be2);
}

// round 8
// speedup vs baseline: 5.6260x; 1.0151x over previous
#include <cuda_runtime.h>
#include <cuda_bf16.h>
#include <math.h>

#define NTOK (32768*16)          // 524288 tokens
#define TPB  256
#define TOKS 64                  // tokens per tile
#define NT   4                   // tiles per CTA
#define NBLK (NTOK/(TOKS*NT))    // 2048 CTAs

// ---------------- device globals (allocation-free scratch) ----------------
__device__ float g_scratch[(size_t)NTOK * 64];
__device__ __align__(16) __nv_bfloat16 g_W1b[64*256];
__device__ __align__(16) __nv_bfloat16 g_W2b[256*64];
__device__ __align__(16) __nv_bfloat16 g_Tu[64*192];   // [d][h*8+s (+0/64/128 for q/k/v)]
__device__ __align__(16) __nv_bfloat16 g_Tm[64*192];
__device__ __align__(16) __nv_bfloat16 g_Wpu[64*64];
__device__ __align__(16) __nv_bfloat16 g_Wpm[64*64];

// ---------------- small helpers ----------------
__device__ __forceinline__ unsigned bf2u(float a, float b) {
    unsigned r;
    asm("cvt.rn.bf16x2.f32 %0, %1, %2;" : "=r"(r) : "f"(b), "f"(a));
    return r;
}
__device__ __forceinline__ unsigned su32(const void* p) {
    return (unsigned)__cvta_generic_to_shared(p);
}
// fast GELU: 0.5z(1+tanh(0.79788456(z + 0.044715 z^3))), HW tanh
__device__ __forceinline__ float gelu_f(float z) {
    float w = z * fmaf(0.035677408136f, z*z, 0.79788456080287f);
    float t;
    asm("tanh.approx.f32 %0, %1;" : "=f"(t) : "f"(w));
    float hz = 0.5f*z;
    return fmaf(hz, t, hz);
}

#define LDSM2(r0,r1,addr) \
    asm volatile("ldmatrix.sync.aligned.m8n8.x2.shared.b16 {%0,%1},[%2];" \
        : "=r"(r0),"=r"(r1) : "r"(addr))
#define LDSM2T(r0,r1,addr) \
    asm volatile("ldmatrix.sync.aligned.m8n8.x2.trans.shared.b16 {%0,%1},[%2];" \
        : "=r"(r0),"=r"(r1) : "r"(addr))
#define LDSM4(r0,r1,r2,r3,addr) \
    asm volatile("ldmatrix.sync.aligned.m8n8.x4.shared.b16 {%0,%1,%2,%3},[%4];" \
        : "=r"(r0),"=r"(r1),"=r"(r2),"=r"(r3) : "r"(addr))
#define LDSM4T(r0,r1,r2,r3,addr) \
    asm volatile("ldmatrix.sync.aligned.m8n8.x4.trans.shared.b16 {%0,%1,%2,%3},[%4];" \
        : "=r"(r0),"=r"(r1),"=r"(r2),"=r"(r3) : "r"(addr))
#define MMA16816(c0,c1,c2,c3,a0,a1,a2,a3,b0,b1) \
    asm volatile("mma.sync.aligned.m16n8k16.row.col.f32.bf16.bf16.f32 " \
        "{%0,%1,%2,%3},{%4,%5,%6,%7},{%8,%9},{%0,%1,%2,%3};" \
        : "+f"(c0),"+f"(c1),"+f"(c2),"+f"(c3) \
        : "r"(a0),"r"(a1),"r"(a2),"r"(a3),"r"(b0),"r"(b1))
#define MMA16808(c0,c1,c2,c3,a0,a1,b0) \
    asm volatile("mma.sync.aligned.m16n8k8.row.col.f32.bf16.bf16.f32 " \
        "{%0,%1,%2,%3},{%4,%5},{%6},{%0,%1,%2,%3};" \
        : "+f"(c0),"+f"(c1),"+f"(c2),"+f"(c3) \
        : "r"(a0),"r"(a1),"r"(b0))

// ---- LN split into prefetch (LDG only) + commit (shuffle + STS) ----
// token = tid>>2, quarter = tid&3
__device__ __forceinline__ void ln_prefetch(float* xv, const float* __restrict__ xin,
                                            size_t base, int tid) {
    const int t = tid >> 2, qp = tid & 3;
    const float4* x4 = (const float4*)(xin + (base + t)*64) + qp*4;
#pragma unroll
    for (int i = 0; i < 4; i++) {
        float4 v = x4[i];
        xv[4*i]=v.x; xv[4*i+1]=v.y; xv[4*i+2]=v.z; xv[4*i+3]=v.w;
    }
}
__device__ __forceinline__ void ln_commit(const float* xv, char* __restrict__ sA,
                                          int tid, const float* __restrict__ sg) {
    const int t = tid >> 2, qp = tid & 3;
    float s = 0.f, ss = 0.f;
#pragma unroll
    for (int i = 0; i < 16; i++) { s += xv[i]; ss = fmaf(xv[i], xv[i], ss); }
    s  += __shfl_xor_sync(0xffffffffu, s, 1);  ss += __shfl_xor_sync(0xffffffffu, ss, 1);
    s  += __shfl_xor_sync(0xffffffffu, s, 2);  ss += __shfl_xor_sync(0xffffffffu, ss, 2);
    const float mean = s * (1.f/64.f);
    const float var  = ss * (1.f/64.f) - mean*mean;
    const float rstd = rsqrtf(var + 1e-5f);
    const int kb = qp * 16;
#pragma unroll
    for (int c = 0; c < 2; c++) {
        float v[8];
#pragma unroll
        for (int e = 0; e < 8; e++) {
            int k = kb + c*8 + e;
            v[e] = (xv[c*8+e] - mean) * rstd * sg[k] + sg[64+k];
        }
        uint4 q;
        q.x = bf2u(v[0], v[1]); q.y = bf2u(v[2], v[3]);
        q.z = bf2u(v[4], v[5]); q.w = bf2u(v[6], v[7]);
        int ch = qp*2 + c;
        *(uint4*)(sA + t*128 + ((ch ^ (t & 7)) << 4)) = q;
    }
}

// ---------------- prep: fp32 weights -> bf16 (and qkv transpose) ----------------
__global__ void prep_kernel(const float* __restrict__ W1, const float* __restrict__ W2,
                            const float* __restrict__ uWq, const float* __restrict__ uWk,
                            const float* __restrict__ uWv, const float* __restrict__ uWp,
                            const float* __restrict__ mWq, const float* __restrict__ mWk,
                            const float* __restrict__ mWv, const float* __restrict__ mWp)
{
    int i0 = blockIdx.x * blockDim.x + threadIdx.x;
    int stride = gridDim.x * blockDim.x;
    for (int i = i0; i < 16384; i += stride) {
        g_W1b[i] = __float2bfloat16(W1[i]);
        g_W2b[i] = __float2bfloat16(W2[i]);
    }
    for (int i = i0; i < 4096; i += stride) {
        int h = i >> 9, d = (i >> 3) & 63, s = i & 7;
        int c = h*8 + s;
        g_Tu[d*192 + c]       = __float2bfloat16(uWq[i]);
        g_Tu[d*192 + 64 + c]  = __float2bfloat16(uWk[i]);
        g_Tu[d*192 + 128 + c] = __float2bfloat16(uWv[i]);
        g_Tm[d*192 + c]       = __float2bfloat16(mWq[i]);
        g_Tm[d*192 + 64 + c]  = __float2bfloat16(mWk[i]);
        g_Tm[d*192 + 128 + c] = __float2bfloat16(mWv[i]);
        g_Wpu[i] = __float2bfloat16(uWp[i]);
        g_Wpm[i] = __float2bfloat16(mWp[i]);
    }
}

// ==================================================================
// FFN kernel: out = x + gelu(LN(x)@W1 + b1)@W2 + b2 ; NT tiles/CTA,
// LN software-pipelined across tiles (double-buffered sA).
// ==================================================================
#define FFN_SW1  0
#define FFN_SW2  32768
#define FFN_SA0  65536
#define FFN_SA1  73728
#define FFN_SRED 81920            // 4 groups x 16 x 68 floats = 17408
#define FFN_SB1  99328
#define FFN_SB2  100352
#define FFN_SG   100608
#define FFN_SMEM_BYTES 101120

__global__ void __launch_bounds__(TPB, 2) ffn_kernel(
    const float* __restrict__ xin, float* __restrict__ xout,
    const float* __restrict__ b1, const float* __restrict__ b2,
    const float* __restrict__ g2, const float* __restrict__ be2)
{
    extern __shared__ char smc[];
    float* sb1 = (float*)(smc + FFN_SB1);
    float* sb2 = (float*)(smc + FFN_SB2);
    float* sg  = (float*)(smc + FFN_SG);

    const int tid = threadIdx.x;
    const unsigned sbase = su32(smc);

    {
        const uint4* src1 = (const uint4*)g_W1b;
        const uint4* src2 = (const uint4*)g_W2b;
        for (int c = tid; c < 2048; c += TPB) {
            int r1 = c >> 5, c1 = c & 31;
            *(uint4*)(smc + FFN_SW1 + r1*512 + ((c1 ^ (r1 & 7)) << 4)) = src1[c];
            int r2 = c >> 3, c2 = c & 7;
            *(uint4*)(smc + FFN_SW2 + r2*128 + ((c2 ^ (r2 & 7)) << 4)) = src2[c];
        }
    }
    sb1[tid] = b1[tid];
    if (tid < 64) { sb2[tid] = b2[tid]; sg[tid] = g2[tid]; sg[64+tid] = be2[tid]; }
    __syncthreads();

    const int lane = tid & 31, wid = tid >> 5;
    const int gid = lane >> 2, tig = lane & 3;
    const int tw = wid & 3, nh = wid >> 2;
    const int t0 = tw * 16;
    const int jbase = nh * 128;

    const size_t cta0 = (size_t)blockIdx.x * NT * TOKS;

    // prologue: LN tile 0
    float xv[16];
    ln_prefetch(xv, xin, cta0, tid);
    ln_commit(xv, smc + FFN_SA0, tid, sg);
    __syncthreads();

    for (int tt = 0; tt < NT; tt++) {
        const size_t base = cta0 + (size_t)tt * TOKS;
        const unsigned curA = sbase + (((tt & 1) == 0) ? FFN_SA0 : FFN_SA1);
        const unsigned nxtOff = (((tt & 1) == 0) ? FFN_SA1 : FFN_SA0);

        // ---------- phase 1: Z = A @ W1 (c-frags in regs); warp = 16t x 128j ----------
        float acc[16][4];
#pragma unroll
        for (int m = 0; m < 16; m++)
#pragma unroll
            for (int p = 0; p < 4; p++) acc[m][p] = 0.f;

#pragma unroll
        for (int ks = 0; ks < 4; ks++) {
            const int k0 = ks * 16;
            unsigned a0,a1,a2,a3;
            {
                int ar = t0 + (lane & 15);
                int ac = (k0 >> 3) + (lane >> 4);
                unsigned aaddr = curA + ar*128 + ((ac ^ (ar & 7)) << 4);
                LDSM4(a0,a1,a2,a3, aaddr);
            }
#pragma unroll
            for (int st = 0; st < 8; st++) {
                int n0 = jbase + st * 16;
                unsigned b0,b1r,b2,b3;
                int br = k0 + (lane & 15);
                int bc = (n0 >> 3) + (lane >> 4);
                unsigned baddr = sbase + FFN_SW1 + br*512 + ((bc ^ (br & 7)) << 4);
                LDSM4T(b0,b1r,b2,b3, baddr);
                MMA16816(acc[2*st][0],acc[2*st][1],acc[2*st][2],acc[2*st][3],
                         a0,a1,a2,a3, b0,b1r);
                MMA16816(acc[2*st+1][0],acc[2*st+1][1],acc[2*st+1][2],acc[2*st+1][3],
                         a0,a1,a2,a3, b2,b3);
            }
        }

        // ---------- gelu in registers, pack to A-frags of phase 2 ----------
        unsigned pk[8][4];
#pragma unroll
        for (int m = 0; m < 16; m++) {
            int col = jbase + m*8 + 2*tig;
            float bb0 = sb1[col], bb1 = sb1[col+1];
            float h00 = gelu_f(acc[m][0] + bb0);
            float h01 = gelu_f(acc[m][1] + bb1);
            float h10 = gelu_f(acc[m][2] + bb0);
            float h11 = gelu_f(acc[m][3] + bb1);
            if ((m & 1) == 0) {
                pk[m>>1][0] = bf2u(h00, h01);
                pk[m>>1][1] = bf2u(h10, h11);
            } else {
                pk[m>>1][2] = bf2u(h00, h01);
                pk[m>>1][3] = bf2u(h10, h11);
            }
        }

        // prefetch next tile's x (acc is dead; low register pressure window)
        if (tt + 1 < NT) ln_prefetch(xv, xin, base + TOKS, tid);

        // ---------- phase 2: partial out = H_slab @ W2[jbase:+128][0:64] ----------
        float acc2[8][4];
#pragma unroll
        for (int m = 0; m < 8; m++)
#pragma unroll
            for (int p = 0; p < 4; p++) acc2[m][p] = 0.f;

#pragma unroll
        for (int ks = 0; ks < 8; ks++) {
            const int br = jbase + ks*16 + (lane & 15);
#pragma unroll
            for (int st = 0; st < 4; st++) {
                int n0 = st * 16;
                unsigned b0,b1r,b2,b3;
                int bc = (n0 >> 3) + (lane >> 4);
                unsigned baddr = sbase + FFN_SW2 + br*128 + ((bc ^ (br & 7)) << 4);
                LDSM4T(b0,b1r,b2,b3, baddr);
                MMA16816(acc2[2*st][0],acc2[2*st][1],acc2[2*st][2],acc2[2*st][3],
                         pk[ks][0],pk[ks][1],pk[ks][2],pk[ks][3], b0,b1r);
                MMA16816(acc2[2*st+1][0],acc2[2*st+1][1],acc2[2*st+1][2],acc2[2*st+1][3],
                         pk[ks][0],pk[ks][1],pk[ks][2],pk[ks][3], b2,b3);
            }
        }

        // ---------- cross-warp k-reduction (balanced halves) ----------
        float* red = (float*)(smc + FFN_SRED) + tw * (16*68);
        const int st_sto = (nh == 1) ? 0 : 4;
        const int st_fin = (nh == 1) ? 4 : 0;
#pragma unroll
        for (int s = 0; s < 4; s++) {
            int st = st_sto + s;
#pragma unroll
            for (int rp = 0; rp < 2; rp++) {
                int row = gid + rp*8;
                *(float2*)(red + row*68 + st*8 + 2*tig) =
                    make_float2(acc2[st][2*rp], acc2[st][2*rp+1]);
            }
        }
        __syncthreads();
#pragma unroll
        for (int s = 0; s < 4; s++) {
            int st = st_fin + s;
            int e = st*8 + 2*tig;
            float bb0 = sb2[e], bb1 = sb2[e+1];
#pragma unroll
            for (int rp = 0; rp < 2; rp++) {
                int row = gid + rp*8;
                float2 r = *(const float2*)(red + row*68 + e);
                float2 x = *(const float2*)(xin + (base + t0 + row)*64 + e);
                float2 o = make_float2(x.x + r.x + acc2[st][2*rp]   + bb0,
                                       x.y + r.y + acc2[st][2*rp+1] + bb1);
                *(float2*)(xout + (base + t0 + row)*64 + e) = o;
            }
        }

        // commit LN of next tile into the other sA buffer
        if (tt + 1 < NT) ln_commit(xv, smc + nxtOff, tid, sg);
        __syncthreads();
    }
}

// ==================================================================
// Attention kernel: out = x + attn(LN(x)) ; NT tiles/CTA,
// LN software-pipelined (double-buffered sA; sOb now separate).
// ==================================================================
#define ATT_ST    0
#define ATT_SWP   24576
#define ATT_SA0   32768
#define ATT_SA1   40960
#define ATT_SOB   49152
#define ATT_SQKV  57344
#define ATT_SBQKV 81920
#define ATT_SBP   82688
#define ATT_SG    82944
#define ATT_SMEM_BYTES 83456

template <bool CAUSAL>
__global__ void __launch_bounds__(TPB, 2) attn_kernel(
    const float* __restrict__ xin, float* __restrict__ xout,
    const __nv_bfloat16* __restrict__ Tqkv, const __nv_bfloat16* __restrict__ Wpb,
    const float* __restrict__ bq, const float* __restrict__ bk,
    const float* __restrict__ bv, const float* __restrict__ bp,
    const float* __restrict__ g1, const float* __restrict__ be1)
{
    extern __shared__ char smc[];
    float* sbqkv = (float*)(smc + ATT_SBQKV);
    float* sbp   = (float*)(smc + ATT_SBP);
    float* sg    = (float*)(smc + ATT_SG);

    const int tid = threadIdx.x;
    const unsigned sbase = su32(smc);

    {
        const uint4* srcT = (const uint4*)Tqkv;   // 64 rows x 24 chunks
        for (int c = tid; c < 1536; c += TPB) {
            int r = c / 24, ch = c % 24;
            *(uint4*)(smc + ATT_ST + r*384 + ((ch ^ (r & 7)) << 4)) = srcT[c];
        }
        const uint4* srcP = (const uint4*)Wpb;
        for (int c = tid; c < 512; c += TPB) {
            int r = c >> 3, ch = c & 7;
            *(uint4*)(smc + ATT_SWP + r*128 + ((ch ^ (r & 7)) << 4)) = srcP[c];
        }
    }
    if (tid < 192) sbqkv[tid] = (tid < 64) ? bq[tid] : (tid < 128 ? bk[tid-64] : bv[tid-128]);
    if (tid < 64)  sbp[tid] = bp[tid];
    if (tid < 128) sg[tid] = (tid < 64) ? g1[tid] : be1[tid-64];
    __syncthreads();

    const int lane = tid & 31, wid = tid >> 5;
    const int gid = lane >> 2, tig = lane & 3;
    const int tw = wid & 3, nh = wid >> 2;
    const int t0 = tw * 16;

    const size_t cta0 = (size_t)blockIdx.x * NT * TOKS;

    float xv[16];
    ln_prefetch(xv, xin, cta0, tid);
    ln_commit(xv, smc + ATT_SA0, tid, sg);
    __syncthreads();

    for (int tt = 0; tt < NT; tt++) {
        const size_t base = cta0 + (size_t)tt * TOKS;
        const unsigned curA = sbase + (((tt & 1) == 0) ? ATT_SA0 : ATT_SA1);
        const unsigned nxtOff = (((tt & 1) == 0) ? ATT_SA1 : ATT_SA0);

        // ---------- phase 1: QKV = A @ T + b ; warp = batch tw, 96 c-cols ----------
        {
            const int cbase = nh * 96;
            float acc[12][4];
#pragma unroll
            for (int m = 0; m < 12; m++)
#pragma unroll
                for (int p = 0; p < 4; p++) acc[m][p] = 0.f;

#pragma unroll
            for (int ks = 0; ks < 4; ks++) {
                const int k0 = ks * 16;
                unsigned a0,a1,a2,a3;
                {
                    int ar = t0 + (lane & 15);
                    int ac = (k0 >> 3) + (lane >> 4);
                    unsigned aaddr = curA + ar*128 + ((ac ^ (ar & 7)) << 4);
                    LDSM4(a0,a1,a2,a3, aaddr);
                }
#pragma unroll
                for (int st = 0; st < 6; st++) {
                    int n0 = cbase + st * 16;
                    unsigned b0,b1r,b2,b3;
                    int br = k0 + (lane & 15);
                    int bc = (n0 >> 3) + (lane >> 4);
                    unsigned baddr = sbase + ATT_ST + br*384 + ((bc ^ (br & 7)) << 4);
                    LDSM4T(b0,b1r,b2,b3, baddr);
                    MMA16816(acc[2*st][0],acc[2*st][1],acc[2*st][2],acc[2*st][3],
                             a0,a1,a2,a3, b0,b1r);
                    MMA16816(acc[2*st+1][0],acc[2*st+1][1],acc[2*st+1][2],acc[2*st+1][3],
                             a0,a1,a2,a3, b2,b3);
                }
            }

            // prefetch next tile's x (covers epilogue + phases 2/3)
            if (tt + 1 < NT) ln_prefetch(xv, xin, base + TOKS, tid);

#pragma unroll
            for (int m = 0; m < 12; m++) {
                int cc = cbase + m*8;
                int sec = cc >> 6;               // 0=q 1=k 2=v
                int h = (cc >> 3) & 7;
                int c = cc + 2*tig;
                float bb0 = sbqkv[c], bb1 = sbqkv[c+1];
                float scale = (sec == 0) ? 0.35355339059327373f : 1.f;
                float v00 = (acc[m][0] + bb0) * scale, v01 = (acc[m][1] + bb1) * scale;
                float v10 = (acc[m][2] + bb0) * scale, v11 = (acc[m][3] + bb1) * scale;
                unsigned tb = ATT_SQKV + sec*8192 + (tw*8 + h)*256 + tig*4;
                *(unsigned*)(smc + tb + gid*16)       = bf2u(v00, v01);
                *(unsigned*)(smc + tb + (gid+8)*16)   = bf2u(v10, v11);
            }
        }
        __syncthreads();

        // ---------- phase 2: MMA attention core; warp handles 4 (b,h) pairs ----------
        {
#pragma unroll
            for (int i = 0; i < 4; i++) {
                const int p = wid*4 + i;
                const int b = p >> 3, h = p & 7;
                const unsigned tq = sbase + ATT_SQKV + (b*8+h)*256 + (lane & 15)*16;

                unsigned qa0, qa1, kb0, kb1, vb0, vb1;
                LDSM2 (qa0, qa1, tq);
                LDSM2 (kb0, kb1, tq + 8192);
                LDSM2T(vb0, vb1, tq + 16384);

                float s0=0,s1=0,s2=0,s3=0,s4=0,s5=0,s6=0,s7=0;
                MMA16808(s0,s1,s2,s3, qa0,qa1, kb0);
                MMA16808(s4,s5,s6,s7, qa0,qa1, kb1);

                if (CAUSAL) {
                    const int u0 = 2*tig, u1 = 2*tig+1, u2 = 2*tig+8, u3 = 2*tig+9;
                    if (u0 > gid)   s0 = -1e30f;
                    if (u1 > gid)   s1 = -1e30f;
                    if (u2 > gid)   s4 = -1e30f;
                    if (u3 > gid)   s5 = -1e30f;
                    if (u0 > gid+8) s2 = -1e30f;
                    if (u1 > gid+8) s3 = -1e30f;
                    if (u2 > gid+8) s6 = -1e30f;
                    if (u3 > gid+8) s7 = -1e30f;
                }
                float e0 = __expf(s0), e1 = __expf(s1);
                float e4 = __expf(s4), e5 = __expf(s5);
                float e2 = __expf(s2), e3 = __expf(s3);
                float e6 = __expf(s6), e7 = __expf(s7);
                float slo = e0+e1+e4+e5, shi = e2+e3+e6+e7;
                slo += __shfl_xor_sync(0xffffffffu, slo, 1);
                slo += __shfl_xor_sync(0xffffffffu, slo, 2);
                shi += __shfl_xor_sync(0xffffffffu, shi, 1);
                shi += __shfl_xor_sync(0xffffffffu, shi, 2);
                const float ilo = 1.f/slo, ihi = 1.f/shi;

                unsigned pa0 = bf2u(e0, e1);
                unsigned pa1 = bf2u(e2, e3);
                unsigned pa2 = bf2u(e4, e5);
                unsigned pa3 = bf2u(e6, e7);

                float o0=0,o1=0,o2=0,o3=0;
                MMA16816(o0,o1,o2,o3, pa0,pa1,pa2,pa3, vb0,vb1);
                o0 *= ilo; o1 *= ilo; o2 *= ihi; o3 *= ihi;

                const int tA = b*16 + gid, tB = tA + 8;
                const int c = h*8 + 2*tig;
                unsigned offA = ATT_SOB + tA*128 + (((c>>3) ^ (tA & 7)) << 4) + ((c & 7) << 1);
                unsigned offB = ATT_SOB + tB*128 + (((c>>3) ^ (tB & 7)) << 4) + ((c & 7) << 1);
                *(unsigned*)(smc + offA) = bf2u(o0, o1);
                *(unsigned*)(smc + offB) = bf2u(o2, o3);
            }
        }
        __syncthreads();

        // ---------- phase 3: out = x + O @ Wp + bp ; warp = 16t x 32e ----------
        {
            const int ebase = nh * 32;
            float acc[4][4];
#pragma unroll
            for (int m = 0; m < 4; m++)
#pragma unroll
                for (int p = 0; p < 4; p++) acc[m][p] = 0.f;

#pragma unroll
            for (int ks = 0; ks < 4; ks++) {
                const int k0 = ks * 16;
                unsigned a0,a1,a2,a3;
                {
                    int ar = t0 + (lane & 15);
                    int ac = (k0 >> 3) + (lane >> 4);
                    unsigned aaddr = sbase + ATT_SOB + ar*128 + ((ac ^ (ar & 7)) << 4);
                    LDSM4(a0,a1,a2,a3, aaddr);
                }
#pragma unroll
                for (int st = 0; st < 2; st++) {
                    int n0 = ebase + st * 16;
                    unsigned b0,b1r,b2,b3;
                    int br = k0 + (lane & 15);
                    int bc = (n0 >> 3) + (lane >> 4);
                    unsigned baddr = sbase + ATT_SWP + br*128 + ((bc ^ (br & 7)) << 4);
                    LDSM4T(b0,b1r,b2,b3, baddr);
                    MMA16816(acc[2*st][0],acc[2*st][1],acc[2*st][2],acc[2*st][3],
                             a0,a1,a2,a3, b0,b1r);
                    MMA16816(acc[2*st+1][0],acc[2*st+1][1],acc[2*st+1][2],acc[2*st+1][3],
                             a0,a1,a2,a3, b2,b3);
                }
            }
            const int r0 = t0 + gid, r1 = t0 + gid + 8;
#pragma unroll
            for (int m = 0; m < 4; m++) {
                int e = ebase + m*8 + 2*tig;
                float bb0 = sbp[e], bb1 = sbp[e+1];
                float2 x0 = *(const float2*)(xin + (base + r0)*64 + e);
                float2 x1 = *(const float2*)(xin + (base + r1)*64 + e);
                float2 o0 = make_float2(x0.x + acc[m][0] + bb0, x0.y + acc[m][1] + bb1);
                float2 o1 = make_float2(x1.x + acc[m][2] + bb0, x1.y + acc[m][3] + bb1);
                *(float2*)(xout + (base + r0)*64 + e) = o0;
                *(float2*)(xout + (base + r1)*64 + e) = o1;
            }
        }

        // commit LN of next tile into the other sA buffer
        if (tt + 1 < NT) ln_commit(xv, smc + nxtOff, tid, sg);
        __syncthreads();
    }
}

// ==================================================================
// launch: prep -> attn(u) -> ffn -> attn(m, causal) -> ffn
// ==================================================================
extern "C" void kernel_launch(void* const* d_in, const int* in_sizes, int n_in,
                              void* d_out, int out_size)
{
    (void)in_sizes; (void)n_in; (void)out_size;
    const float* x   = (const float*)d_in[0];
    const float* uWq = (const float*)d_in[1];  const float* ubq = (const float*)d_in[2];
    const float* uWk = (const float*)d_in[3];  const float* ubk = (const float*)d_in[4];
    const float* uWv = (const float*)d_in[5];  const float* ubv = (const float*)d_in[6];
    const float* uWp = (const float*)d_in[7];  const float* ubp = (const float*)d_in[8];
    const float* mWq = (const float*)d_in[9];  const float* mbq = (const float*)d_in[10];
    const float* mWk = (const float*)d_in[11]; const float* mbk = (const float*)d_in[12];
    const float* mWv = (const float*)d_in[13]; const float* mbv = (const float*)d_in[14];
    const float* mWp = (const float*)d_in[15]; const float* mbp = (const float*)d_in[16];
    const float* fW1 = (const float*)d_in[17]; const float* fb1 = (const float*)d_in[18];
    const float* fW2 = (const float*)d_in[19]; const float* fb2 = (const float*)d_in[20];
    const float* g1  = (const float*)d_in[21]; const float* be1 = (const float*)d_in[22];
    const float* g2  = (const float*)d_in[23]; const float* be2 = (const float*)d_in[24];
    float* out = (float*)d_out;

    float* scratch = nullptr;
    cudaGetSymbolAddress((void**)&scratch, g_scratch);
    __nv_bfloat16 *Tu = nullptr, *Tm = nullptr, *Wpu = nullptr, *Wpm = nullptr;
    cudaGetSymbolAddress((void**)&Tu, g_Tu);
    cudaGetSymbolAddress((void**)&Tm, g_Tm);
    cudaGetSymbolAddress((void**)&Wpu, g_Wpu);
    cudaGetSymbolAddress((void**)&Wpm, g_Wpm);

    cudaFuncSetAttribute(attn_kernel<false>, cudaFuncAttributeMaxDynamicSharedMemorySize, ATT_SMEM_BYTES);
    cudaFuncSetAttribute(attn_kernel<true>,  cudaFuncAttributeMaxDynamicSharedMemorySize, ATT_SMEM_BYTES);
    cudaFuncSetAttribute(ffn_kernel,         cudaFuncAttributeMaxDynamicSharedMemorySize, FFN_SMEM_BYTES);

    prep_kernel<<<32, 256>>>(fW1, fW2, uWq, uWk, uWv, uWp, mWq, mWk, mWv, mWp);

    attn_kernel<false><<<NBLK, TPB, ATT_SMEM_BYTES>>>(x, scratch, Tu, Wpu,
        ubq, ubk, ubv, ubp, g1, be1);
    ffn_kernel<<<NBLK, TPB, FFN_SMEM_BYTES>>>(scratch, out, fb1, fb2, g2, be2);
    attn_kernel<true><<<NBLK, TPB, ATT_SMEM_BYTES>>>(out, scratch, Tm, Wpm,
        mbq, mbk, mbv, mbp, g1, be1);
    ffn_kernel<<<NBLK, TPB, FFN_SMEM_BYTES>>>(scratch, out, fb1, fb2, g2, be2);
}

// round 10
// speedup vs baseline: 5.6874x; 1.0109x over previous
#include <cuda_runtime.h>
#include <cuda_bf16.h>
#include <math.h>

#define NTOK (32768*16)          // 524288 tokens
#define TPB  256
#define TOKS 64                  // tokens per tile
#define NT   4                   // tiles per CTA
#define NBLK (NTOK/(TOKS*NT))    // 2048 CTAs

// ---------------- device globals (allocation-free scratch) ----------------
__device__ float g_scratch[(size_t)NTOK * 64];
__device__ __align__(16) __nv_bfloat16 g_W1b[64*256];
__device__ __align__(16) __nv_bfloat16 g_W2b[256*64];
__device__ __align__(16) __nv_bfloat16 g_Tu[64*192];   // [d][h*8+s (+0/64/128 for q/k/v)]
__device__ __align__(16) __nv_bfloat16 g_Tm[64*192];
__device__ __align__(16) __nv_bfloat16 g_Wpu[64*64];
__device__ __align__(16) __nv_bfloat16 g_Wpm[64*64];

// ---------------- small helpers ----------------
__device__ __forceinline__ unsigned bf2u(float a, float b) {
    unsigned r;
    asm("cvt.rn.bf16x2.f32 %0, %1, %2;" : "=r"(r) : "f"(b), "f"(a));
    return r;
}
__device__ __forceinline__ unsigned su32(const void* p) {
    return (unsigned)__cvta_generic_to_shared(p);
}
// fast GELU: 0.5z(1+tanh(0.79788456(z + 0.044715 z^3))), HW tanh
__device__ __forceinline__ float gelu_f(float z) {
    float w = z * fmaf(0.035677408136f, z*z, 0.79788456080287f);
    float t;
    asm("tanh.approx.f32 %0, %1;" : "=f"(t) : "f"(w));
    float hz = 0.5f*z;
    return fmaf(hz, t, hz);
}

#define LDSM2(r0,r1,addr) \
    asm volatile("ldmatrix.sync.aligned.m8n8.x2.shared.b16 {%0,%1},[%2];" \
        : "=r"(r0),"=r"(r1) : "r"(addr))
#define LDSM2T(r0,r1,addr) \
    asm volatile("ldmatrix.sync.aligned.m8n8.x2.trans.shared.b16 {%0,%1},[%2];" \
        : "=r"(r0),"=r"(r1) : "r"(addr))
#define LDSM4(r0,r1,r2,r3,addr) \
    asm volatile("ldmatrix.sync.aligned.m8n8.x4.shared.b16 {%0,%1,%2,%3},[%4];" \
        : "=r"(r0),"=r"(r1),"=r"(r2),"=r"(r3) : "r"(addr))
#define LDSM4T(r0,r1,r2,r3,addr) \
    asm volatile("ldmatrix.sync.aligned.m8n8.x4.trans.shared.b16 {%0,%1,%2,%3},[%4];" \
        : "=r"(r0),"=r"(r1),"=r"(r2),"=r"(r3) : "r"(addr))
#define MMA16816(c0,c1,c2,c3,a0,a1,a2,a3,b0,b1) \
    asm volatile("mma.sync.aligned.m16n8k16.row.col.f32.bf16.bf16.f32 " \
        "{%0,%1,%2,%3},{%4,%5,%6,%7},{%8,%9},{%0,%1,%2,%3};" \
        : "+f"(c0),"+f"(c1),"+f"(c2),"+f"(c3) \
        : "r"(a0),"r"(a1),"r"(a2),"r"(a3),"r"(b0),"r"(b1))
#define MMA16808(c0,c1,c2,c3,a0,a1,b0) \
    asm volatile("mma.sync.aligned.m16n8k8.row.col.f32.bf16.bf16.f32 " \
        "{%0,%1,%2,%3},{%4,%5},{%6},{%0,%1,%2,%3};" \
        : "+f"(c0),"+f"(c1),"+f"(c2),"+f"(c3) \
        : "r"(a0),"r"(a1),"r"(b0))

// ---- LN split into prefetch (LDG only) + commit (shuffle + STS) ----
__device__ __forceinline__ void ln_prefetch(float* xv, const float* __restrict__ xin,
                                            size_t base, int tid) {
    const int t = tid >> 2, qp = tid & 3;
    const float4* x4 = (const float4*)(xin + (base + t)*64) + qp*4;
#pragma unroll
    for (int i = 0; i < 4; i++) {
        float4 v = x4[i];
        xv[4*i]=v.x; xv[4*i+1]=v.y; xv[4*i+2]=v.z; xv[4*i+3]=v.w;
    }
}
__device__ __forceinline__ void ln_commit(const float* xv, char* __restrict__ sA,
                                          int tid, const float* __restrict__ sg) {
    const int t = tid >> 2, qp = tid & 3;
    float s = 0.f, ss = 0.f;
#pragma unroll
    for (int i = 0; i < 16; i++) { s += xv[i]; ss = fmaf(xv[i], xv[i], ss); }
    s  += __shfl_xor_sync(0xffffffffu, s, 1);  ss += __shfl_xor_sync(0xffffffffu, ss, 1);
    s  += __shfl_xor_sync(0xffffffffu, s, 2);  ss += __shfl_xor_sync(0xffffffffu, ss, 2);
    const float mean = s * (1.f/64.f);
    const float var  = ss * (1.f/64.f) - mean*mean;
    const float rstd = rsqrtf(var + 1e-5f);
    const int kb = qp * 16;
#pragma unroll
    for (int c = 0; c < 2; c++) {
        float v[8];
#pragma unroll
        for (int e = 0; e < 8; e++) {
            int k = kb + c*8 + e;
            v[e] = (xv[c*8+e] - mean) * rstd * sg[k] + sg[64+k];
        }
        uint4 q;
        q.x = bf2u(v[0], v[1]); q.y = bf2u(v[2], v[3]);
        q.z = bf2u(v[4], v[5]); q.w = bf2u(v[6], v[7]);
        int ch = qp*2 + c;
        *(uint4*)(sA + t*128 + ((ch ^ (t & 7)) << 4)) = q;
    }
}

// ---------------- prep: fp32 weights -> bf16 (and qkv transpose) ----------------
__global__ void prep_kernel(const float* __restrict__ W1, const float* __restrict__ W2,
                            const float* __restrict__ uWq, const float* __restrict__ uWk,
                            const float* __restrict__ uWv, const float* __restrict__ uWp,
                            const float* __restrict__ mWq, const float* __restrict__ mWk,
                            const float* __restrict__ mWv, const float* __restrict__ mWp)
{
    int i0 = blockIdx.x * blockDim.x + threadIdx.x;
    int stride = gridDim.x * blockDim.x;
    for (int i = i0; i < 16384; i += stride) {
        g_W1b[i] = __float2bfloat16(W1[i]);
        g_W2b[i] = __float2bfloat16(W2[i]);
    }
    for (int i = i0; i < 4096; i += stride) {
        int h = i >> 9, d = (i >> 3) & 63, s = i & 7;
        int c = h*8 + s;
        g_Tu[d*192 + c]       = __float2bfloat16(uWq[i]);
        g_Tu[d*192 + 64 + c]  = __float2bfloat16(uWk[i]);
        g_Tu[d*192 + 128 + c] = __float2bfloat16(uWv[i]);
        g_Tm[d*192 + c]       = __float2bfloat16(mWq[i]);
        g_Tm[d*192 + 64 + c]  = __float2bfloat16(mWk[i]);
        g_Tm[d*192 + 128 + c] = __float2bfloat16(mWv[i]);
        g_Wpu[i] = __float2bfloat16(uWp[i]);
        g_Wpm[i] = __float2bfloat16(mWp[i]);
    }
}

// ==================================================================
// FFN kernel (R8 proven design): out = x + gelu(LN(x)@W1 + b1)@W2 + b2
// phase1: warp = 16t x 128j, H c-frags in regs; phase2 = 2-way k-split,
// balanced-halves cross-warp fp32 reduce in smem. NT tiles/CTA,
// LN software-pipelined (double-buffered sA).
// ==================================================================
#define FFN_SW1  0
#define FFN_SW2  32768
#define FFN_SA0  65536
#define FFN_SA1  73728
#define FFN_SRED 81920            // 4 groups x 16 x 68 floats = 17408
#define FFN_SB1  99328
#define FFN_SB2  100352
#define FFN_SG   100608
#define FFN_SMEM_BYTES 101120

__global__ void __launch_bounds__(TPB, 2) ffn_kernel(
    const float* __restrict__ xin, float* __restrict__ xout,
    const float* __restrict__ b1, const float* __restrict__ b2,
    const float* __restrict__ g2, const float* __restrict__ be2)
{
    extern __shared__ char smc[];
    float* sb1 = (float*)(smc + FFN_SB1);
    float* sb2 = (float*)(smc + FFN_SB2);
    float* sg  = (float*)(smc + FFN_SG);

    const int tid = threadIdx.x;
    const unsigned sbase = su32(smc);

    {
        const uint4* src1 = (const uint4*)g_W1b;
        const uint4* src2 = (const uint4*)g_W2b;
        for (int c = tid; c < 2048; c += TPB) {
            int r1 = c >> 5, c1 = c & 31;
            *(uint4*)(smc + FFN_SW1 + r1*512 + ((c1 ^ (r1 & 7)) << 4)) = src1[c];
            int r2 = c >> 3, c2 = c & 7;
            *(uint4*)(smc + FFN_SW2 + r2*128 + ((c2 ^ (r2 & 7)) << 4)) = src2[c];
        }
    }
    sb1[tid] = b1[tid];
    if (tid < 64) { sb2[tid] = b2[tid]; sg[tid] = g2[tid]; sg[64+tid] = be2[tid]; }
    __syncthreads();

    const int lane = tid & 31, wid = tid >> 5;
    const int gid = lane >> 2, tig = lane & 3;
    const int tw = wid & 3, nh = wid >> 2;
    const int t0 = tw * 16;
    const int jbase = nh * 128;

    const size_t cta0 = (size_t)blockIdx.x * NT * TOKS;

    float xv[16];
    ln_prefetch(xv, xin, cta0, tid);
    ln_commit(xv, smc + FFN_SA0, tid, sg);
    __syncthreads();

    for (int tt = 0; tt < NT; tt++) {
        const size_t base = cta0 + (size_t)tt * TOKS;
        const unsigned curA = sbase + (((tt & 1) == 0) ? FFN_SA0 : FFN_SA1);
        const unsigned nxtOff = (((tt & 1) == 0) ? FFN_SA1 : FFN_SA0);

        // ---------- phase 1: Z = A @ W1 (c-frags in regs); warp = 16t x 128j ----------
        float acc[16][4];
#pragma unroll
        for (int m = 0; m < 16; m++)
#pragma unroll
            for (int p = 0; p < 4; p++) acc[m][p] = 0.f;

#pragma unroll
        for (int ks = 0; ks < 4; ks++) {
            const int k0 = ks * 16;
            unsigned a0,a1,a2,a3;
            {
                int ar = t0 + (lane & 15);
                int ac = (k0 >> 3) + (lane >> 4);
                unsigned aaddr = curA + ar*128 + ((ac ^ (ar & 7)) << 4);
                LDSM4(a0,a1,a2,a3, aaddr);
            }
#pragma unroll
            for (int st = 0; st < 8; st++) {
                int n0 = jbase + st * 16;
                unsigned b0,b1r,b2,b3;
                int br = k0 + (lane & 15);
                int bc = (n0 >> 3) + (lane >> 4);
                unsigned baddr = sbase + FFN_SW1 + br*512 + ((bc ^ (br & 7)) << 4);
                LDSM4T(b0,b1r,b2,b3, baddr);
                MMA16816(acc[2*st][0],acc[2*st][1],acc[2*st][2],acc[2*st][3],
                         a0,a1,a2,a3, b0,b1r);
                MMA16816(acc[2*st+1][0],acc[2*st+1][1],acc[2*st+1][2],acc[2*st+1][3],
                         a0,a1,a2,a3, b2,b3);
            }
        }

        // ---------- gelu in registers, pack to A-frags of phase 2 ----------
        unsigned pk[8][4];
#pragma unroll
        for (int m = 0; m < 16; m++) {
            int col = jbase + m*8 + 2*tig;
            float bb0 = sb1[col], bb1 = sb1[col+1];
            float h00 = gelu_f(acc[m][0] + bb0);
            float h01 = gelu_f(acc[m][1] + bb1);
            float h10 = gelu_f(acc[m][2] + bb0);
            float h11 = gelu_f(acc[m][3] + bb1);
            if ((m & 1) == 0) {
                pk[m>>1][0] = bf2u(h00, h01);
                pk[m>>1][1] = bf2u(h10, h11);
            } else {
                pk[m>>1][2] = bf2u(h00, h01);
                pk[m>>1][3] = bf2u(h10, h11);
            }
        }

        // prefetch next tile's x (acc is dead; low register pressure window)
        if (tt + 1 < NT) ln_prefetch(xv, xin, base + TOKS, tid);

        // ---------- phase 2: partial out = H_slab @ W2[jbase:+128][0:64] ----------
        float acc2[8][4];
#pragma unroll
        for (int m = 0; m < 8; m++)
#pragma unroll
            for (int p = 0; p < 4; p++) acc2[m][p] = 0.f;

#pragma unroll
        for (int ks = 0; ks < 8; ks++) {
            const int br = jbase + ks*16 + (lane & 15);
#pragma unroll
            for (int st = 0; st < 4; st++) {
                int n0 = st * 16;
                unsigned b0,b1r,b2,b3;
                int bc = (n0 >> 3) + (lane >> 4);
                unsigned baddr = sbase + FFN_SW2 + br*128 + ((bc ^ (br & 7)) << 4);
                LDSM4T(b0,b1r,b2,b3, baddr);
                MMA16816(acc2[2*st][0],acc2[2*st][1],acc2[2*st][2],acc2[2*st][3],
                         pk[ks][0],pk[ks][1],pk[ks][2],pk[ks][3], b0,b1r);
                MMA16816(acc2[2*st+1][0],acc2[2*st+1][1],acc2[2*st+1][2],acc2[2*st+1][3],
                         pk[ks][0],pk[ks][1],pk[ks][2],pk[ks][3], b2,b3);
            }
        }

        // ---------- cross-warp k-reduction (balanced halves, 2-way) ----------
        float* red = (float*)(smc + FFN_SRED) + tw * (16*68);
        const int st_sto = (nh == 1) ? 0 : 4;   // partial stored for partner
        const int st_fin = (nh == 1) ? 4 : 0;   // half this warp finalizes
#pragma unroll
        for (int s = 0; s < 4; s++) {
            int st = st_sto + s;
#pragma unroll
            for (int rp = 0; rp < 2; rp++) {
                int row = gid + rp*8;
                *(float2*)(red + row*68 + st*8 + 2*tig) =
                    make_float2(acc2[st][2*rp], acc2[st][2*rp+1]);
            }
        }
        __syncthreads();
#pragma unroll
        for (int s = 0; s < 4; s++) {
            int st = st_fin + s;
            int e = st*8 + 2*tig;
            float bb0 = sb2[e], bb1 = sb2[e+1];
#pragma unroll
            for (int rp = 0; rp < 2; rp++) {
                int row = gid + rp*8;
                float2 r = *(const float2*)(red + row*68 + e);
                float2 x = *(const float2*)(xin + (base + t0 + row)*64 + e);
                float2 o = make_float2(x.x + r.x + acc2[st][2*rp]   + bb0,
                                       x.y + r.y + acc2[st][2*rp+1] + bb1);
                *(float2*)(xout + (base + t0 + row)*64 + e) = o;
            }
        }

        // commit LN of next tile into the other sA buffer
        if (tt + 1 < NT) ln_commit(xv, smc + nxtOff, tid, sg);
        __syncthreads();
    }
}

// ==================================================================
// Attention kernel: out = x + attn(LN(x)) ; NT tiles/CTA
// phase1 remapped: warp = 32 tokens x 48 cols (tg = wid&1, cg = wid>>1)
// ==================================================================
#define ATT_ST    0
#define ATT_SWP   24576
#define ATT_SA0   32768
#define ATT_SA1   40960
#define ATT_SOB   49152
#define ATT_SQKV  57344
#define ATT_SBQKV 81920
#define ATT_SBP   82688
#define ATT_SG    82944
#define ATT_SMEM_BYTES 83456

template <bool CAUSAL>
__global__ void __launch_bounds__(TPB, 2) attn_kernel(
    const float* __restrict__ xin, float* __restrict__ xout,
    const __nv_bfloat16* __restrict__ Tqkv, const __nv_bfloat16* __restrict__ Wpb,
    const float* __restrict__ bq, const float* __restrict__ bk,
    const float* __restrict__ bv, const float* __restrict__ bp,
    const float* __restrict__ g1, const float* __restrict__ be1)
{
    extern __shared__ char smc[];
    float* sbqkv = (float*)(smc + ATT_SBQKV);
    float* sbp   = (float*)(smc + ATT_SBP);
    float* sg    = (float*)(smc + ATT_SG);

    const int tid = threadIdx.x;
    const unsigned sbase = su32(smc);

    {
        const uint4* srcT = (const uint4*)Tqkv;   // 64 rows x 24 chunks
        for (int c = tid; c < 1536; c += TPB) {
            int r = c / 24, ch = c % 24;
            *(uint4*)(smc + ATT_ST + r*384 + ((ch ^ (r & 7)) << 4)) = srcT[c];
        }
        const uint4* srcP = (const uint4*)Wpb;
        for (int c = tid; c < 512; c += TPB) {
            int r = c >> 3, ch = c & 7;
            *(uint4*)(smc + ATT_SWP + r*128 + ((ch ^ (r & 7)) << 4)) = srcP[c];
        }
    }
    if (tid < 192) sbqkv[tid] = (tid < 64) ? bq[tid] : (tid < 128 ? bk[tid-64] : bv[tid-128]);
    if (tid < 64)  sbp[tid] = bp[tid];
    if (tid < 128) sg[tid] = (tid < 64) ? g1[tid] : be1[tid-64];
    __syncthreads();

    const int lane = tid & 31, wid = tid >> 5;
    const int gid = lane >> 2, tig = lane & 3;
    const int tw = wid & 3, nh = wid >> 2;    // phase-3 mapping (unchanged)
    const int t0 = tw * 16;
    const int tg = wid & 1, cg = wid >> 1;    // phase-1 mapping: 32t x 48c
    const int tb0 = tg * 32;

    const size_t cta0 = (size_t)blockIdx.x * NT * TOKS;

    float xv[16];
    ln_prefetch(xv, xin, cta0, tid);
    ln_commit(xv, smc + ATT_SA0, tid, sg);
    __syncthreads();

    for (int tt = 0; tt < NT; tt++) {
        const size_t base = cta0 + (size_t)tt * TOKS;
        const unsigned curA = sbase + (((tt & 1) == 0) ? ATT_SA0 : ATT_SA1);
        const unsigned nxtOff = (((tt & 1) == 0) ? ATT_SA1 : ATT_SA0);

        // ---------- phase 1: QKV = A @ T + b ; warp = 32t x 48c ----------
        {
            float acc[2][6][4];
#pragma unroll
            for (int mi = 0; mi < 2; mi++)
#pragma unroll
                for (int m = 0; m < 6; m++)
#pragma unroll
                    for (int p = 0; p < 4; p++) acc[mi][m][p] = 0.f;

#pragma unroll
            for (int ks = 0; ks < 4; ks++) {
                const int k0 = ks * 16;
                unsigned aA[2][4];
#pragma unroll
                for (int mi = 0; mi < 2; mi++) {
                    int ar = tb0 + mi*16 + (lane & 15);
                    int ac = (k0 >> 3) + (lane >> 4);
                    unsigned aaddr = curA + ar*128 + ((ac ^ (ar & 7)) << 4);
                    LDSM4(aA[mi][0], aA[mi][1], aA[mi][2], aA[mi][3], aaddr);
                }
#pragma unroll
                for (int st = 0; st < 3; st++) {
                    int n0 = cg*48 + st * 16;
                    unsigned b0,b1r,b2,b3;
                    int br = k0 + (lane & 15);
                    int bc = (n0 >> 3) + (lane >> 4);
                    unsigned baddr = sbase + ATT_ST + br*384 + ((bc ^ (br & 7)) << 4);
                    LDSM4T(b0,b1r,b2,b3, baddr);
#pragma unroll
                    for (int mi = 0; mi < 2; mi++) {
                        MMA16816(acc[mi][2*st][0],acc[mi][2*st][1],acc[mi][2*st][2],acc[mi][2*st][3],
                                 aA[mi][0],aA[mi][1],aA[mi][2],aA[mi][3], b0,b1r);
                        MMA16816(acc[mi][2*st+1][0],acc[mi][2*st+1][1],acc[mi][2*st+1][2],acc[mi][2*st+1][3],
                                 aA[mi][0],aA[mi][1],aA[mi][2],aA[mi][3], b2,b3);
                    }
                }
            }

            // prefetch next tile's x (covers epilogue + phases 2/3)
            if (tt + 1 < NT) ln_prefetch(xv, xin, base + TOKS, tid);

            // epilogue: bias (+0.35355 scale for Q), write bf16 tiles [16 x 16B]
#pragma unroll
            for (int mi = 0; mi < 2; mi++)
#pragma unroll
                for (int nf = 0; nf < 6; nf++) {
                    int cc = cg*48 + nf*8;
                    int sec = cc >> 6;               // 0=q 1=k 2=v
                    int h = (cc >> 3) & 7;
                    int c = cc + 2*tig;
                    int b_loc = tg*2 + mi;           // batch within tile
                    float bb0 = sbqkv[c], bb1 = sbqkv[c+1];
                    float scale = (sec == 0) ? 0.35355339059327373f : 1.f;
                    float v00 = (acc[mi][nf][0] + bb0) * scale, v01 = (acc[mi][nf][1] + bb1) * scale;
                    float v10 = (acc[mi][nf][2] + bb0) * scale, v11 = (acc[mi][nf][3] + bb1) * scale;
                    unsigned tb = ATT_SQKV + sec*8192 + (b_loc*8 + h)*256 + tig*4;
                    *(unsigned*)(smc + tb + gid*16)     = bf2u(v00, v01);
                    *(unsigned*)(smc + tb + (gid+8)*16) = bf2u(v10, v11);
                }
        }
        __syncthreads();

        // ---------- phase 2: MMA attention core; warp handles 4 (b,h) pairs ----------
        {
#pragma unroll
            for (int i = 0; i < 4; i++) {
                const int p = wid*4 + i;
                const int b = p >> 3, h = p & 7;
                const unsigned tq = sbase + ATT_SQKV + (b*8+h)*256 + (lane & 15)*16;

                unsigned qa0, qa1, kb0, kb1, vb0, vb1;
                LDSM2 (qa0, qa1, tq);
                LDSM2 (kb0, kb1, tq + 8192);
                LDSM2T(vb0, vb1, tq + 16384);

                float s0=0,s1=0,s2=0,s3=0,s4=0,s5=0,s6=0,s7=0;
                MMA16808(s0,s1,s2,s3, qa0,qa1, kb0);
                MMA16808(s4,s5,s6,s7, qa0,qa1, kb1);

                if (CAUSAL) {
                    const int u0 = 2*tig, u1 = 2*tig+1, u2 = 2*tig+8, u3 = 2*tig+9;
                    if (u0 > gid)   s0 = -1e30f;
                    if (u1 > gid)   s1 = -1e30f;
                    if (u2 > gid)   s4 = -1e30f;
                    if (u3 > gid)   s5 = -1e30f;
                    if (u0 > gid+8) s2 = -1e30f;
                    if (u1 > gid+8) s3 = -1e30f;
                    if (u2 > gid+8) s6 = -1e30f;
                    if (u3 > gid+8) s7 = -1e30f;
                }
                float e0 = __expf(s0), e1 = __expf(s1);
                float e4 = __expf(s4), e5 = __expf(s5);
                float e2 = __expf(s2), e3 = __expf(s3);
                float e6 = __expf(s6), e7 = __expf(s7);
                float slo = e0+e1+e4+e5, shi = e2+e3+e6+e7;
                slo += __shfl_xor_sync(0xffffffffu, slo, 1);
                slo += __shfl_xor_sync(0xffffffffu, slo, 2);
                shi += __shfl_xor_sync(0xffffffffu, shi, 1);
                shi += __shfl_xor_sync(0xffffffffu, shi, 2);
                const float ilo = 1.f/slo, ihi = 1.f/shi;

                unsigned pa0 = bf2u(e0, e1);
                unsigned pa1 = bf2u(e2, e3);
                unsigned pa2 = bf2u(e4, e5);
                unsigned pa3 = bf2u(e6, e7);

                float o0=0,o1=0,o2=0,o3=0;
                MMA16816(o0,o1,o2,o3, pa0,pa1,pa2,pa3, vb0,vb1);
                o0 *= ilo; o1 *= ilo; o2 *= ihi; o3 *= ihi;

                const int tA = b*16 + gid, tB = tA + 8;
                const int c = h*8 + 2*tig;
                unsigned offA = ATT_SOB + tA*128 + (((c>>3) ^ (tA & 7)) << 4) + ((c & 7) << 1);
                unsigned offB = ATT_SOB + tB*128 + (((c>>3) ^ (tB & 7)) << 4) + ((c & 7) << 1);
                *(unsigned*)(smc + offA) = bf2u(o0, o1);
                *(unsigned*)(smc + offB) = bf2u(o2, o3);
            }
        }
        __syncthreads();

        // ---------- phase 3: out = x + O @ Wp + bp ; warp = 16t x 32e ----------
        {
            const int ebase = nh * 32;
            float acc[4][4];
#pragma unroll
            for (int m = 0; m < 4; m++)
#pragma unroll
                for (int p = 0; p < 4; p++) acc[m][p] = 0.f;

#pragma unroll
            for (int ks = 0; ks < 4; ks++) {
                const int k0 = ks * 16;
                unsigned a0,a1,a2,a3;
                {
                    int ar = t0 + (lane & 15);
                    int ac = (k0 >> 3) + (lane >> 4);
                    unsigned aaddr = sbase + ATT_SOB + ar*128 + ((ac ^ (ar & 7)) << 4);
                    LDSM4(a0,a1,a2,a3, aaddr);
                }
#pragma unroll
                for (int st = 0; st < 2; st++) {
                    int n0 = ebase + st * 16;
                    unsigned b0,b1r,b2,b3;
                    int br = k0 + (lane & 15);
                    int bc = (n0 >> 3) + (lane >> 4);
                    unsigned baddr = sbase + ATT_SWP + br*128 + ((bc ^ (br & 7)) << 4);
                    LDSM4T(b0,b1r,b2,b3, baddr);
                    MMA16816(acc[2*st][0],acc[2*st][1],acc[2*st][2],acc[2*st][3],
                             a0,a1,a2,a3, b0,b1r);
                    MMA16816(acc[2*st+1][0],acc[2*st+1][1],acc[2*st+1][2],acc[2*st+1][3],
                             a0,a1,a2,a3, b2,b3);
                }
            }
            const int r0 = t0 + gid, r1 = t0 + gid + 8;
#pragma unroll
            for (int m = 0; m < 4; m++) {
                int e = ebase + m*8 + 2*tig;
                float bb0 = sbp[e], bb1 = sbp[e+1];
                float2 x0 = *(const float2*)(xin + (base + r0)*64 + e);
                float2 x1 = *(const float2*)(xin + (base + r1)*64 + e);
                float2 o0 = make_float2(x0.x + acc[m][0] + bb0, x0.y + acc[m][1] + bb1);
                float2 o1 = make_float2(x1.x + acc[m][2] + bb0, x1.y + acc[m][3] + bb1);
                *(float2*)(xout + (base + r0)*64 + e) = o0;
                *(float2*)(xout + (base + r1)*64 + e) = o1;
            }
        }

        // commit LN of next tile into the other sA buffer
        if (tt + 1 < NT) ln_commit(xv, smc + nxtOff, tid, sg);
        __syncthreads();
    }
}

// ==================================================================
// launch: prep -> attn(u) -> ffn -> attn(m, causal) -> ffn
// ==================================================================
extern "C" void kernel_launch(void* const* d_in, const int* in_sizes, int n_in,
                              void* d_out, int out_size)
{
    (void)in_sizes; (void)n_in; (void)out_size;
    const float* x   = (const float*)d_in[0];
    const float* uWq = (const float*)d_in[1];  const float* ubq = (const float*)d_in[2];
    const float* uWk = (const float*)d_in[3];  const float* ubk = (const float*)d_in[4];
    const float* uWv = (const float*)d_in[5];  const float* ubv = (const float*)d_in[6];
    const float* uWp = (const float*)d_in[7];  const float* ubp = (const float*)d_in[8];
    const float* mWq = (const float*)d_in[9];  const float* mbq = (const float*)d_in[10];
    const float* mWk = (const float*)d_in[11]; const float* mbk = (const float*)d_in[12];
    const float* mWv = (const float*)d_in[13]; const float* mbv = (const float*)d_in[14];
    const float* mWp = (const float*)d_in[15]; const float* mbp = (const float*)d_in[16];
    const float* fW1 = (const float*)d_in[17]; const float* fb1 = (const float*)d_in[18];
    const float* fW2 = (const float*)d_in[19]; const float* fb2 = (const float*)d_in[20];
    const float* g1  = (const float*)d_in[21]; const float* be1 = (const float*)d_in[22];
    const float* g2  = (const float*)d_in[23]; const float* be2 = (const float*)d_in[24];
    float* out = (float*)d_out;

    float* scratch = nullptr;
    cudaGetSymbolAddress((void**)&scratch, g_scratch);
    __nv_bfloat16 *Tu = nullptr, *Tm = nullptr, *Wpu = nullptr, *Wpm = nullptr;
    cudaGetSymbolAddress((void**)&Tu, g_Tu);
    cudaGetSymbolAddress((void**)&Tm, g_Tm);
    cudaGetSymbolAddress((void**)&Wpu, g_Wpu);
    cudaGetSymbolAddress((void**)&Wpm, g_Wpm);

    cudaFuncSetAttribute(attn_kernel<false>, cudaFuncAttributeMaxDynamicSharedMemorySize, ATT_SMEM_BYTES);
    cudaFuncSetAttribute(attn_kernel<true>,  cudaFuncAttributeMaxDynamicSharedMemorySize, ATT_SMEM_BYTES);
    cudaFuncSetAttribute(ffn_kernel,         cudaFuncAttributeMaxDynamicSharedMemorySize, FFN_SMEM_BYTES);

    prep_kernel<<<32, 256>>>(fW1, fW2, uWq, uWk, uWv, uWp, mWq, mWk, mWv, mWp);

    attn_kernel<false><<<NBLK, TPB, ATT_SMEM_BYTES>>>(x, scratch, Tu, Wpu,
        ubq, ubk, ubv, ubp, g1, be1);
    ffn_kernel<<<NBLK, TPB, FFN_SMEM_BYTES>>>(scratch, out, fb1, fb2, g2, be2);
    attn_kernel<true><<<NBLK, TPB, ATT_SMEM_BYTES>>>(out, scratch, Tm, Wpm,
        mbq, mbk, mbv, mbp, g1, be1);
    ffn_kernel<<<NBLK, TPB, FFN_SMEM_BYTES>>>(scratch, out, fb1, fb2, g2, be2);
}